// round 5
// baseline (speedup 1.0000x reference)
#include <cuda_runtime.h>
#include <cuda_bf16.h>
#include <math.h>

#define DIM 2048
#define NH 16
#define KV_LORA 512
#define NOPE 128
#define ROPE_D 64
#define VD 128
#define QKD 192
#define BATCH 2
#define SEQ 2048
#define NTOK (BATCH*SEQ)

// ---------------- scratch (static device arrays; no allocation) --------------
__device__ float g_q[(size_t)NTOK * NH * QKD];            // 4096 x 3072
__device__ float g_kv[(size_t)NTOK * (KV_LORA + ROPE_D)]; // 4096 x 576
__device__ float g_kvc[(size_t)NTOK * KV_LORA];           // 4096 x 512
__device__ float g_kpe[(size_t)NTOK * ROPE_D];            // 4096 x 64
__device__ float g_kvb[(size_t)NTOK * NH * (NOPE + VD)];  // 4096 x 4096
__device__ float g_attn[(size_t)NTOK * NH * VD];          // 4096 x 2048

// ---------------- generic NT SGEMM: C[M,N] = A[M,K] * B[N,K]^T ---------------
__global__ void __launch_bounds__(256, 2)
sgemm_nt(const float* __restrict__ A, const float* __restrict__ B,
         float* __restrict__ C, int M, int N, int K)
{
    __shared__ float As[8][132];
    __shared__ float Bs[8][132];
    const int tid  = threadIdx.x;
    const int tx   = tid & 15, ty = tid >> 4;
    const int bm   = blockIdx.y * 128;
    const int bn   = blockIdx.x * 128;
    const int lrow = tid >> 1;
    const int lseg = tid & 1;

    const bool aval = (bm + lrow) < M;
    const bool bval = (bn + lrow) < N;
    const float* Ap = A + (size_t)(bm + lrow) * K + lseg * 4;
    const float* Bp = B + (size_t)(bn + lrow) * K + lseg * 4;

    float acc[8][8];
#pragma unroll
    for (int i = 0; i < 8; i++)
#pragma unroll
        for (int j = 0; j < 8; j++) acc[i][j] = 0.f;

    for (int kt = 0; kt < K; kt += 8) {
        float4 av = make_float4(0.f, 0.f, 0.f, 0.f);
        float4 bv = make_float4(0.f, 0.f, 0.f, 0.f);
        if (aval) av = *reinterpret_cast<const float4*>(Ap + kt);
        if (bval) bv = *reinterpret_cast<const float4*>(Bp + kt);
        __syncthreads();
        As[lseg*4+0][lrow] = av.x; As[lseg*4+1][lrow] = av.y;
        As[lseg*4+2][lrow] = av.z; As[lseg*4+3][lrow] = av.w;
        Bs[lseg*4+0][lrow] = bv.x; Bs[lseg*4+1][lrow] = bv.y;
        Bs[lseg*4+2][lrow] = bv.z; Bs[lseg*4+3][lrow] = bv.w;
        __syncthreads();
#pragma unroll
        for (int kk = 0; kk < 8; kk++) {
            float4 a0 = *reinterpret_cast<const float4*>(&As[kk][ty*8]);
            float4 a1 = *reinterpret_cast<const float4*>(&As[kk][ty*8+4]);
            float4 b0 = *reinterpret_cast<const float4*>(&Bs[kk][tx*8]);
            float4 b1 = *reinterpret_cast<const float4*>(&Bs[kk][tx*8+4]);
            float a[8] = {a0.x,a0.y,a0.z,a0.w,a1.x,a1.y,a1.z,a1.w};
            float b[8] = {b0.x,b0.y,b0.z,b0.w,b1.x,b1.y,b1.z,b1.w};
#pragma unroll
            for (int i = 0; i < 8; i++)
#pragma unroll
                for (int j = 0; j < 8; j++) acc[i][j] += a[i]*b[j];
        }
    }
#pragma unroll
    for (int i = 0; i < 8; i++) {
        int row = bm + ty*8 + i;
        if (row >= M) continue;
#pragma unroll
        for (int j = 0; j < 8; j++) {
            int col = bn + tx*8 + j;
            if (col < N) C[(size_t)row * N + col] = acc[i][j];
        }
    }
}

// ------------- prep: RMSNorm(kv_c), RoPE(k_pe).  NOTE: reference does NOT ----
// ------------- rotate q_pe (it rotates a copy and drops it), so q is untouched.
__global__ void __launch_bounds__(256)
prep_kernel(const float* __restrict__ kv,
            const float* __restrict__ kvnw,
            const float* __restrict__ fcos, const float* __restrict__ fsin,
            float* __restrict__ kvc, float* __restrict__ kpe)
{
    const int token = blockIdx.x;
    const int spos  = token & (SEQ - 1);
    const int tid   = threadIdx.x;
    __shared__ float red[256];

    const float* kvrow = kv + (size_t)token * (KV_LORA + ROPE_D);
    float ss = 0.f;
    for (int i = tid; i < KV_LORA; i += 256) { float v = kvrow[i]; ss += v*v; }
    red[tid] = ss;
    __syncthreads();
    for (int st = 128; st > 0; st >>= 1) {
        if (tid < st) red[tid] += red[tid + st];
        __syncthreads();
    }
    const float rms = rsqrtf(red[0] / (float)KV_LORA + 1e-6f);

    for (int i = tid; i < KV_LORA; i += 256)
        kvc[(size_t)token * KV_LORA + i] = kvrow[i] * rms * kvnw[i];

    if (tid < 32) {
        float re = kvrow[KV_LORA + 2*tid], im = kvrow[KV_LORA + 2*tid + 1];
        float c = fcos[spos*32 + tid], s = fsin[spos*32 + tid];
        kpe[(size_t)token * ROPE_D + 2*tid]     = re*c - im*s;
        kpe[(size_t)token * ROPE_D + 2*tid + 1] = re*s + im*c;
    }
}

// ------------------------------- flash attention -----------------------------
#define AT_BM 64
#define AT_BN 64

struct AttnSmem {
    float Qst[QKD][68];    // [k][q_row]   (transposed, pre-scaled)
    float Kst[QKD][68];    // [k][k_row]
    float Vs[AT_BN][132];  // [k_row][v_dim]
    float Ss[AT_BM][68];   // scores / probs
};

__global__ void __launch_bounds__(256, 1)
attn_kernel(const float* __restrict__ q, const float* __restrict__ kvb,
            const float* __restrict__ kpe, float* __restrict__ attn_out,
            float scale)
{
    extern __shared__ char smem_raw[];
    AttnSmem& sm = *reinterpret_cast<AttnSmem*>(smem_raw);
    const int qi = blockIdx.x;  // query tile 0..31
    const int h  = blockIdx.y;  // head
    const int b  = blockIdx.z;  // batch
    const int tid = threadIdx.x;
    const int tx = tid & 15, ty = tid >> 4;  // S-compute mapping (16x16)
    const int r  = tid >> 2;                 // softmax/PV mapping: query row
    const int vs = tid & 3;                  // v-dim slice
    const size_t tokq0 = (size_t)b * SEQ + qi * AT_BM;

    // load Q tile transposed, folding in the softmax scale (q is UNROTATED,
    // matching the reference which drops its rotated q_pe copy)
    for (int i = tid; i < AT_BM * (QKD/4); i += 256) {
        int row = i / (QKD/4), c4 = i % (QKD/4);
        float4 v = *reinterpret_cast<const float4*>(
            &q[(tokq0 + row) * (size_t)(NH*QKD) + h*QKD + c4*4]);
        sm.Qst[c4*4+0][row] = v.x * scale; sm.Qst[c4*4+1][row] = v.y * scale;
        sm.Qst[c4*4+2][row] = v.z * scale; sm.Qst[c4*4+3][row] = v.w * scale;
    }

    float o[32];
#pragma unroll
    for (int i = 0; i < 32; i++) o[i] = 0.f;
    float m_r = -1e30f, l_r = 0.f;

    for (int j = 0; j <= qi; j++) {
        __syncthreads();  // previous tile fully consumed
        const size_t tokk0 = (size_t)b * SEQ + j * AT_BN;
        // K tile (k_nope from kvb, k_pe shared across heads) transposed
        for (int i = tid; i < AT_BN * (QKD/4); i += 256) {
            int row = i / (QKD/4), c4 = i % (QKD/4);
            float4 v;
            if (c4 < NOPE/4)
                v = *reinterpret_cast<const float4*>(
                    &kvb[(tokk0 + row) * (size_t)(NH*(NOPE+VD)) + h*(NOPE+VD) + c4*4]);
            else
                v = *reinterpret_cast<const float4*>(
                    &kpe[(tokk0 + row) * (size_t)ROPE_D + (c4 - NOPE/4)*4]);
            sm.Kst[c4*4+0][row] = v.x; sm.Kst[c4*4+1][row] = v.y;
            sm.Kst[c4*4+2][row] = v.z; sm.Kst[c4*4+3][row] = v.w;
        }
        // V tile
        for (int i = tid; i < AT_BN * (VD/4); i += 256) {
            int row = i / (VD/4), c4 = i % (VD/4);
            float4 v = *reinterpret_cast<const float4*>(
                &kvb[(tokk0 + row) * (size_t)(NH*(NOPE+VD)) + h*(NOPE+VD) + NOPE + c4*4]);
            sm.Vs[row][c4*4+0] = v.x; sm.Vs[row][c4*4+1] = v.y;
            sm.Vs[row][c4*4+2] = v.z; sm.Vs[row][c4*4+3] = v.w;
        }
        __syncthreads();

        // S = Q K^T : 4x4 per thread over 16x16 grid
        float acc[4][4];
#pragma unroll
        for (int i = 0; i < 4; i++)
#pragma unroll
            for (int jj = 0; jj < 4; jj++) acc[i][jj] = 0.f;
#pragma unroll 4
        for (int k = 0; k < QKD; k++) {
            float4 a  = *reinterpret_cast<const float4*>(&sm.Qst[k][ty*4]);
            float4 bb = *reinterpret_cast<const float4*>(&sm.Kst[k][tx*4]);
            float av[4] = {a.x, a.y, a.z, a.w};
            float bv[4] = {bb.x, bb.y, bb.z, bb.w};
#pragma unroll
            for (int i = 0; i < 4; i++)
#pragma unroll
                for (int jj = 0; jj < 4; jj++) acc[i][jj] += av[i]*bv[jj];
        }
        const bool diag = (j == qi);
#pragma unroll
        for (int i = 0; i < 4; i++) {
            int lr = ty*4 + i;
            float t0 = (diag && (tx*4+0) > lr) ? -1e30f : acc[i][0];
            float t1 = (diag && (tx*4+1) > lr) ? -1e30f : acc[i][1];
            float t2 = (diag && (tx*4+2) > lr) ? -1e30f : acc[i][2];
            float t3 = (diag && (tx*4+3) > lr) ? -1e30f : acc[i][3];
            *reinterpret_cast<float4*>(&sm.Ss[lr][tx*4]) = make_float4(t0,t1,t2,t3);
        }
        __syncthreads();

        // online softmax: 4 threads per row, each owns cols [vs*16, vs*16+16)
        float rmax = -1e30f;
#pragma unroll
        for (int t = 0; t < 16; t++) rmax = fmaxf(rmax, sm.Ss[r][vs*16 + t]);
        rmax = fmaxf(rmax, __shfl_xor_sync(0xffffffffu, rmax, 1));
        rmax = fmaxf(rmax, __shfl_xor_sync(0xffffffffu, rmax, 2));
        float m_new = fmaxf(m_r, rmax);
        float corr  = __expf(m_r - m_new);
        float pr[16];
        float lp = 0.f;
#pragma unroll
        for (int t = 0; t < 16; t++) {
            float svv = sm.Ss[r][vs*16 + t];
            float p = (svv < -1e29f) ? 0.f : __expf(svv - m_new);
            pr[t] = p;
            lp += p;
        }
        lp += __shfl_xor_sync(0xffffffffu, lp, 1);
        lp += __shfl_xor_sync(0xffffffffu, lp, 2);
        float l_new = l_r * corr + lp;
        __syncwarp();  // all raw-S reads done before overwriting with P
#pragma unroll
        for (int t = 0; t < 16; t++) sm.Ss[r][vs*16 + t] = pr[t];
#pragma unroll
        for (int jj = 0; jj < 32; jj++) o[jj] *= corr;
        m_r = m_new; l_r = l_new;
        __syncwarp();  // P visible to the 4-thread row team

        // O += P V  (thread owns v dims {vs, vs+4, ..., vs+124} of its row)
#pragma unroll 4
        for (int k = 0; k < AT_BN; k++) {
            float p = sm.Ss[r][k];
#pragma unroll
            for (int jj = 0; jj < 32; jj++)
                o[jj] += p * sm.Vs[k][vs + 4*jj];
        }
    }

    const float inv_l = 1.f / l_r;
    const size_t tok = tokq0 + r;
#pragma unroll
    for (int jj = 0; jj < 32; jj++)
        attn_out[tok * (size_t)(NH*VD) + h*VD + vs + 4*jj] = o[jj] * inv_l;
}

// ---------------------------------- launch -----------------------------------
extern "C" void kernel_launch(void* const* d_in, const int* in_sizes, int n_in,
                              void* d_out, int out_size)
{
    const float* x     = (const float*)d_in[0];
    const float* wq    = (const float*)d_in[1];
    const float* wkv_a = (const float*)d_in[2];
    const float* kvnw  = (const float*)d_in[3];
    const float* wkv_b = (const float*)d_in[4];
    const float* wo    = (const float*)d_in[5];
    const float* fcos  = (const float*)d_in[6];
    const float* fsin  = (const float*)d_in[7];
    float* out = (float*)d_out;

    float *q, *kv, *kvc, *kpe, *kvb, *attn;
    cudaGetSymbolAddress((void**)&q,    g_q);
    cudaGetSymbolAddress((void**)&kv,   g_kv);
    cudaGetSymbolAddress((void**)&kvc,  g_kvc);
    cudaGetSymbolAddress((void**)&kpe,  g_kpe);
    cudaGetSymbolAddress((void**)&kvb,  g_kvb);
    cudaGetSymbolAddress((void**)&attn, g_attn);

    // softmax scale: qk_dim^-0.5 * mscale^2 (yarn, MAX_LEN > ORIG_LEN)
    double mm = 0.1 * 1.0 * log(40.0) + 1.0;
    float scale = (float)(mm * mm / sqrt((double)QKD));

    dim3 blk(256);
    // q = x @ wq^T    [4096, 3072]
    sgemm_nt<<<dim3((NH*QKD + 127)/128, (NTOK + 127)/128), blk>>>(
        x, wq, q, NTOK, NH*QKD, DIM);
    // kv = x @ wkv_a^T  [4096, 576]
    sgemm_nt<<<dim3((KV_LORA + ROPE_D + 127)/128, (NTOK + 127)/128), blk>>>(
        x, wkv_a, kv, NTOK, KV_LORA + ROPE_D, DIM);
    // rmsnorm + k_pe rope (q is NOT rotated — matches reference semantics)
    prep_kernel<<<NTOK, 256>>>(kv, kvnw, fcos, fsin, kvc, kpe);
    // kvb = kvc @ wkv_b^T  [4096, 4096]
    sgemm_nt<<<dim3((NH*(NOPE+VD) + 127)/128, (NTOK + 127)/128), blk>>>(
        kvc, wkv_b, kvb, NTOK, NH*(NOPE+VD), KV_LORA);
    // flash attention (scale folded into Q load)
    cudaFuncSetAttribute(attn_kernel, cudaFuncAttributeMaxDynamicSharedMemorySize,
                         (int)sizeof(AttnSmem));
    attn_kernel<<<dim3(SEQ/AT_BM, NH, BATCH), 256, sizeof(AttnSmem)>>>(
        q, kvb, kpe, attn, scale);
    // out = attn @ wo^T  [4096, 2048]
    sgemm_nt<<<dim3((DIM + 127)/128, (NTOK + 127)/128), blk>>>(
        attn, wo, out, NTOK, DIM, NH*VD);
}

// round 6
// speedup vs baseline: 1.1572x; 1.1572x over previous
#include <cuda_runtime.h>
#include <cuda_bf16.h>
#include <math.h>

#define DIM 2048
#define NH 16
#define KV_LORA 512
#define NOPE 128
#define ROPE_D 64
#define VD 128
#define QKD 192
#define BATCH 2
#define SEQ 2048
#define NTOK (BATCH*SEQ)

// ---------------- scratch (static device arrays; no allocation) --------------
__device__ float g_q[(size_t)NTOK * NH * QKD];            // 4096 x 3072
__device__ float g_kv[(size_t)NTOK * (KV_LORA + ROPE_D)]; // 4096 x 576
__device__ float g_kvc[(size_t)NTOK * KV_LORA];           // 4096 x 512
__device__ float g_kpe[(size_t)NTOK * ROPE_D];            // 4096 x 64
__device__ float g_kvb[(size_t)NTOK * NH * (NOPE + VD)];  // 4096 x 4096
__device__ float g_attn[(size_t)NTOK * NH * VD];          // 4096 x 2048

// ------- generic NT SGEMM, double-buffered: C[M,N] = A[M,K] * B[N,K]^T -------
__global__ void __launch_bounds__(256, 2)
sgemm_nt(const float* __restrict__ A, const float* __restrict__ B,
         float* __restrict__ C, int M, int N, int K)
{
    __shared__ float As[2][8][132];
    __shared__ float Bs[2][8][132];
    const int tid  = threadIdx.x;
    const int tx   = tid & 15, ty = tid >> 4;
    const int bm   = blockIdx.y * 128;
    const int bn   = blockIdx.x * 128;
    const int lrow = tid >> 1;
    const int lseg = tid & 1;

    const bool aval = (bm + lrow) < M;
    const bool bval = (bn + lrow) < N;
    const float* Ap = A + (size_t)(bm + lrow) * K + lseg * 4;
    const float* Bp = B + (size_t)(bn + lrow) * K + lseg * 4;

    float acc[8][8];
#pragma unroll
    for (int i = 0; i < 8; i++)
#pragma unroll
        for (int j = 0; j < 8; j++) acc[i][j] = 0.f;

    // prologue: load first K-slab into stage 0
    float4 av = make_float4(0.f,0.f,0.f,0.f), bv = make_float4(0.f,0.f,0.f,0.f);
    if (aval) av = *reinterpret_cast<const float4*>(Ap);
    if (bval) bv = *reinterpret_cast<const float4*>(Bp);
    As[0][lseg*4+0][lrow] = av.x; As[0][lseg*4+1][lrow] = av.y;
    As[0][lseg*4+2][lrow] = av.z; As[0][lseg*4+3][lrow] = av.w;
    Bs[0][lseg*4+0][lrow] = bv.x; Bs[0][lseg*4+1][lrow] = bv.y;
    Bs[0][lseg*4+2][lrow] = bv.z; Bs[0][lseg*4+3][lrow] = bv.w;
    __syncthreads();

    int buf = 0;
    for (int kt = 0; kt < K; kt += 8) {
        const bool more = (kt + 8) < K;
        if (more) {
            av = make_float4(0.f,0.f,0.f,0.f); bv = av;
            if (aval) av = *reinterpret_cast<const float4*>(Ap + kt + 8);
            if (bval) bv = *reinterpret_cast<const float4*>(Bp + kt + 8);
        }
#pragma unroll
        for (int kk = 0; kk < 8; kk++) {
            float4 a0 = *reinterpret_cast<const float4*>(&As[buf][kk][ty*8]);
            float4 a1 = *reinterpret_cast<const float4*>(&As[buf][kk][ty*8+4]);
            float4 b0 = *reinterpret_cast<const float4*>(&Bs[buf][kk][tx*8]);
            float4 b1 = *reinterpret_cast<const float4*>(&Bs[buf][kk][tx*8+4]);
            float a[8] = {a0.x,a0.y,a0.z,a0.w,a1.x,a1.y,a1.z,a1.w};
            float b[8] = {b0.x,b0.y,b0.z,b0.w,b1.x,b1.y,b1.z,b1.w};
#pragma unroll
            for (int i = 0; i < 8; i++)
#pragma unroll
                for (int j = 0; j < 8; j++) acc[i][j] += a[i]*b[j];
        }
        if (more) {
            int nb = buf ^ 1;
            As[nb][lseg*4+0][lrow] = av.x; As[nb][lseg*4+1][lrow] = av.y;
            As[nb][lseg*4+2][lrow] = av.z; As[nb][lseg*4+3][lrow] = av.w;
            Bs[nb][lseg*4+0][lrow] = bv.x; Bs[nb][lseg*4+1][lrow] = bv.y;
            Bs[nb][lseg*4+2][lrow] = bv.z; Bs[nb][lseg*4+3][lrow] = bv.w;
            __syncthreads();
            buf = nb;
        }
    }
#pragma unroll
    for (int i = 0; i < 8; i++) {
        int row = bm + ty*8 + i;
        if (row >= M) continue;
#pragma unroll
        for (int j = 0; j < 8; j++) {
            int col = bn + tx*8 + j;
            if (col < N) C[(size_t)row * N + col] = acc[i][j];
        }
    }
}

// ------------- prep: RMSNorm(kv_c), RoPE(k_pe).  NOTE: reference does NOT ----
// ------------- rotate q_pe (it rotates a copy and drops it), so q is untouched.
__global__ void __launch_bounds__(256)
prep_kernel(const float* __restrict__ kv,
            const float* __restrict__ kvnw,
            const float* __restrict__ fcos, const float* __restrict__ fsin,
            float* __restrict__ kvc, float* __restrict__ kpe)
{
    const int token = blockIdx.x;
    const int spos  = token & (SEQ - 1);
    const int tid   = threadIdx.x;
    __shared__ float red[256];

    const float* kvrow = kv + (size_t)token * (KV_LORA + ROPE_D);
    float ss = 0.f;
    for (int i = tid; i < KV_LORA; i += 256) { float v = kvrow[i]; ss += v*v; }
    red[tid] = ss;
    __syncthreads();
    for (int st = 128; st > 0; st >>= 1) {
        if (tid < st) red[tid] += red[tid + st];
        __syncthreads();
    }
    const float rms = rsqrtf(red[0] / (float)KV_LORA + 1e-6f);

    for (int i = tid; i < KV_LORA; i += 256)
        kvc[(size_t)token * KV_LORA + i] = kvrow[i] * rms * kvnw[i];

    if (tid < 32) {
        float re = kvrow[KV_LORA + 2*tid], im = kvrow[KV_LORA + 2*tid + 1];
        float c = fcos[spos*32 + tid], s = fsin[spos*32 + tid];
        kpe[(size_t)token * ROPE_D + 2*tid]     = re*c - im*s;
        kpe[(size_t)token * ROPE_D + 2*tid + 1] = re*s + im*c;
    }
}

// ------------------------------- flash attention -----------------------------
#define AT_BM 64
#define AT_BN 64

struct AttnSmem {
    float Qst[QKD][68];    // [k][q_row]   (transposed, pre-scaled)
    float Kst[QKD][68];    // [k][k_row]
    float Vs[AT_BN][132];  // [k_row][v_dim]
    float Ps[AT_BM][68];   // scores / probs, row-major
    float corr_s[AT_BM];   // per-row online-softmax rescale for this tile
    float l_s[AT_BM];      // per-row final denominators
};

__global__ void __launch_bounds__(256, 1)
attn_kernel(const float* __restrict__ q, const float* __restrict__ kvb,
            const float* __restrict__ kpe, float* __restrict__ attn_out,
            float scale)
{
    extern __shared__ char smem_raw[];
    AttnSmem& sm = *reinterpret_cast<AttnSmem*>(smem_raw);
    const int qi = blockIdx.x;  // query tile 0..31
    const int h  = blockIdx.y;  // head
    const int b  = blockIdx.z;  // batch
    const int tid = threadIdx.x;
    const int tx = tid & 15, ty = tid >> 4;  // compute mapping (16x16 grid)
    const int r  = tid >> 2;                 // softmax mapping: query row
    const int vs = tid & 3;                  // softmax col-slice
    const size_t tokq0 = (size_t)b * SEQ + qi * AT_BM;

    // load Q tile transposed, softmax scale folded in (q is UNROTATED,
    // matching the reference which drops its rotated q_pe copy)
    for (int i = tid; i < AT_BM * (QKD/4); i += 256) {
        int row = i / (QKD/4), c4 = i % (QKD/4);
        float4 v = *reinterpret_cast<const float4*>(
            &q[(tokq0 + row) * (size_t)(NH*QKD) + h*QKD + c4*4]);
        sm.Qst[c4*4+0][row] = v.x * scale; sm.Qst[c4*4+1][row] = v.y * scale;
        sm.Qst[c4*4+2][row] = v.z * scale; sm.Qst[c4*4+3][row] = v.w * scale;
    }

    // O accumulator: rows ty*4+i, v-dims tx*8+j  (register-blocked PV)
    float o[4][8];
#pragma unroll
    for (int i = 0; i < 4; i++)
#pragma unroll
        for (int j = 0; j < 8; j++) o[i][j] = 0.f;
    float m_r = -1e30f, l_r = 0.f;   // tracked by softmax mapping (row r)

    for (int j = 0; j <= qi; j++) {
        __syncthreads();  // previous tile's Ps/Vs fully consumed
        const size_t tokk0 = (size_t)b * SEQ + j * AT_BN;
        // K tile (k_nope from kvb, k_pe shared across heads) transposed
        for (int i = tid; i < AT_BN * (QKD/4); i += 256) {
            int row = i / (QKD/4), c4 = i % (QKD/4);
            float4 v;
            if (c4 < NOPE/4)
                v = *reinterpret_cast<const float4*>(
                    &kvb[(tokk0 + row) * (size_t)(NH*(NOPE+VD)) + h*(NOPE+VD) + c4*4]);
            else
                v = *reinterpret_cast<const float4*>(
                    &kpe[(tokk0 + row) * (size_t)ROPE_D + (c4 - NOPE/4)*4]);
            sm.Kst[c4*4+0][row] = v.x; sm.Kst[c4*4+1][row] = v.y;
            sm.Kst[c4*4+2][row] = v.z; sm.Kst[c4*4+3][row] = v.w;
        }
        // V tile
        for (int i = tid; i < AT_BN * (VD/4); i += 256) {
            int row = i / (VD/4), c4 = i % (VD/4);
            float4 v = *reinterpret_cast<const float4*>(
                &kvb[(tokk0 + row) * (size_t)(NH*(NOPE+VD)) + h*(NOPE+VD) + NOPE + c4*4]);
            sm.Vs[row][c4*4+0] = v.x; sm.Vs[row][c4*4+1] = v.y;
            sm.Vs[row][c4*4+2] = v.z; sm.Vs[row][c4*4+3] = v.w;
        }
        __syncthreads();

        // S = Q K^T : 4x4 per thread over 16x16 grid
        float acc[4][4];
#pragma unroll
        for (int i = 0; i < 4; i++)
#pragma unroll
            for (int jj = 0; jj < 4; jj++) acc[i][jj] = 0.f;
#pragma unroll 4
        for (int k = 0; k < QKD; k++) {
            float4 a  = *reinterpret_cast<const float4*>(&sm.Qst[k][ty*4]);
            float4 bb = *reinterpret_cast<const float4*>(&sm.Kst[k][tx*4]);
            float av[4] = {a.x, a.y, a.z, a.w};
            float bv[4] = {bb.x, bb.y, bb.z, bb.w};
#pragma unroll
            for (int i = 0; i < 4; i++)
#pragma unroll
                for (int jj = 0; jj < 4; jj++) acc[i][jj] += av[i]*bv[jj];
        }
        const bool diag = (j == qi);
#pragma unroll
        for (int i = 0; i < 4; i++) {
            int lr = ty*4 + i;
            float t0 = (diag && (tx*4+0) > lr) ? -1e30f : acc[i][0];
            float t1 = (diag && (tx*4+1) > lr) ? -1e30f : acc[i][1];
            float t2 = (diag && (tx*4+2) > lr) ? -1e30f : acc[i][2];
            float t3 = (diag && (tx*4+3) > lr) ? -1e30f : acc[i][3];
            *reinterpret_cast<float4*>(&sm.Ps[lr][tx*4]) = make_float4(t0,t1,t2,t3);
        }
        __syncthreads();

        // online softmax: 4 threads per row, each owns cols [vs*16, vs*16+16)
        {
            float rmax = -1e30f;
#pragma unroll
            for (int t = 0; t < 16; t++) rmax = fmaxf(rmax, sm.Ps[r][vs*16 + t]);
            rmax = fmaxf(rmax, __shfl_xor_sync(0xffffffffu, rmax, 1));
            rmax = fmaxf(rmax, __shfl_xor_sync(0xffffffffu, rmax, 2));
            float m_new = fmaxf(m_r, rmax);
            float corr  = __expf(m_r - m_new);
            float lp = 0.f;
#pragma unroll
            for (int t = 0; t < 16; t++) {
                float svv = sm.Ps[r][vs*16 + t];
                float p = (svv < -1e29f) ? 0.f : __expf(svv - m_new);
                sm.Ps[r][vs*16 + t] = p;   // each lane owns its own 16 cols
                lp += p;
            }
            lp += __shfl_xor_sync(0xffffffffu, lp, 1);
            lp += __shfl_xor_sync(0xffffffffu, lp, 2);
            l_r = l_r * corr + lp;
            m_r = m_new;
            if (vs == 0) sm.corr_s[r] = corr;
        }
        __syncthreads();   // probs + corr_s visible to compute mapping

        // O = corr*O + P V  (register-blocked: 4 rows x 8 v-dims per thread)
        {
            float c0 = sm.corr_s[ty*4+0], c1 = sm.corr_s[ty*4+1];
            float c2 = sm.corr_s[ty*4+2], c3 = sm.corr_s[ty*4+3];
#pragma unroll
            for (int jj = 0; jj < 8; jj++) {
                o[0][jj] *= c0; o[1][jj] *= c1; o[2][jj] *= c2; o[3][jj] *= c3;
            }
#pragma unroll 4
            for (int k = 0; k < AT_BN; k++) {
                float4 v0 = *reinterpret_cast<const float4*>(&sm.Vs[k][tx*8]);
                float4 v1 = *reinterpret_cast<const float4*>(&sm.Vs[k][tx*8+4]);
                float vv[8] = {v0.x,v0.y,v0.z,v0.w,v1.x,v1.y,v1.z,v1.w};
                float p0 = sm.Ps[ty*4+0][k];
                float p1 = sm.Ps[ty*4+1][k];
                float p2 = sm.Ps[ty*4+2][k];
                float p3 = sm.Ps[ty*4+3][k];
#pragma unroll
                for (int jj = 0; jj < 8; jj++) {
                    o[0][jj] += p0 * vv[jj];
                    o[1][jj] += p1 * vv[jj];
                    o[2][jj] += p2 * vv[jj];
                    o[3][jj] += p3 * vv[jj];
                }
            }
        }
    }

    // publish per-row denominators, then write O
    if (vs == 0) sm.l_s[r] = l_r;
    __syncthreads();
#pragma unroll
    for (int i = 0; i < 4; i++) {
        int row = ty*4 + i;
        float inv = 1.f / sm.l_s[row];
        float4 w0 = make_float4(o[i][0]*inv, o[i][1]*inv, o[i][2]*inv, o[i][3]*inv);
        float4 w1 = make_float4(o[i][4]*inv, o[i][5]*inv, o[i][6]*inv, o[i][7]*inv);
        float* dst = &attn_out[(tokq0 + row) * (size_t)(NH*VD) + h*VD + tx*8];
        *reinterpret_cast<float4*>(dst)     = w0;
        *reinterpret_cast<float4*>(dst + 4) = w1;
    }
}

// ---------------------------------- launch -----------------------------------
extern "C" void kernel_launch(void* const* d_in, const int* in_sizes, int n_in,
                              void* d_out, int out_size)
{
    const float* x     = (const float*)d_in[0];
    const float* wq    = (const float*)d_in[1];
    const float* wkv_a = (const float*)d_in[2];
    const float* kvnw  = (const float*)d_in[3];
    const float* wkv_b = (const float*)d_in[4];
    const float* wo    = (const float*)d_in[5];
    const float* fcos  = (const float*)d_in[6];
    const float* fsin  = (const float*)d_in[7];
    float* out = (float*)d_out;

    float *q, *kv, *kvc, *kpe, *kvb, *attn;
    cudaGetSymbolAddress((void**)&q,    g_q);
    cudaGetSymbolAddress((void**)&kv,   g_kv);
    cudaGetSymbolAddress((void**)&kvc,  g_kvc);
    cudaGetSymbolAddress((void**)&kpe,  g_kpe);
    cudaGetSymbolAddress((void**)&kvb,  g_kvb);
    cudaGetSymbolAddress((void**)&attn, g_attn);

    // softmax scale: qk_dim^-0.5 * mscale^2 (yarn, MAX_LEN > ORIG_LEN)
    double mm = 0.1 * 1.0 * log(40.0) + 1.0;
    float scale = (float)(mm * mm / sqrt((double)QKD));

    dim3 blk(256);
    // q = x @ wq^T    [4096, 3072]
    sgemm_nt<<<dim3((NH*QKD + 127)/128, (NTOK + 127)/128), blk>>>(
        x, wq, q, NTOK, NH*QKD, DIM);
    // kv = x @ wkv_a^T  [4096, 576]
    sgemm_nt<<<dim3((KV_LORA + ROPE_D + 127)/128, (NTOK + 127)/128), blk>>>(
        x, wkv_a, kv, NTOK, KV_LORA + ROPE_D, DIM);
    // rmsnorm + k_pe rope (q is NOT rotated — matches reference semantics)
    prep_kernel<<<NTOK, 256>>>(kv, kvnw, fcos, fsin, kvc, kpe);
    // kvb = kvc @ wkv_b^T  [4096, 4096]
    sgemm_nt<<<dim3((NH*(NOPE+VD) + 127)/128, (NTOK + 127)/128), blk>>>(
        kvc, wkv_b, kvb, NTOK, NH*(NOPE+VD), KV_LORA);
    // flash attention (scale folded into Q load)
    cudaFuncSetAttribute(attn_kernel, cudaFuncAttributeMaxDynamicSharedMemorySize,
                         (int)sizeof(AttnSmem));
    attn_kernel<<<dim3(SEQ/AT_BM, NH, BATCH), 256, sizeof(AttnSmem)>>>(
        q, kvb, kpe, attn, scale);
    // out = attn @ wo^T  [4096, 2048]
    sgemm_nt<<<dim3((DIM + 127)/128, (NTOK + 127)/128), blk>>>(
        attn, wo, out, NTOK, DIM, NH*VD);
}

// round 7
// speedup vs baseline: 1.1633x; 1.0053x over previous
#include <cuda_runtime.h>
#include <cuda_bf16.h>
#include <math.h>

#define DIM 2048
#define NH 16
#define KV_LORA 512
#define NOPE 128
#define ROPE_D 64
#define VD 128
#define QKD 192
#define BATCH 2
#define SEQ 2048
#define NTOK (BATCH*SEQ)

// ---------------- scratch (static device arrays; no allocation) --------------
__device__ float g_q[(size_t)NTOK * NH * QKD];            // 4096 x 3072
__device__ float g_kv[(size_t)NTOK * (KV_LORA + ROPE_D)]; // 4096 x 576
__device__ float g_kvc[(size_t)NTOK * KV_LORA];           // 4096 x 512
__device__ float g_kpe[(size_t)NTOK * ROPE_D];            // 4096 x 64
__device__ float g_kvb[(size_t)NTOK * NH * (NOPE + VD)];  // 4096 x 4096
__device__ float g_attn[(size_t)NTOK * NH * VD];          // 4096 x 2048

// ------- generic NT SGEMM, double-buffered: C[M,N] = A[M,K] * B[N,K]^T -------
__global__ void __launch_bounds__(256, 2)
sgemm_nt(const float* __restrict__ A, const float* __restrict__ B,
         float* __restrict__ C, int M, int N, int K)
{
    __shared__ float As[2][8][132];
    __shared__ float Bs[2][8][132];
    const int tid  = threadIdx.x;
    const int tx   = tid & 15, ty = tid >> 4;
    const int bm   = blockIdx.y * 128;
    const int bn   = blockIdx.x * 128;
    const int lrow = tid >> 1;
    const int lseg = tid & 1;

    const bool aval = (bm + lrow) < M;
    const bool bval = (bn + lrow) < N;
    const float* Ap = A + (size_t)(bm + lrow) * K + lseg * 4;
    const float* Bp = B + (size_t)(bn + lrow) * K + lseg * 4;

    float acc[8][8];
#pragma unroll
    for (int i = 0; i < 8; i++)
#pragma unroll
        for (int j = 0; j < 8; j++) acc[i][j] = 0.f;

    // prologue: load first K-slab into stage 0
    float4 av = make_float4(0.f,0.f,0.f,0.f), bv = make_float4(0.f,0.f,0.f,0.f);
    if (aval) av = *reinterpret_cast<const float4*>(Ap);
    if (bval) bv = *reinterpret_cast<const float4*>(Bp);
    As[0][lseg*4+0][lrow] = av.x; As[0][lseg*4+1][lrow] = av.y;
    As[0][lseg*4+2][lrow] = av.z; As[0][lseg*4+3][lrow] = av.w;
    Bs[0][lseg*4+0][lrow] = bv.x; Bs[0][lseg*4+1][lrow] = bv.y;
    Bs[0][lseg*4+2][lrow] = bv.z; Bs[0][lseg*4+3][lrow] = bv.w;
    __syncthreads();

    int buf = 0;
    for (int kt = 0; kt < K; kt += 8) {
        const bool more = (kt + 8) < K;
        if (more) {
            av = make_float4(0.f,0.f,0.f,0.f); bv = av;
            if (aval) av = *reinterpret_cast<const float4*>(Ap + kt + 8);
            if (bval) bv = *reinterpret_cast<const float4*>(Bp + kt + 8);
        }
#pragma unroll
        for (int kk = 0; kk < 8; kk++) {
            float4 a0 = *reinterpret_cast<const float4*>(&As[buf][kk][ty*8]);
            float4 a1 = *reinterpret_cast<const float4*>(&As[buf][kk][ty*8+4]);
            float4 b0 = *reinterpret_cast<const float4*>(&Bs[buf][kk][tx*8]);
            float4 b1 = *reinterpret_cast<const float4*>(&Bs[buf][kk][tx*8+4]);
            float a[8] = {a0.x,a0.y,a0.z,a0.w,a1.x,a1.y,a1.z,a1.w};
            float b[8] = {b0.x,b0.y,b0.z,b0.w,b1.x,b1.y,b1.z,b1.w};
#pragma unroll
            for (int i = 0; i < 8; i++)
#pragma unroll
                for (int j = 0; j < 8; j++) acc[i][j] += a[i]*b[j];
        }
        if (more) {
            int nb = buf ^ 1;
            As[nb][lseg*4+0][lrow] = av.x; As[nb][lseg*4+1][lrow] = av.y;
            As[nb][lseg*4+2][lrow] = av.z; As[nb][lseg*4+3][lrow] = av.w;
            Bs[nb][lseg*4+0][lrow] = bv.x; Bs[nb][lseg*4+1][lrow] = bv.y;
            Bs[nb][lseg*4+2][lrow] = bv.z; Bs[nb][lseg*4+3][lrow] = bv.w;
            __syncthreads();
            buf = nb;
        }
    }
#pragma unroll
    for (int i = 0; i < 8; i++) {
        int row = bm + ty*8 + i;
        if (row >= M) continue;
#pragma unroll
        for (int j = 0; j < 8; j++) {
            int col = bn + tx*8 + j;
            if (col < N) C[(size_t)row * N + col] = acc[i][j];
        }
    }
}

// ------------- prep: RMSNorm(kv_c), RoPE(k_pe).  NOTE: reference does NOT ----
// ------------- rotate q_pe (it rotates a copy and drops it), so q is untouched.
__global__ void __launch_bounds__(256)
prep_kernel(const float* __restrict__ kv,
            const float* __restrict__ kvnw,
            const float* __restrict__ fcos, const float* __restrict__ fsin,
            float* __restrict__ kvc, float* __restrict__ kpe)
{
    const int token = blockIdx.x;
    const int spos  = token & (SEQ - 1);
    const int tid   = threadIdx.x;
    __shared__ float red[256];

    const float* kvrow = kv + (size_t)token * (KV_LORA + ROPE_D);
    float ss = 0.f;
    for (int i = tid; i < KV_LORA; i += 256) { float v = kvrow[i]; ss += v*v; }
    red[tid] = ss;
    __syncthreads();
    for (int st = 128; st > 0; st >>= 1) {
        if (tid < st) red[tid] += red[tid + st];
        __syncthreads();
    }
    const float rms = rsqrtf(red[0] / (float)KV_LORA + 1e-6f);

    for (int i = tid; i < KV_LORA; i += 256)
        kvc[(size_t)token * KV_LORA + i] = kvrow[i] * rms * kvnw[i];

    if (tid < 32) {
        float re = kvrow[KV_LORA + 2*tid], im = kvrow[KV_LORA + 2*tid + 1];
        float c = fcos[spos*32 + tid], s = fsin[spos*32 + tid];
        kpe[(size_t)token * ROPE_D + 2*tid]     = re*c - im*s;
        kpe[(size_t)token * ROPE_D + 2*tid + 1] = re*s + im*c;
    }
}

// ------------------------------- flash attention -----------------------------
#define AT_BM 64
#define AT_BN 64

struct AttnSmem {
    float Qst[QKD][68];    // [k][q_row]   (transposed, pre-scaled)
    float Kst[QKD][68];    // [k][k_row]
    float Vs[AT_BN][132];  // [k_row][v_dim]
    float Ps[AT_BM][68];   // scores / probs, row-major
    float corr_s[AT_BM];   // per-row online-softmax rescale for this tile
    float l_s[AT_BM];      // per-row final denominators
};

__global__ void __launch_bounds__(256, 1)
attn_kernel(const float* __restrict__ q, const float* __restrict__ kvb,
            const float* __restrict__ kpe, float* __restrict__ attn_out,
            float scale)
{
    extern __shared__ char smem_raw[];
    AttnSmem& sm = *reinterpret_cast<AttnSmem*>(smem_raw);
    const int qi = blockIdx.x;  // query tile 0..31
    const int h  = blockIdx.y;  // head
    const int b  = blockIdx.z;  // batch
    const int tid = threadIdx.x;
    const int tx = tid & 15, ty = tid >> 4;  // compute mapping (16x16 grid)
    const int r  = tid >> 2;                 // softmax mapping: query row
    const int vs = tid & 3;                  // softmax col-slice
    const size_t tokq0 = (size_t)b * SEQ + qi * AT_BM;

    // load Q tile transposed, softmax scale folded in (q is UNROTATED,
    // matching the reference which drops its rotated q_pe copy)
    for (int i = tid; i < AT_BM * (QKD/4); i += 256) {
        int row = i / (QKD/4), c4 = i % (QKD/4);
        float4 v = *reinterpret_cast<const float4*>(
            &q[(tokq0 + row) * (size_t)(NH*QKD) + h*QKD + c4*4]);
        sm.Qst[c4*4+0][row] = v.x * scale; sm.Qst[c4*4+1][row] = v.y * scale;
        sm.Qst[c4*4+2][row] = v.z * scale; sm.Qst[c4*4+3][row] = v.w * scale;
    }

    // O accumulator: rows ty*4+i, v-dims tx*8+j  (register-blocked PV)
    float o[4][8];
#pragma unroll
    for (int i = 0; i < 4; i++)
#pragma unroll
        for (int j = 0; j < 8; j++) o[i][j] = 0.f;
    float m_r = -1e30f, l_r = 0.f;   // tracked by softmax mapping (row r)

    for (int j = 0; j <= qi; j++) {
        __syncthreads();  // previous tile's Ps/Vs fully consumed
        const size_t tokk0 = (size_t)b * SEQ + j * AT_BN;
        // K tile (k_nope from kvb, k_pe shared across heads) transposed
        for (int i = tid; i < AT_BN * (QKD/4); i += 256) {
            int row = i / (QKD/4), c4 = i % (QKD/4);
            float4 v;
            if (c4 < NOPE/4)
                v = *reinterpret_cast<const float4*>(
                    &kvb[(tokk0 + row) * (size_t)(NH*(NOPE+VD)) + h*(NOPE+VD) + c4*4]);
            else
                v = *reinterpret_cast<const float4*>(
                    &kpe[(tokk0 + row) * (size_t)ROPE_D + (c4 - NOPE/4)*4]);
            sm.Kst[c4*4+0][row] = v.x; sm.Kst[c4*4+1][row] = v.y;
            sm.Kst[c4*4+2][row] = v.z; sm.Kst[c4*4+3][row] = v.w;
        }
        // V tile
        for (int i = tid; i < AT_BN * (VD/4); i += 256) {
            int row = i / (VD/4), c4 = i % (VD/4);
            float4 v = *reinterpret_cast<const float4*>(
                &kvb[(tokk0 + row) * (size_t)(NH*(NOPE+VD)) + h*(NOPE+VD) + NOPE + c4*4]);
            sm.Vs[row][c4*4+0] = v.x; sm.Vs[row][c4*4+1] = v.y;
            sm.Vs[row][c4*4+2] = v.z; sm.Vs[row][c4*4+3] = v.w;
        }
        __syncthreads();

        // S = Q K^T : 4x4 per thread over 16x16 grid
        float acc[4][4];
#pragma unroll
        for (int i = 0; i < 4; i++)
#pragma unroll
            for (int jj = 0; jj < 4; jj++) acc[i][jj] = 0.f;
#pragma unroll 4
        for (int k = 0; k < QKD; k++) {
            float4 a  = *reinterpret_cast<const float4*>(&sm.Qst[k][ty*4]);
            float4 bb = *reinterpret_cast<const float4*>(&sm.Kst[k][tx*4]);
            float av[4] = {a.x, a.y, a.z, a.w};
            float bv[4] = {bb.x, bb.y, bb.z, bb.w};
#pragma unroll
            for (int i = 0; i < 4; i++)
#pragma unroll
                for (int jj = 0; jj < 4; jj++) acc[i][jj] += av[i]*bv[jj];
        }
        const bool diag = (j == qi);
#pragma unroll
        for (int i = 0; i < 4; i++) {
            int lr = ty*4 + i;
            float t0 = (diag && (tx*4+0) > lr) ? -1e30f : acc[i][0];
            float t1 = (diag && (tx*4+1) > lr) ? -1e30f : acc[i][1];
            float t2 = (diag && (tx*4+2) > lr) ? -1e30f : acc[i][2];
            float t3 = (diag && (tx*4+3) > lr) ? -1e30f : acc[i][3];
            *reinterpret_cast<float4*>(&sm.Ps[lr][tx*4]) = make_float4(t0,t1,t2,t3);
        }
        __syncthreads();

        // online softmax: 4 threads per row, each owns cols [vs*16, vs*16+16)
        {
            float rmax = -1e30f;
#pragma unroll
            for (int t = 0; t < 16; t++) rmax = fmaxf(rmax, sm.Ps[r][vs*16 + t]);
            rmax = fmaxf(rmax, __shfl_xor_sync(0xffffffffu, rmax, 1));
            rmax = fmaxf(rmax, __shfl_xor_sync(0xffffffffu, rmax, 2));
            float m_new = fmaxf(m_r, rmax);
            float corr  = __expf(m_r - m_new);
            float lp = 0.f;
#pragma unroll
            for (int t = 0; t < 16; t++) {
                float svv = sm.Ps[r][vs*16 + t];
                float p = (svv < -1e29f) ? 0.f : __expf(svv - m_new);
                sm.Ps[r][vs*16 + t] = p;   // each lane owns its own 16 cols
                lp += p;
            }
            lp += __shfl_xor_sync(0xffffffffu, lp, 1);
            lp += __shfl_xor_sync(0xffffffffu, lp, 2);
            l_r = l_r * corr + lp;
            m_r = m_new;
            if (vs == 0) sm.corr_s[r] = corr;
        }
        __syncthreads();   // probs + corr_s visible to compute mapping

        // O = corr*O + P V  (register-blocked: 4 rows x 8 v-dims per thread)
        {
            float c0 = sm.corr_s[ty*4+0], c1 = sm.corr_s[ty*4+1];
            float c2 = sm.corr_s[ty*4+2], c3 = sm.corr_s[ty*4+3];
#pragma unroll
            for (int jj = 0; jj < 8; jj++) {
                o[0][jj] *= c0; o[1][jj] *= c1; o[2][jj] *= c2; o[3][jj] *= c3;
            }
#pragma unroll 4
            for (int k = 0; k < AT_BN; k++) {
                float4 v0 = *reinterpret_cast<const float4*>(&sm.Vs[k][tx*8]);
                float4 v1 = *reinterpret_cast<const float4*>(&sm.Vs[k][tx*8+4]);
                float vv[8] = {v0.x,v0.y,v0.z,v0.w,v1.x,v1.y,v1.z,v1.w};
                float p0 = sm.Ps[ty*4+0][k];
                float p1 = sm.Ps[ty*4+1][k];
                float p2 = sm.Ps[ty*4+2][k];
                float p3 = sm.Ps[ty*4+3][k];
#pragma unroll
                for (int jj = 0; jj < 8; jj++) {
                    o[0][jj] += p0 * vv[jj];
                    o[1][jj] += p1 * vv[jj];
                    o[2][jj] += p2 * vv[jj];
                    o[3][jj] += p3 * vv[jj];
                }
            }
        }
    }

    // publish per-row denominators, then write O
    if (vs == 0) sm.l_s[r] = l_r;
    __syncthreads();
#pragma unroll
    for (int i = 0; i < 4; i++) {
        int row = ty*4 + i;
        float inv = 1.f / sm.l_s[row];
        float4 w0 = make_float4(o[i][0]*inv, o[i][1]*inv, o[i][2]*inv, o[i][3]*inv);
        float4 w1 = make_float4(o[i][4]*inv, o[i][5]*inv, o[i][6]*inv, o[i][7]*inv);
        float* dst = &attn_out[(tokq0 + row) * (size_t)(NH*VD) + h*VD + tx*8];
        *reinterpret_cast<float4*>(dst)     = w0;
        *reinterpret_cast<float4*>(dst + 4) = w1;
    }
}

// ---------------------------------- launch -----------------------------------
extern "C" void kernel_launch(void* const* d_in, const int* in_sizes, int n_in,
                              void* d_out, int out_size)
{
    const float* x     = (const float*)d_in[0];
    const float* wq    = (const float*)d_in[1];
    const float* wkv_a = (const float*)d_in[2];
    const float* kvnw  = (const float*)d_in[3];
    const float* wkv_b = (const float*)d_in[4];
    const float* wo    = (const float*)d_in[5];
    const float* fcos  = (const float*)d_in[6];
    const float* fsin  = (const float*)d_in[7];
    float* out = (float*)d_out;

    float *q, *kv, *kvc, *kpe, *kvb, *attn;
    cudaGetSymbolAddress((void**)&q,    g_q);
    cudaGetSymbolAddress((void**)&kv,   g_kv);
    cudaGetSymbolAddress((void**)&kvc,  g_kvc);
    cudaGetSymbolAddress((void**)&kpe,  g_kpe);
    cudaGetSymbolAddress((void**)&kvb,  g_kvb);
    cudaGetSymbolAddress((void**)&attn, g_attn);

    // softmax scale: qk_dim^-0.5 * mscale^2 (yarn, MAX_LEN > ORIG_LEN)
    double mm = 0.1 * 1.0 * log(40.0) + 1.0;
    float scale = (float)(mm * mm / sqrt((double)QKD));

    dim3 blk(256);
    // q = x @ wq^T    [4096, 3072]
    sgemm_nt<<<dim3((NH*QKD + 127)/128, (NTOK + 127)/128), blk>>>(
        x, wq, q, NTOK, NH*QKD, DIM);
    // kv = x @ wkv_a^T  [4096, 576]
    sgemm_nt<<<dim3((KV_LORA + ROPE_D + 127)/128, (NTOK + 127)/128), blk>>>(
        x, wkv_a, kv, NTOK, KV_LORA + ROPE_D, DIM);
    // rmsnorm + k_pe rope (q is NOT rotated — matches reference semantics)
    prep_kernel<<<NTOK, 256>>>(kv, kvnw, fcos, fsin, kvc, kpe);
    // kvb = kvc @ wkv_b^T  [4096, 4096]
    sgemm_nt<<<dim3((NH*(NOPE+VD) + 127)/128, (NTOK + 127)/128), blk>>>(
        kvc, wkv_b, kvb, NTOK, NH*(NOPE+VD), KV_LORA);
    // flash attention (scale folded into Q load)
    cudaFuncSetAttribute(attn_kernel, cudaFuncAttributeMaxDynamicSharedMemorySize,
                         (int)sizeof(AttnSmem));
    attn_kernel<<<dim3(SEQ/AT_BM, NH, BATCH), 256, sizeof(AttnSmem)>>>(
        q, kvb, kpe, attn, scale);
    // out = attn @ wo^T  [4096, 2048]
    sgemm_nt<<<dim3((DIM + 127)/128, (NTOK + 127)/128), blk>>>(
        attn, wo, out, NTOK, DIM, NH*VD);
}

// round 8
// speedup vs baseline: 1.1639x; 1.0005x over previous
#include <cuda_runtime.h>
#include <cuda_bf16.h>
#include <math.h>

#define DIM 2048
#define NH 16
#define KV_LORA 512
#define NOPE 128
#define ROPE_D 64
#define VD 128
#define QKD 192
#define BATCH 2
#define SEQ 2048
#define NTOK (BATCH*SEQ)

// ---------------- scratch (static device arrays; no allocation) --------------
__device__ float g_q[(size_t)NTOK * NH * QKD];            // 4096 x 3072
__device__ float g_kv[(size_t)NTOK * (KV_LORA + ROPE_D)]; // 4096 x 576
__device__ float g_kvc[(size_t)NTOK * KV_LORA];           // 4096 x 512
__device__ float g_kpe[(size_t)NTOK * ROPE_D];            // 4096 x 64
__device__ float g_kvb[(size_t)NTOK * NH * (NOPE + VD)];  // 4096 x 4096
__device__ float g_attn[(size_t)NTOK * NH * VD];          // 4096 x 2048

// ------- generic NT SGEMM, double-buffered: C[M,N] = A[M,K] * B[N,K]^T -------
__global__ void __launch_bounds__(256, 2)
sgemm_nt(const float* __restrict__ A, const float* __restrict__ B,
         float* __restrict__ C, int M, int N, int K)
{
    __shared__ float As[2][8][132];
    __shared__ float Bs[2][8][132];
    const int tid  = threadIdx.x;
    const int tx   = tid & 15, ty = tid >> 4;
    const int bm   = blockIdx.y * 128;
    const int bn   = blockIdx.x * 128;
    const int lrow = tid >> 1;
    const int lseg = tid & 1;

    const bool aval = (bm + lrow) < M;
    const bool bval = (bn + lrow) < N;
    const float* Ap = A + (size_t)(bm + lrow) * K + lseg * 4;
    const float* Bp = B + (size_t)(bn + lrow) * K + lseg * 4;

    float acc[8][8];
#pragma unroll
    for (int i = 0; i < 8; i++)
#pragma unroll
        for (int j = 0; j < 8; j++) acc[i][j] = 0.f;

    // prologue: load first K-slab into stage 0
    float4 av = make_float4(0.f,0.f,0.f,0.f), bv = make_float4(0.f,0.f,0.f,0.f);
    if (aval) av = *reinterpret_cast<const float4*>(Ap);
    if (bval) bv = *reinterpret_cast<const float4*>(Bp);
    As[0][lseg*4+0][lrow] = av.x; As[0][lseg*4+1][lrow] = av.y;
    As[0][lseg*4+2][lrow] = av.z; As[0][lseg*4+3][lrow] = av.w;
    Bs[0][lseg*4+0][lrow] = bv.x; Bs[0][lseg*4+1][lrow] = bv.y;
    Bs[0][lseg*4+2][lrow] = bv.z; Bs[0][lseg*4+3][lrow] = bv.w;
    __syncthreads();

    int buf = 0;
    for (int kt = 0; kt < K; kt += 8) {
        const bool more = (kt + 8) < K;
        if (more) {
            av = make_float4(0.f,0.f,0.f,0.f); bv = av;
            if (aval) av = *reinterpret_cast<const float4*>(Ap + kt + 8);
            if (bval) bv = *reinterpret_cast<const float4*>(Bp + kt + 8);
        }
#pragma unroll
        for (int kk = 0; kk < 8; kk++) {
            float4 a0 = *reinterpret_cast<const float4*>(&As[buf][kk][ty*8]);
            float4 a1 = *reinterpret_cast<const float4*>(&As[buf][kk][ty*8+4]);
            float4 b0 = *reinterpret_cast<const float4*>(&Bs[buf][kk][tx*8]);
            float4 b1 = *reinterpret_cast<const float4*>(&Bs[buf][kk][tx*8+4]);
            float a[8] = {a0.x,a0.y,a0.z,a0.w,a1.x,a1.y,a1.z,a1.w};
            float b[8] = {b0.x,b0.y,b0.z,b0.w,b1.x,b1.y,b1.z,b1.w};
#pragma unroll
            for (int i = 0; i < 8; i++)
#pragma unroll
                for (int j = 0; j < 8; j++) acc[i][j] += a[i]*b[j];
        }
        if (more) {
            int nb = buf ^ 1;
            As[nb][lseg*4+0][lrow] = av.x; As[nb][lseg*4+1][lrow] = av.y;
            As[nb][lseg*4+2][lrow] = av.z; As[nb][lseg*4+3][lrow] = av.w;
            Bs[nb][lseg*4+0][lrow] = bv.x; Bs[nb][lseg*4+1][lrow] = bv.y;
            Bs[nb][lseg*4+2][lrow] = bv.z; Bs[nb][lseg*4+3][lrow] = bv.w;
            __syncthreads();
            buf = nb;
        }
    }
#pragma unroll
    for (int i = 0; i < 8; i++) {
        int row = bm + ty*8 + i;
        if (row >= M) continue;
#pragma unroll
        for (int j = 0; j < 8; j++) {
            int col = bn + tx*8 + j;
            if (col < N) C[(size_t)row * N + col] = acc[i][j];
        }
    }
}

// ------------- prep: RMSNorm(kv_c), RoPE(k_pe).  NOTE: reference does NOT ----
// ------------- rotate q_pe (it rotates a copy and drops it), so q is untouched.
__global__ void __launch_bounds__(256)
prep_kernel(const float* __restrict__ kv,
            const float* __restrict__ kvnw,
            const float* __restrict__ fcos, const float* __restrict__ fsin,
            float* __restrict__ kvc, float* __restrict__ kpe)
{
    const int token = blockIdx.x;
    const int spos  = token & (SEQ - 1);
    const int tid   = threadIdx.x;
    __shared__ float red[256];

    const float* kvrow = kv + (size_t)token * (KV_LORA + ROPE_D);
    float ss = 0.f;
    for (int i = tid; i < KV_LORA; i += 256) { float v = kvrow[i]; ss += v*v; }
    red[tid] = ss;
    __syncthreads();
    for (int st = 128; st > 0; st >>= 1) {
        if (tid < st) red[tid] += red[tid + st];
        __syncthreads();
    }
    const float rms = rsqrtf(red[0] / (float)KV_LORA + 1e-6f);

    for (int i = tid; i < KV_LORA; i += 256)
        kvc[(size_t)token * KV_LORA + i] = kvrow[i] * rms * kvnw[i];

    if (tid < 32) {
        float re = kvrow[KV_LORA + 2*tid], im = kvrow[KV_LORA + 2*tid + 1];
        float c = fcos[spos*32 + tid], s = fsin[spos*32 + tid];
        kpe[(size_t)token * ROPE_D + 2*tid]     = re*c - im*s;
        kpe[(size_t)token * ROPE_D + 2*tid + 1] = re*s + im*c;
    }
}

// ------------------------------- flash attention -----------------------------
#define AT_BM 64
#define AT_BN 64

struct AttnSmem {
    float Qst[QKD][68];    // [k][q_row]   (transposed, pre-scaled)
    float Kst[QKD][68];    // [k][k_row]
    float Vs[AT_BN][132];  // [k_row][v_dim]
    float Ps[AT_BM][68];   // scores / probs, row-major
    float corr_s[AT_BM];   // per-row online-softmax rescale for this tile
    float l_s[AT_BM];      // per-row final denominators
};

__global__ void __launch_bounds__(256, 1)
attn_kernel(const float* __restrict__ q, const float* __restrict__ kvb,
            const float* __restrict__ kpe, float* __restrict__ attn_out,
            float scale)
{
    extern __shared__ char smem_raw[];
    AttnSmem& sm = *reinterpret_cast<AttnSmem*>(smem_raw);
    const int qi = blockIdx.x;  // query tile 0..31
    const int h  = blockIdx.y;  // head
    const int b  = blockIdx.z;  // batch
    const int tid = threadIdx.x;
    const int tx = tid & 15, ty = tid >> 4;  // compute mapping (16x16 grid)
    const int r  = tid >> 2;                 // softmax mapping: query row
    const int vs = tid & 3;                  // softmax col-slice
    const size_t tokq0 = (size_t)b * SEQ + qi * AT_BM;

    // load Q tile transposed, softmax scale folded in (q is UNROTATED,
    // matching the reference which drops its rotated q_pe copy)
    for (int i = tid; i < AT_BM * (QKD/4); i += 256) {
        int row = i / (QKD/4), c4 = i % (QKD/4);
        float4 v = *reinterpret_cast<const float4*>(
            &q[(tokq0 + row) * (size_t)(NH*QKD) + h*QKD + c4*4]);
        sm.Qst[c4*4+0][row] = v.x * scale; sm.Qst[c4*4+1][row] = v.y * scale;
        sm.Qst[c4*4+2][row] = v.z * scale; sm.Qst[c4*4+3][row] = v.w * scale;
    }

    // O accumulator: rows ty*4+i, v-dims tx*8+j  (register-blocked PV)
    float o[4][8];
#pragma unroll
    for (int i = 0; i < 4; i++)
#pragma unroll
        for (int j = 0; j < 8; j++) o[i][j] = 0.f;
    float m_r = -1e30f, l_r = 0.f;   // tracked by softmax mapping (row r)

    for (int j = 0; j <= qi; j++) {
        __syncthreads();  // previous tile's Ps/Vs fully consumed
        const size_t tokk0 = (size_t)b * SEQ + j * AT_BN;
        // K tile (k_nope from kvb, k_pe shared across heads) transposed
        for (int i = tid; i < AT_BN * (QKD/4); i += 256) {
            int row = i / (QKD/4), c4 = i % (QKD/4);
            float4 v;
            if (c4 < NOPE/4)
                v = *reinterpret_cast<const float4*>(
                    &kvb[(tokk0 + row) * (size_t)(NH*(NOPE+VD)) + h*(NOPE+VD) + c4*4]);
            else
                v = *reinterpret_cast<const float4*>(
                    &kpe[(tokk0 + row) * (size_t)ROPE_D + (c4 - NOPE/4)*4]);
            sm.Kst[c4*4+0][row] = v.x; sm.Kst[c4*4+1][row] = v.y;
            sm.Kst[c4*4+2][row] = v.z; sm.Kst[c4*4+3][row] = v.w;
        }
        // V tile
        for (int i = tid; i < AT_BN * (VD/4); i += 256) {
            int row = i / (VD/4), c4 = i % (VD/4);
            float4 v = *reinterpret_cast<const float4*>(
                &kvb[(tokk0 + row) * (size_t)(NH*(NOPE+VD)) + h*(NOPE+VD) + NOPE + c4*4]);
            sm.Vs[row][c4*4+0] = v.x; sm.Vs[row][c4*4+1] = v.y;
            sm.Vs[row][c4*4+2] = v.z; sm.Vs[row][c4*4+3] = v.w;
        }
        __syncthreads();

        // S = Q K^T : 4x4 per thread over 16x16 grid
        float acc[4][4];
#pragma unroll
        for (int i = 0; i < 4; i++)
#pragma unroll
            for (int jj = 0; jj < 4; jj++) acc[i][jj] = 0.f;
#pragma unroll 4
        for (int k = 0; k < QKD; k++) {
            float4 a  = *reinterpret_cast<const float4*>(&sm.Qst[k][ty*4]);
            float4 bb = *reinterpret_cast<const float4*>(&sm.Kst[k][tx*4]);
            float av[4] = {a.x, a.y, a.z, a.w};
            float bv[4] = {bb.x, bb.y, bb.z, bb.w};
#pragma unroll
            for (int i = 0; i < 4; i++)
#pragma unroll
                for (int jj = 0; jj < 4; jj++) acc[i][jj] += av[i]*bv[jj];
        }
        const bool diag = (j == qi);
#pragma unroll
        for (int i = 0; i < 4; i++) {
            int lr = ty*4 + i;
            float t0 = (diag && (tx*4+0) > lr) ? -1e30f : acc[i][0];
            float t1 = (diag && (tx*4+1) > lr) ? -1e30f : acc[i][1];
            float t2 = (diag && (tx*4+2) > lr) ? -1e30f : acc[i][2];
            float t3 = (diag && (tx*4+3) > lr) ? -1e30f : acc[i][3];
            *reinterpret_cast<float4*>(&sm.Ps[lr][tx*4]) = make_float4(t0,t1,t2,t3);
        }
        __syncthreads();

        // online softmax: 4 threads per row, each owns cols [vs*16, vs*16+16)
        {
            float rmax = -1e30f;
#pragma unroll
            for (int t = 0; t < 16; t++) rmax = fmaxf(rmax, sm.Ps[r][vs*16 + t]);
            rmax = fmaxf(rmax, __shfl_xor_sync(0xffffffffu, rmax, 1));
            rmax = fmaxf(rmax, __shfl_xor_sync(0xffffffffu, rmax, 2));
            float m_new = fmaxf(m_r, rmax);
            float corr  = __expf(m_r - m_new);
            float lp = 0.f;
#pragma unroll
            for (int t = 0; t < 16; t++) {
                float svv = sm.Ps[r][vs*16 + t];
                float p = (svv < -1e29f) ? 0.f : __expf(svv - m_new);
                sm.Ps[r][vs*16 + t] = p;   // each lane owns its own 16 cols
                lp += p;
            }
            lp += __shfl_xor_sync(0xffffffffu, lp, 1);
            lp += __shfl_xor_sync(0xffffffffu, lp, 2);
            l_r = l_r * corr + lp;
            m_r = m_new;
            if (vs == 0) sm.corr_s[r] = corr;
        }
        __syncthreads();   // probs + corr_s visible to compute mapping

        // O = corr*O + P V  (register-blocked: 4 rows x 8 v-dims per thread)
        {
            float c0 = sm.corr_s[ty*4+0], c1 = sm.corr_s[ty*4+1];
            float c2 = sm.corr_s[ty*4+2], c3 = sm.corr_s[ty*4+3];
#pragma unroll
            for (int jj = 0; jj < 8; jj++) {
                o[0][jj] *= c0; o[1][jj] *= c1; o[2][jj] *= c2; o[3][jj] *= c3;
            }
#pragma unroll 4
            for (int k = 0; k < AT_BN; k++) {
                float4 v0 = *reinterpret_cast<const float4*>(&sm.Vs[k][tx*8]);
                float4 v1 = *reinterpret_cast<const float4*>(&sm.Vs[k][tx*8+4]);
                float vv[8] = {v0.x,v0.y,v0.z,v0.w,v1.x,v1.y,v1.z,v1.w};
                float p0 = sm.Ps[ty*4+0][k];
                float p1 = sm.Ps[ty*4+1][k];
                float p2 = sm.Ps[ty*4+2][k];
                float p3 = sm.Ps[ty*4+3][k];
#pragma unroll
                for (int jj = 0; jj < 8; jj++) {
                    o[0][jj] += p0 * vv[jj];
                    o[1][jj] += p1 * vv[jj];
                    o[2][jj] += p2 * vv[jj];
                    o[3][jj] += p3 * vv[jj];
                }
            }
        }
    }

    // publish per-row denominators, then write O
    if (vs == 0) sm.l_s[r] = l_r;
    __syncthreads();
#pragma unroll
    for (int i = 0; i < 4; i++) {
        int row = ty*4 + i;
        float inv = 1.f / sm.l_s[row];
        float4 w0 = make_float4(o[i][0]*inv, o[i][1]*inv, o[i][2]*inv, o[i][3]*inv);
        float4 w1 = make_float4(o[i][4]*inv, o[i][5]*inv, o[i][6]*inv, o[i][7]*inv);
        float* dst = &attn_out[(tokq0 + row) * (size_t)(NH*VD) + h*VD + tx*8];
        *reinterpret_cast<float4*>(dst)     = w0;
        *reinterpret_cast<float4*>(dst + 4) = w1;
    }
}

// ---------------------------------- launch -----------------------------------
extern "C" void kernel_launch(void* const* d_in, const int* in_sizes, int n_in,
                              void* d_out, int out_size)
{
    const float* x     = (const float*)d_in[0];
    const float* wq    = (const float*)d_in[1];
    const float* wkv_a = (const float*)d_in[2];
    const float* kvnw  = (const float*)d_in[3];
    const float* wkv_b = (const float*)d_in[4];
    const float* wo    = (const float*)d_in[5];
    const float* fcos  = (const float*)d_in[6];
    const float* fsin  = (const float*)d_in[7];
    float* out = (float*)d_out;

    float *q, *kv, *kvc, *kpe, *kvb, *attn;
    cudaGetSymbolAddress((void**)&q,    g_q);
    cudaGetSymbolAddress((void**)&kv,   g_kv);
    cudaGetSymbolAddress((void**)&kvc,  g_kvc);
    cudaGetSymbolAddress((void**)&kpe,  g_kpe);
    cudaGetSymbolAddress((void**)&kvb,  g_kvb);
    cudaGetSymbolAddress((void**)&attn, g_attn);

    // softmax scale: qk_dim^-0.5 * mscale^2 (yarn, MAX_LEN > ORIG_LEN)
    double mm = 0.1 * 1.0 * log(40.0) + 1.0;
    float scale = (float)(mm * mm / sqrt((double)QKD));

    dim3 blk(256);
    // q = x @ wq^T    [4096, 3072]
    sgemm_nt<<<dim3((NH*QKD + 127)/128, (NTOK + 127)/128), blk>>>(
        x, wq, q, NTOK, NH*QKD, DIM);
    // kv = x @ wkv_a^T  [4096, 576]
    sgemm_nt<<<dim3((KV_LORA + ROPE_D + 127)/128, (NTOK + 127)/128), blk>>>(
        x, wkv_a, kv, NTOK, KV_LORA + ROPE_D, DIM);
    // rmsnorm + k_pe rope (q is NOT rotated — matches reference semantics)
    prep_kernel<<<NTOK, 256>>>(kv, kvnw, fcos, fsin, kvc, kpe);
    // kvb = kvc @ wkv_b^T  [4096, 4096]
    sgemm_nt<<<dim3((NH*(NOPE+VD) + 127)/128, (NTOK + 127)/128), blk>>>(
        kvc, wkv_b, kvb, NTOK, NH*(NOPE+VD), KV_LORA);
    // flash attention (scale folded into Q load)
    cudaFuncSetAttribute(attn_kernel, cudaFuncAttributeMaxDynamicSharedMemorySize,
                         (int)sizeof(AttnSmem));
    attn_kernel<<<dim3(SEQ/AT_BM, NH, BATCH), 256, sizeof(AttnSmem)>>>(
        q, kvb, kpe, attn, scale);
    // out = attn @ wo^T  [4096, 2048]
    sgemm_nt<<<dim3((DIM + 127)/128, (NTOK + 127)/128), blk>>>(
        attn, wo, out, NTOK, DIM, NH*VD);
}

// round 9
// speedup vs baseline: 1.3508x; 1.1606x over previous
#include <cuda_runtime.h>
#include <cuda_bf16.h>
#include <math.h>

#define DIM 2048
#define NH 16
#define KV_LORA 512
#define NOPE 128
#define ROPE_D 64
#define VD 128
#define QKD 192
#define BATCH 2
#define SEQ 2048
#define NTOK (BATCH*SEQ)

// ---------------- scratch (static device arrays; no allocation) --------------
__device__ float g_q[(size_t)NTOK * NH * QKD];            // 4096 x 3072
__device__ float g_kv[(size_t)NTOK * (KV_LORA + ROPE_D)]; // 4096 x 576
__device__ float g_kvc[(size_t)NTOK * KV_LORA];           // 4096 x 512
__device__ float g_kpe[(size_t)NTOK * ROPE_D];            // 4096 x 64
__device__ float g_kvb[(size_t)NTOK * NH * (NOPE + VD)];  // 4096 x 4096
__device__ float g_attn[(size_t)NTOK * NH * VD];          // 4096 x 2048

// ------- generic NT SGEMM, double-buffered: C[M,N] = A[M,K] * B[N,K]^T -------
// B-fragment split into cols {tx*4, 64+tx*4} => conflict-free LDS.128
__global__ void __launch_bounds__(256, 2)
sgemm_nt(const float* __restrict__ A, const float* __restrict__ B,
         float* __restrict__ C, int M, int N, int K)
{
    __shared__ float As[2][8][132];
    __shared__ float Bs[2][8][132];
    const int tid  = threadIdx.x;
    const int tx   = tid & 15, ty = tid >> 4;
    const int bm   = blockIdx.y * 128;
    const int bn   = blockIdx.x * 128;
    const int lrow = tid >> 1;
    const int lseg = tid & 1;

    const bool aval = (bm + lrow) < M;
    const bool bval = (bn + lrow) < N;
    const float* Ap = A + (size_t)(bm + lrow) * K + lseg * 4;
    const float* Bp = B + (size_t)(bn + lrow) * K + lseg * 4;

    float acc[8][8];
#pragma unroll
    for (int i = 0; i < 8; i++)
#pragma unroll
        for (int j = 0; j < 8; j++) acc[i][j] = 0.f;

    // prologue
    float4 av = make_float4(0.f,0.f,0.f,0.f), bv = make_float4(0.f,0.f,0.f,0.f);
    if (aval) av = *reinterpret_cast<const float4*>(Ap);
    if (bval) bv = *reinterpret_cast<const float4*>(Bp);
    As[0][lseg*4+0][lrow] = av.x; As[0][lseg*4+1][lrow] = av.y;
    As[0][lseg*4+2][lrow] = av.z; As[0][lseg*4+3][lrow] = av.w;
    Bs[0][lseg*4+0][lrow] = bv.x; Bs[0][lseg*4+1][lrow] = bv.y;
    Bs[0][lseg*4+2][lrow] = bv.z; Bs[0][lseg*4+3][lrow] = bv.w;
    __syncthreads();

    int buf = 0;
    for (int kt = 0; kt < K; kt += 8) {
        const bool more = (kt + 8) < K;
        if (more) {
            av = make_float4(0.f,0.f,0.f,0.f); bv = av;
            if (aval) av = *reinterpret_cast<const float4*>(Ap + kt + 8);
            if (bval) bv = *reinterpret_cast<const float4*>(Bp + kt + 8);
        }
#pragma unroll
        for (int kk = 0; kk < 8; kk++) {
            float4 a0 = *reinterpret_cast<const float4*>(&As[buf][kk][ty*8]);
            float4 a1 = *reinterpret_cast<const float4*>(&As[buf][kk][ty*8+4]);
            float4 b0 = *reinterpret_cast<const float4*>(&Bs[buf][kk][tx*4]);
            float4 b1 = *reinterpret_cast<const float4*>(&Bs[buf][kk][64+tx*4]);
            float a[8] = {a0.x,a0.y,a0.z,a0.w,a1.x,a1.y,a1.z,a1.w};
            float b[8] = {b0.x,b0.y,b0.z,b0.w,b1.x,b1.y,b1.z,b1.w};
#pragma unroll
            for (int i = 0; i < 8; i++)
#pragma unroll
                for (int j = 0; j < 8; j++) acc[i][j] += a[i]*b[j];
        }
        if (more) {
            int nb = buf ^ 1;
            As[nb][lseg*4+0][lrow] = av.x; As[nb][lseg*4+1][lrow] = av.y;
            As[nb][lseg*4+2][lrow] = av.z; As[nb][lseg*4+3][lrow] = av.w;
            Bs[nb][lseg*4+0][lrow] = bv.x; Bs[nb][lseg*4+1][lrow] = bv.y;
            Bs[nb][lseg*4+2][lrow] = bv.z; Bs[nb][lseg*4+3][lrow] = bv.w;
            __syncthreads();
            buf = nb;
        }
    }
#pragma unroll
    for (int i = 0; i < 8; i++) {
        int row = bm + ty*8 + i;
        if (row >= M) continue;
#pragma unroll
        for (int j = 0; j < 8; j++) {
            int col = bn + ((j < 4) ? (tx*4 + j) : (64 + tx*4 + j - 4));
            if (col < N) C[(size_t)row * N + col] = acc[i][j];
        }
    }
}

// ------------- prep: RMSNorm(kv_c), RoPE(k_pe).  NOTE: reference does NOT ----
// ------------- rotate q_pe (it rotates a copy and drops it), so q is untouched.
__global__ void __launch_bounds__(256)
prep_kernel(const float* __restrict__ kv,
            const float* __restrict__ kvnw,
            const float* __restrict__ fcos, const float* __restrict__ fsin,
            float* __restrict__ kvc, float* __restrict__ kpe)
{
    const int token = blockIdx.x;
    const int spos  = token & (SEQ - 1);
    const int tid   = threadIdx.x;
    __shared__ float red[256];

    const float* kvrow = kv + (size_t)token * (KV_LORA + ROPE_D);
    float ss = 0.f;
    for (int i = tid; i < KV_LORA; i += 256) { float v = kvrow[i]; ss += v*v; }
    red[tid] = ss;
    __syncthreads();
    for (int st = 128; st > 0; st >>= 1) {
        if (tid < st) red[tid] += red[tid + st];
        __syncthreads();
    }
    const float rms = rsqrtf(red[0] / (float)KV_LORA + 1e-6f);

    for (int i = tid; i < KV_LORA; i += 256)
        kvc[(size_t)token * KV_LORA + i] = kvrow[i] * rms * kvnw[i];

    if (tid < 32) {
        float re = kvrow[KV_LORA + 2*tid], im = kvrow[KV_LORA + 2*tid + 1];
        float c = fcos[spos*32 + tid], s = fsin[spos*32 + tid];
        kpe[(size_t)token * ROPE_D + 2*tid]     = re*c - im*s;
        kpe[(size_t)token * ROPE_D + 2*tid + 1] = re*s + im*c;
    }
}

// ------------------------------- flash attention v3 --------------------------
// Slab-staged QK GEMM (tiny smem) -> 59 KB total -> 2 CTAs/SM for latency hiding.
#define AT_BM 64
#define AT_BN 64
#define NSLAB (QKD/8)   // 24

struct AttnSmem {
    float Qs[2][8][68];    // K-slab staging for Q (transposed [k][row])
    float Ks[2][8][68];    // K-slab staging for K
    float Vs[AT_BN][132];  // V tile [k_row][v_dim]
    float Ps[AT_BM][68];   // scores / probs
    float corr_s[AT_BM];
    float l_s[AT_BM];
};

__global__ void __launch_bounds__(256, 2)
attn_kernel(const float* __restrict__ q, const float* __restrict__ kvb,
            const float* __restrict__ kpe, float* __restrict__ attn_out,
            float scale)
{
    extern __shared__ char smem_raw[];
    AttnSmem& sm = *reinterpret_cast<AttnSmem*>(smem_raw);
    const int qi = blockIdx.x;
    const int h  = blockIdx.y;
    const int b  = blockIdx.z;
    const int tid = threadIdx.x;
    const int tx = tid & 15, ty = tid >> 4;   // compute mapping
    const int r  = tid >> 2, vs = tid & 3;    // softmax mapping
    // slab loader mapping: half threads load Q, half load K
    const int lmat = tid >> 7;                // 0 = Q, 1 = K
    const int lrow = (tid & 127) >> 1;        // 0..63
    const int lseg = tid & 1;                 // which float4 of the 8-wide slab
    const size_t tokq0 = (size_t)b * SEQ + qi * AT_BM;
    const float* qbase = q + (tokq0 + lrow) * (size_t)(NH*QKD) + h*QKD + lseg*4;

    float o[4][8];
#pragma unroll
    for (int i = 0; i < 4; i++)
#pragma unroll
        for (int j = 0; j < 8; j++) o[i][j] = 0.f;
    float m_r = -1e30f, l_r = 0.f;

    for (int j = 0; j <= qi; j++) {
        __syncthreads();   // prev iteration's Vs/Ps fully consumed
        const size_t tokk0 = (size_t)b * SEQ + j * AT_BN;

        // V tile loads (become visible at the S-store barrier below)
        for (int i = tid; i < AT_BN * (VD/4); i += 256) {
            int row = i >> 5, c4 = i & 31;
            float4 v = *reinterpret_cast<const float4*>(
                &kvb[(tokk0 + row) * (size_t)(NH*(NOPE+VD)) + h*(NOPE+VD) + NOPE + c4*4]);
            sm.Vs[row][c4*4+0] = v.x; sm.Vs[row][c4*4+1] = v.y;
            sm.Vs[row][c4*4+2] = v.z; sm.Vs[row][c4*4+3] = v.w;
        }

        // ---- inline 64x64x192 GEMM: S = (scale*Q) K^T, 8-deep slabs ----
        float acc[4][4];
#pragma unroll
        for (int i = 0; i < 4; i++)
#pragma unroll
            for (int jj = 0; jj < 4; jj++) acc[i][jj] = 0.f;

        // slab loader lambda-ish (manually inlined): slab s covers k = s*8..s*8+7
        float4 av;
        {   // prologue: slab 0
            if (lmat == 0) {
                av = *reinterpret_cast<const float4*>(qbase);
                av.x *= scale; av.y *= scale; av.z *= scale; av.w *= scale;
            } else {
                int kk0 = lseg*4;   // < NOPE always for slab 0
                av = *reinterpret_cast<const float4*>(
                    &kvb[(tokk0 + lrow) * (size_t)(NH*(NOPE+VD)) + h*(NOPE+VD) + kk0]);
            }
            float (*dst)[68] = lmat ? sm.Ks[0] : sm.Qs[0];
            dst[lseg*4+0][lrow] = av.x; dst[lseg*4+1][lrow] = av.y;
            dst[lseg*4+2][lrow] = av.z; dst[lseg*4+3][lrow] = av.w;
        }
        __syncthreads();

        int buf = 0;
        for (int s = 0; s < NSLAB; s++) {
            const bool more = (s + 1) < NSLAB;
            if (more) {
                int kt = (s + 1) * 8;
                if (lmat == 0) {
                    av = *reinterpret_cast<const float4*>(qbase + kt);
                    av.x *= scale; av.y *= scale; av.z *= scale; av.w *= scale;
                } else {
                    int kk0 = kt + lseg*4;
                    if (kk0 < NOPE)
                        av = *reinterpret_cast<const float4*>(
                            &kvb[(tokk0 + lrow) * (size_t)(NH*(NOPE+VD)) + h*(NOPE+VD) + kk0]);
                    else
                        av = *reinterpret_cast<const float4*>(
                            &kpe[(tokk0 + lrow) * (size_t)ROPE_D + (kk0 - NOPE)]);
                }
            }
#pragma unroll
            for (int kk = 0; kk < 8; kk++) {
                float4 a  = *reinterpret_cast<const float4*>(&sm.Qs[buf][kk][ty*4]);
                float4 bb = *reinterpret_cast<const float4*>(&sm.Ks[buf][kk][tx*4]);
                float aa[4] = {a.x, a.y, a.z, a.w};
                float bv[4] = {bb.x, bb.y, bb.z, bb.w};
#pragma unroll
                for (int i = 0; i < 4; i++)
#pragma unroll
                    for (int jj = 0; jj < 4; jj++) acc[i][jj] += aa[i]*bv[jj];
            }
            if (more) {
                int nb = buf ^ 1;
                float (*dst)[68] = lmat ? sm.Ks[nb] : sm.Qs[nb];
                dst[lseg*4+0][lrow] = av.x; dst[lseg*4+1][lrow] = av.y;
                dst[lseg*4+2][lrow] = av.z; dst[lseg*4+3][lrow] = av.w;
                __syncthreads();
                buf = nb;
            }
        }

        // mask (causal on the diagonal tile) + store S
        const bool diag = (j == qi);
#pragma unroll
        for (int i = 0; i < 4; i++) {
            int lr = ty*4 + i;
            float t0 = (diag && (tx*4+0) > lr) ? -1e30f : acc[i][0];
            float t1 = (diag && (tx*4+1) > lr) ? -1e30f : acc[i][1];
            float t2 = (diag && (tx*4+2) > lr) ? -1e30f : acc[i][2];
            float t3 = (diag && (tx*4+3) > lr) ? -1e30f : acc[i][3];
            *reinterpret_cast<float4*>(&sm.Ps[lr][tx*4]) = make_float4(t0,t1,t2,t3);
        }
        __syncthreads();   // Ps + Vs now visible

        // online softmax: 4 threads per row, each owns cols [vs*16, vs*16+16)
        {
            float rmax = -1e30f;
#pragma unroll
            for (int t = 0; t < 16; t++) rmax = fmaxf(rmax, sm.Ps[r][vs*16 + t]);
            rmax = fmaxf(rmax, __shfl_xor_sync(0xffffffffu, rmax, 1));
            rmax = fmaxf(rmax, __shfl_xor_sync(0xffffffffu, rmax, 2));
            float m_new = fmaxf(m_r, rmax);
            float corr  = __expf(m_r - m_new);
            float lp = 0.f;
#pragma unroll
            for (int t = 0; t < 16; t++) {
                float svv = sm.Ps[r][vs*16 + t];
                float p = (svv < -1e29f) ? 0.f : __expf(svv - m_new);
                sm.Ps[r][vs*16 + t] = p;
                lp += p;
            }
            lp += __shfl_xor_sync(0xffffffffu, lp, 1);
            lp += __shfl_xor_sync(0xffffffffu, lp, 2);
            l_r = l_r * corr + lp;
            m_r = m_new;
            if (vs == 0) sm.corr_s[r] = corr;
        }
        __syncthreads();   // probs + corr visible to compute mapping

        // O = corr*O + P V  (rows ty*4+i; v-cols tx*4 and 64+tx*4, conflict-free)
        {
            float c0 = sm.corr_s[ty*4+0], c1 = sm.corr_s[ty*4+1];
            float c2 = sm.corr_s[ty*4+2], c3 = sm.corr_s[ty*4+3];
#pragma unroll
            for (int jj = 0; jj < 8; jj++) {
                o[0][jj] *= c0; o[1][jj] *= c1; o[2][jj] *= c2; o[3][jj] *= c3;
            }
#pragma unroll 4
            for (int k = 0; k < AT_BN; k++) {
                float4 v0 = *reinterpret_cast<const float4*>(&sm.Vs[k][tx*4]);
                float4 v1 = *reinterpret_cast<const float4*>(&sm.Vs[k][64+tx*4]);
                float vv[8] = {v0.x,v0.y,v0.z,v0.w,v1.x,v1.y,v1.z,v1.w};
                float p0 = sm.Ps[ty*4+0][k];
                float p1 = sm.Ps[ty*4+1][k];
                float p2 = sm.Ps[ty*4+2][k];
                float p3 = sm.Ps[ty*4+3][k];
#pragma unroll
                for (int jj = 0; jj < 8; jj++) {
                    o[0][jj] += p0 * vv[jj];
                    o[1][jj] += p1 * vv[jj];
                    o[2][jj] += p2 * vv[jj];
                    o[3][jj] += p3 * vv[jj];
                }
            }
        }
    }

    if (vs == 0) sm.l_s[r] = l_r;
    __syncthreads();
#pragma unroll
    for (int i = 0; i < 4; i++) {
        int row = ty*4 + i;
        float inv = 1.f / sm.l_s[row];
        float4 w0 = make_float4(o[i][0]*inv, o[i][1]*inv, o[i][2]*inv, o[i][3]*inv);
        float4 w1 = make_float4(o[i][4]*inv, o[i][5]*inv, o[i][6]*inv, o[i][7]*inv);
        float* dst = &attn_out[(tokq0 + row) * (size_t)(NH*VD) + h*VD];
        *reinterpret_cast<float4*>(dst + tx*4)      = w0;
        *reinterpret_cast<float4*>(dst + 64 + tx*4) = w1;
    }
}

// ---------------------------------- launch -----------------------------------
extern "C" void kernel_launch(void* const* d_in, const int* in_sizes, int n_in,
                              void* d_out, int out_size)
{
    const float* x     = (const float*)d_in[0];
    const float* wq    = (const float*)d_in[1];
    const float* wkv_a = (const float*)d_in[2];
    const float* kvnw  = (const float*)d_in[3];
    const float* wkv_b = (const float*)d_in[4];
    const float* wo    = (const float*)d_in[5];
    const float* fcos  = (const float*)d_in[6];
    const float* fsin  = (const float*)d_in[7];
    float* out = (float*)d_out;

    float *q, *kv, *kvc, *kpe, *kvb, *attn;
    cudaGetSymbolAddress((void**)&q,    g_q);
    cudaGetSymbolAddress((void**)&kv,   g_kv);
    cudaGetSymbolAddress((void**)&kvc,  g_kvc);
    cudaGetSymbolAddress((void**)&kpe,  g_kpe);
    cudaGetSymbolAddress((void**)&kvb,  g_kvb);
    cudaGetSymbolAddress((void**)&attn, g_attn);

    // softmax scale: qk_dim^-0.5 * mscale^2 (yarn, MAX_LEN > ORIG_LEN)
    double mm = 0.1 * 1.0 * log(40.0) + 1.0;
    float scale = (float)(mm * mm / sqrt((double)QKD));

    dim3 blk(256);
    sgemm_nt<<<dim3((NH*QKD + 127)/128, (NTOK + 127)/128), blk>>>(
        x, wq, q, NTOK, NH*QKD, DIM);
    sgemm_nt<<<dim3((KV_LORA + ROPE_D + 127)/128, (NTOK + 127)/128), blk>>>(
        x, wkv_a, kv, NTOK, KV_LORA + ROPE_D, DIM);
    prep_kernel<<<NTOK, 256>>>(kv, kvnw, fcos, fsin, kvc, kpe);
    sgemm_nt<<<dim3((NH*(NOPE+VD) + 127)/128, (NTOK + 127)/128), blk>>>(
        kvc, wkv_b, kvb, NTOK, NH*(NOPE+VD), KV_LORA);
    cudaFuncSetAttribute(attn_kernel, cudaFuncAttributeMaxDynamicSharedMemorySize,
                         (int)sizeof(AttnSmem));
    attn_kernel<<<dim3(SEQ/AT_BM, NH, BATCH), 256, sizeof(AttnSmem)>>>(
        q, kvb, kpe, attn, scale);
    sgemm_nt<<<dim3((DIM + 127)/128, (NTOK + 127)/128), blk>>>(
        attn, wo, out, NTOK, DIM, NH*VD);
}

// round 10
// speedup vs baseline: 1.3540x; 1.0024x over previous
#include <cuda_runtime.h>
#include <cuda_bf16.h>
#include <math.h>

#define DIM 2048
#define NH 16
#define KV_LORA 512
#define NOPE 128
#define ROPE_D 64
#define VD 128
#define QKD 192
#define BATCH 2
#define SEQ 2048
#define NTOK (BATCH*SEQ)

// ---------------- scratch (static device arrays; no allocation) --------------
__device__ float g_q[(size_t)NTOK * NH * QKD];            // 4096 x 3072
__device__ float g_kv[(size_t)NTOK * (KV_LORA + ROPE_D)]; // 4096 x 576
__device__ float g_kvc[(size_t)NTOK * KV_LORA];           // 4096 x 512
__device__ float g_kpe[(size_t)NTOK * ROPE_D];            // 4096 x 64
__device__ float g_kvb[(size_t)NTOK * NH * (NOPE + VD)];  // 4096 x 4096
__device__ float g_attn[(size_t)NTOK * NH * VD];          // 4096 x 2048

// ------- generic NT SGEMM, double-buffered: C[M,N] = A[M,K] * B[N,K]^T -------
// B-fragment split into cols {tx*4, 64+tx*4} => conflict-free LDS.128
__global__ void __launch_bounds__(256, 2)
sgemm_nt(const float* __restrict__ A, const float* __restrict__ B,
         float* __restrict__ C, int M, int N, int K)
{
    __shared__ float As[2][8][132];
    __shared__ float Bs[2][8][132];
    const int tid  = threadIdx.x;
    const int tx   = tid & 15, ty = tid >> 4;
    const int bm   = blockIdx.y * 128;
    const int bn   = blockIdx.x * 128;
    const int lrow = tid >> 1;
    const int lseg = tid & 1;

    const bool aval = (bm + lrow) < M;
    const bool bval = (bn + lrow) < N;
    const float* Ap = A + (size_t)(bm + lrow) * K + lseg * 4;
    const float* Bp = B + (size_t)(bn + lrow) * K + lseg * 4;

    float acc[8][8];
#pragma unroll
    for (int i = 0; i < 8; i++)
#pragma unroll
        for (int j = 0; j < 8; j++) acc[i][j] = 0.f;

    // prologue
    float4 av = make_float4(0.f,0.f,0.f,0.f), bv = make_float4(0.f,0.f,0.f,0.f);
    if (aval) av = *reinterpret_cast<const float4*>(Ap);
    if (bval) bv = *reinterpret_cast<const float4*>(Bp);
    As[0][lseg*4+0][lrow] = av.x; As[0][lseg*4+1][lrow] = av.y;
    As[0][lseg*4+2][lrow] = av.z; As[0][lseg*4+3][lrow] = av.w;
    Bs[0][lseg*4+0][lrow] = bv.x; Bs[0][lseg*4+1][lrow] = bv.y;
    Bs[0][lseg*4+2][lrow] = bv.z; Bs[0][lseg*4+3][lrow] = bv.w;
    __syncthreads();

    int buf = 0;
    for (int kt = 0; kt < K; kt += 8) {
        const bool more = (kt + 8) < K;
        if (more) {
            av = make_float4(0.f,0.f,0.f,0.f); bv = av;
            if (aval) av = *reinterpret_cast<const float4*>(Ap + kt + 8);
            if (bval) bv = *reinterpret_cast<const float4*>(Bp + kt + 8);
        }
#pragma unroll
        for (int kk = 0; kk < 8; kk++) {
            float4 a0 = *reinterpret_cast<const float4*>(&As[buf][kk][ty*8]);
            float4 a1 = *reinterpret_cast<const float4*>(&As[buf][kk][ty*8+4]);
            float4 b0 = *reinterpret_cast<const float4*>(&Bs[buf][kk][tx*4]);
            float4 b1 = *reinterpret_cast<const float4*>(&Bs[buf][kk][64+tx*4]);
            float a[8] = {a0.x,a0.y,a0.z,a0.w,a1.x,a1.y,a1.z,a1.w};
            float b[8] = {b0.x,b0.y,b0.z,b0.w,b1.x,b1.y,b1.z,b1.w};
#pragma unroll
            for (int i = 0; i < 8; i++)
#pragma unroll
                for (int j = 0; j < 8; j++) acc[i][j] += a[i]*b[j];
        }
        if (more) {
            int nb = buf ^ 1;
            As[nb][lseg*4+0][lrow] = av.x; As[nb][lseg*4+1][lrow] = av.y;
            As[nb][lseg*4+2][lrow] = av.z; As[nb][lseg*4+3][lrow] = av.w;
            Bs[nb][lseg*4+0][lrow] = bv.x; Bs[nb][lseg*4+1][lrow] = bv.y;
            Bs[nb][lseg*4+2][lrow] = bv.z; Bs[nb][lseg*4+3][lrow] = bv.w;
            __syncthreads();
            buf = nb;
        }
    }
#pragma unroll
    for (int i = 0; i < 8; i++) {
        int row = bm + ty*8 + i;
        if (row >= M) continue;
#pragma unroll
        for (int j = 0; j < 8; j++) {
            int col = bn + ((j < 4) ? (tx*4 + j) : (64 + tx*4 + j - 4));
            if (col < N) C[(size_t)row * N + col] = acc[i][j];
        }
    }
}

// ------------- prep: RMSNorm(kv_c), RoPE(k_pe).  NOTE: reference does NOT ----
// ------------- rotate q_pe (it rotates a copy and drops it), so q is untouched.
__global__ void __launch_bounds__(256)
prep_kernel(const float* __restrict__ kv,
            const float* __restrict__ kvnw,
            const float* __restrict__ fcos, const float* __restrict__ fsin,
            float* __restrict__ kvc, float* __restrict__ kpe)
{
    const int token = blockIdx.x;
    const int spos  = token & (SEQ - 1);
    const int tid   = threadIdx.x;
    __shared__ float red[256];

    const float* kvrow = kv + (size_t)token * (KV_LORA + ROPE_D);
    float ss = 0.f;
    for (int i = tid; i < KV_LORA; i += 256) { float v = kvrow[i]; ss += v*v; }
    red[tid] = ss;
    __syncthreads();
    for (int st = 128; st > 0; st >>= 1) {
        if (tid < st) red[tid] += red[tid + st];
        __syncthreads();
    }
    const float rms = rsqrtf(red[0] / (float)KV_LORA + 1e-6f);

    for (int i = tid; i < KV_LORA; i += 256)
        kvc[(size_t)token * KV_LORA + i] = kvrow[i] * rms * kvnw[i];

    if (tid < 32) {
        float re = kvrow[KV_LORA + 2*tid], im = kvrow[KV_LORA + 2*tid + 1];
        float c = fcos[spos*32 + tid], s = fsin[spos*32 + tid];
        kpe[(size_t)token * ROPE_D + 2*tid]     = re*c - im*s;
        kpe[(size_t)token * ROPE_D + 2*tid + 1] = re*s + im*c;
    }
}

// ------------------------------- flash attention v3 --------------------------
// Slab-staged QK GEMM (tiny smem) -> 59 KB total -> 2 CTAs/SM for latency hiding.
#define AT_BM 64
#define AT_BN 64
#define NSLAB (QKD/8)   // 24

struct AttnSmem {
    float Qs[2][8][68];    // K-slab staging for Q (transposed [k][row])
    float Ks[2][8][68];    // K-slab staging for K
    float Vs[AT_BN][132];  // V tile [k_row][v_dim]
    float Ps[AT_BM][68];   // scores / probs
    float corr_s[AT_BM];
    float l_s[AT_BM];
};

__global__ void __launch_bounds__(256, 2)
attn_kernel(const float* __restrict__ q, const float* __restrict__ kvb,
            const float* __restrict__ kpe, float* __restrict__ attn_out,
            float scale)
{
    extern __shared__ char smem_raw[];
    AttnSmem& sm = *reinterpret_cast<AttnSmem*>(smem_raw);
    const int qi = blockIdx.x;
    const int h  = blockIdx.y;
    const int b  = blockIdx.z;
    const int tid = threadIdx.x;
    const int tx = tid & 15, ty = tid >> 4;   // compute mapping
    const int r  = tid >> 2, vs = tid & 3;    // softmax mapping
    // slab loader mapping: half threads load Q, half load K
    const int lmat = tid >> 7;                // 0 = Q, 1 = K
    const int lrow = (tid & 127) >> 1;        // 0..63
    const int lseg = tid & 1;                 // which float4 of the 8-wide slab
    const size_t tokq0 = (size_t)b * SEQ + qi * AT_BM;
    const float* qbase = q + (tokq0 + lrow) * (size_t)(NH*QKD) + h*QKD + lseg*4;

    float o[4][8];
#pragma unroll
    for (int i = 0; i < 4; i++)
#pragma unroll
        for (int j = 0; j < 8; j++) o[i][j] = 0.f;
    float m_r = -1e30f, l_r = 0.f;

    for (int j = 0; j <= qi; j++) {
        __syncthreads();   // prev iteration's Vs/Ps fully consumed
        const size_t tokk0 = (size_t)b * SEQ + j * AT_BN;

        // V tile loads (become visible at the S-store barrier below)
        for (int i = tid; i < AT_BN * (VD/4); i += 256) {
            int row = i >> 5, c4 = i & 31;
            float4 v = *reinterpret_cast<const float4*>(
                &kvb[(tokk0 + row) * (size_t)(NH*(NOPE+VD)) + h*(NOPE+VD) + NOPE + c4*4]);
            sm.Vs[row][c4*4+0] = v.x; sm.Vs[row][c4*4+1] = v.y;
            sm.Vs[row][c4*4+2] = v.z; sm.Vs[row][c4*4+3] = v.w;
        }

        // ---- inline 64x64x192 GEMM: S = (scale*Q) K^T, 8-deep slabs ----
        float acc[4][4];
#pragma unroll
        for (int i = 0; i < 4; i++)
#pragma unroll
            for (int jj = 0; jj < 4; jj++) acc[i][jj] = 0.f;

        // slab loader lambda-ish (manually inlined): slab s covers k = s*8..s*8+7
        float4 av;
        {   // prologue: slab 0
            if (lmat == 0) {
                av = *reinterpret_cast<const float4*>(qbase);
                av.x *= scale; av.y *= scale; av.z *= scale; av.w *= scale;
            } else {
                int kk0 = lseg*4;   // < NOPE always for slab 0
                av = *reinterpret_cast<const float4*>(
                    &kvb[(tokk0 + lrow) * (size_t)(NH*(NOPE+VD)) + h*(NOPE+VD) + kk0]);
            }
            float (*dst)[68] = lmat ? sm.Ks[0] : sm.Qs[0];
            dst[lseg*4+0][lrow] = av.x; dst[lseg*4+1][lrow] = av.y;
            dst[lseg*4+2][lrow] = av.z; dst[lseg*4+3][lrow] = av.w;
        }
        __syncthreads();

        int buf = 0;
        for (int s = 0; s < NSLAB; s++) {
            const bool more = (s + 1) < NSLAB;
            if (more) {
                int kt = (s + 1) * 8;
                if (lmat == 0) {
                    av = *reinterpret_cast<const float4*>(qbase + kt);
                    av.x *= scale; av.y *= scale; av.z *= scale; av.w *= scale;
                } else {
                    int kk0 = kt + lseg*4;
                    if (kk0 < NOPE)
                        av = *reinterpret_cast<const float4*>(
                            &kvb[(tokk0 + lrow) * (size_t)(NH*(NOPE+VD)) + h*(NOPE+VD) + kk0]);
                    else
                        av = *reinterpret_cast<const float4*>(
                            &kpe[(tokk0 + lrow) * (size_t)ROPE_D + (kk0 - NOPE)]);
                }
            }
#pragma unroll
            for (int kk = 0; kk < 8; kk++) {
                float4 a  = *reinterpret_cast<const float4*>(&sm.Qs[buf][kk][ty*4]);
                float4 bb = *reinterpret_cast<const float4*>(&sm.Ks[buf][kk][tx*4]);
                float aa[4] = {a.x, a.y, a.z, a.w};
                float bv[4] = {bb.x, bb.y, bb.z, bb.w};
#pragma unroll
                for (int i = 0; i < 4; i++)
#pragma unroll
                    for (int jj = 0; jj < 4; jj++) acc[i][jj] += aa[i]*bv[jj];
            }
            if (more) {
                int nb = buf ^ 1;
                float (*dst)[68] = lmat ? sm.Ks[nb] : sm.Qs[nb];
                dst[lseg*4+0][lrow] = av.x; dst[lseg*4+1][lrow] = av.y;
                dst[lseg*4+2][lrow] = av.z; dst[lseg*4+3][lrow] = av.w;
                __syncthreads();
                buf = nb;
            }
        }

        // mask (causal on the diagonal tile) + store S
        const bool diag = (j == qi);
#pragma unroll
        for (int i = 0; i < 4; i++) {
            int lr = ty*4 + i;
            float t0 = (diag && (tx*4+0) > lr) ? -1e30f : acc[i][0];
            float t1 = (diag && (tx*4+1) > lr) ? -1e30f : acc[i][1];
            float t2 = (diag && (tx*4+2) > lr) ? -1e30f : acc[i][2];
            float t3 = (diag && (tx*4+3) > lr) ? -1e30f : acc[i][3];
            *reinterpret_cast<float4*>(&sm.Ps[lr][tx*4]) = make_float4(t0,t1,t2,t3);
        }
        __syncthreads();   // Ps + Vs now visible

        // online softmax: 4 threads per row, each owns cols [vs*16, vs*16+16)
        {
            float rmax = -1e30f;
#pragma unroll
            for (int t = 0; t < 16; t++) rmax = fmaxf(rmax, sm.Ps[r][vs*16 + t]);
            rmax = fmaxf(rmax, __shfl_xor_sync(0xffffffffu, rmax, 1));
            rmax = fmaxf(rmax, __shfl_xor_sync(0xffffffffu, rmax, 2));
            float m_new = fmaxf(m_r, rmax);
            float corr  = __expf(m_r - m_new);
            float lp = 0.f;
#pragma unroll
            for (int t = 0; t < 16; t++) {
                float svv = sm.Ps[r][vs*16 + t];
                float p = (svv < -1e29f) ? 0.f : __expf(svv - m_new);
                sm.Ps[r][vs*16 + t] = p;
                lp += p;
            }
            lp += __shfl_xor_sync(0xffffffffu, lp, 1);
            lp += __shfl_xor_sync(0xffffffffu, lp, 2);
            l_r = l_r * corr + lp;
            m_r = m_new;
            if (vs == 0) sm.corr_s[r] = corr;
        }
        __syncthreads();   // probs + corr visible to compute mapping

        // O = corr*O + P V  (rows ty*4+i; v-cols tx*4 and 64+tx*4, conflict-free)
        {
            float c0 = sm.corr_s[ty*4+0], c1 = sm.corr_s[ty*4+1];
            float c2 = sm.corr_s[ty*4+2], c3 = sm.corr_s[ty*4+3];
#pragma unroll
            for (int jj = 0; jj < 8; jj++) {
                o[0][jj] *= c0; o[1][jj] *= c1; o[2][jj] *= c2; o[3][jj] *= c3;
            }
#pragma unroll 4
            for (int k = 0; k < AT_BN; k++) {
                float4 v0 = *reinterpret_cast<const float4*>(&sm.Vs[k][tx*4]);
                float4 v1 = *reinterpret_cast<const float4*>(&sm.Vs[k][64+tx*4]);
                float vv[8] = {v0.x,v0.y,v0.z,v0.w,v1.x,v1.y,v1.z,v1.w};
                float p0 = sm.Ps[ty*4+0][k];
                float p1 = sm.Ps[ty*4+1][k];
                float p2 = sm.Ps[ty*4+2][k];
                float p3 = sm.Ps[ty*4+3][k];
#pragma unroll
                for (int jj = 0; jj < 8; jj++) {
                    o[0][jj] += p0 * vv[jj];
                    o[1][jj] += p1 * vv[jj];
                    o[2][jj] += p2 * vv[jj];
                    o[3][jj] += p3 * vv[jj];
                }
            }
        }
    }

    if (vs == 0) sm.l_s[r] = l_r;
    __syncthreads();
#pragma unroll
    for (int i = 0; i < 4; i++) {
        int row = ty*4 + i;
        float inv = 1.f / sm.l_s[row];
        float4 w0 = make_float4(o[i][0]*inv, o[i][1]*inv, o[i][2]*inv, o[i][3]*inv);
        float4 w1 = make_float4(o[i][4]*inv, o[i][5]*inv, o[i][6]*inv, o[i][7]*inv);
        float* dst = &attn_out[(tokq0 + row) * (size_t)(NH*VD) + h*VD];
        *reinterpret_cast<float4*>(dst + tx*4)      = w0;
        *reinterpret_cast<float4*>(dst + 64 + tx*4) = w1;
    }
}

// ---------------------------------- launch -----------------------------------
extern "C" void kernel_launch(void* const* d_in, const int* in_sizes, int n_in,
                              void* d_out, int out_size)
{
    const float* x     = (const float*)d_in[0];
    const float* wq    = (const float*)d_in[1];
    const float* wkv_a = (const float*)d_in[2];
    const float* kvnw  = (const float*)d_in[3];
    const float* wkv_b = (const float*)d_in[4];
    const float* wo    = (const float*)d_in[5];
    const float* fcos  = (const float*)d_in[6];
    const float* fsin  = (const float*)d_in[7];
    float* out = (float*)d_out;

    float *q, *kv, *kvc, *kpe, *kvb, *attn;
    cudaGetSymbolAddress((void**)&q,    g_q);
    cudaGetSymbolAddress((void**)&kv,   g_kv);
    cudaGetSymbolAddress((void**)&kvc,  g_kvc);
    cudaGetSymbolAddress((void**)&kpe,  g_kpe);
    cudaGetSymbolAddress((void**)&kvb,  g_kvb);
    cudaGetSymbolAddress((void**)&attn, g_attn);

    // softmax scale: qk_dim^-0.5 * mscale^2 (yarn, MAX_LEN > ORIG_LEN)
    double mm = 0.1 * 1.0 * log(40.0) + 1.0;
    float scale = (float)(mm * mm / sqrt((double)QKD));

    dim3 blk(256);
    sgemm_nt<<<dim3((NH*QKD + 127)/128, (NTOK + 127)/128), blk>>>(
        x, wq, q, NTOK, NH*QKD, DIM);
    sgemm_nt<<<dim3((KV_LORA + ROPE_D + 127)/128, (NTOK + 127)/128), blk>>>(
        x, wkv_a, kv, NTOK, KV_LORA + ROPE_D, DIM);
    prep_kernel<<<NTOK, 256>>>(kv, kvnw, fcos, fsin, kvc, kpe);
    sgemm_nt<<<dim3((NH*(NOPE+VD) + 127)/128, (NTOK + 127)/128), blk>>>(
        kvc, wkv_b, kvb, NTOK, NH*(NOPE+VD), KV_LORA);
    cudaFuncSetAttribute(attn_kernel, cudaFuncAttributeMaxDynamicSharedMemorySize,
                         (int)sizeof(AttnSmem));
    attn_kernel<<<dim3(SEQ/AT_BM, NH, BATCH), 256, sizeof(AttnSmem)>>>(
        q, kvb, kpe, attn, scale);
    sgemm_nt<<<dim3((DIM + 127)/128, (NTOK + 127)/128), blk>>>(
        attn, wo, out, NTOK, DIM, NH*VD);
}

// round 12
// speedup vs baseline: 1.8403x; 1.3591x over previous
#include <cuda_runtime.h>
#include <cuda_bf16.h>
#include <math.h>
#include <stdint.h>

#define DIM 2048
#define NH 16
#define KV_LORA 512
#define NOPE 128
#define ROPE_D 64
#define VD 128
#define QKD 192
#define BATCH 2
#define SEQ 2048
#define NTOK (BATCH*SEQ)

// ---------------- fp32 scratch ------------------------------------------------
__device__ float g_q[(size_t)NTOK * NH * QKD];            // 4096 x 3072
__device__ float g_kv[(size_t)NTOK * (KV_LORA + ROPE_D)]; // 4096 x 576
__device__ float g_kvc[(size_t)NTOK * KV_LORA];           // 4096 x 512
__device__ float g_kpe[(size_t)NTOK * ROPE_D];            // 4096 x 64
__device__ float g_kvb[(size_t)NTOK * NH * (NOPE + VD)];  // 4096 x 4096
__device__ float g_attn[(size_t)NTOK * NH * VD];          // 4096 x 2048

// ---------------- bf16 hi/lo scratch ------------------------------------------
__device__ __nv_bfloat16 g_xh[(size_t)NTOK * DIM],              g_xl[(size_t)NTOK * DIM];
__device__ __nv_bfloat16 g_wqh[(size_t)NH*QKD * DIM],           g_wql[(size_t)NH*QKD * DIM];
__device__ __nv_bfloat16 g_wah[(size_t)(KV_LORA+ROPE_D) * DIM], g_wal[(size_t)(KV_LORA+ROPE_D) * DIM];
__device__ __nv_bfloat16 g_wbh[(size_t)NH*(NOPE+VD) * KV_LORA], g_wbl[(size_t)NH*(NOPE+VD) * KV_LORA];
__device__ __nv_bfloat16 g_woh[(size_t)DIM * NH*VD],            g_wol[(size_t)DIM * NH*VD];
__device__ __nv_bfloat16 g_kvch[(size_t)NTOK * KV_LORA],        g_kvcl[(size_t)NTOK * KV_LORA];
__device__ __nv_bfloat16 g_ath[(size_t)NTOK * NH*VD],           g_atl[(size_t)NTOK * NH*VD];

// ======================= PTX helpers (baseline sm_103, no 'a' features) =======
__device__ __forceinline__ uint32_t smem_u32(const void* p) {
    uint32_t a;
    asm("{ .reg .u64 t; cvta.to.shared.u64 t, %1; cvt.u32.u64 %0, t; }"
        : "=r"(a) : "l"(p));
    return a;
}
#define CP16(s, g, sz) \
    asm volatile("cp.async.cg.shared.global [%0], [%1], 16, %2;" \
                 :: "r"(s), "l"(g), "r"(sz) : "memory")
#define CP_COMMIT() asm volatile("cp.async.commit_group;" ::: "memory")
#define CP_WAIT1()  asm volatile("cp.async.wait_group 1;" ::: "memory")
#define CP_WAIT0()  asm volatile("cp.async.wait_group 0;" ::: "memory")

#define LDSM_X4(r, a) \
    asm volatile("ldmatrix.sync.aligned.m8n8.x4.shared.b16 {%0,%1,%2,%3}, [%4];" \
                 : "=r"((r)[0]), "=r"((r)[1]), "=r"((r)[2]), "=r"((r)[3]) : "r"(a))
#define LDSM_X2(r, a) \
    asm volatile("ldmatrix.sync.aligned.m8n8.x2.shared.b16 {%0,%1}, [%2];" \
                 : "=r"((r)[0]), "=r"((r)[1]) : "r"(a))
#define MMA16816(d, a, b) \
    asm volatile("mma.sync.aligned.m16n8k16.row.col.f32.bf16.bf16.f32 " \
                 "{%0,%1,%2,%3}, {%4,%5,%6,%7}, {%8,%9}, {%0,%1,%2,%3};" \
                 : "+f"((d)[0]), "+f"((d)[1]), "+f"((d)[2]), "+f"((d)[3]) \
                 : "r"((a)[0]), "r"((a)[1]), "r"((a)[2]), "r"((a)[3]), \
                   "r"((b)[0]), "r"((b)[1]))

// ---------------- fp32 -> (hi, lo) bf16 split ---------------------------------
__global__ void __launch_bounds__(256)
cvt_hilo(const float* __restrict__ s, __nv_bfloat16* __restrict__ h,
         __nv_bfloat16* __restrict__ l, int n4)
{
    int i = blockIdx.x * 256 + threadIdx.x;
    if (i >= n4) return;
    float4 v = reinterpret_cast<const float4*>(s)[i];
    __nv_bfloat16 h0 = __float2bfloat16(v.x), h1 = __float2bfloat16(v.y);
    __nv_bfloat16 h2 = __float2bfloat16(v.z), h3 = __float2bfloat16(v.w);
    __nv_bfloat16 l0 = __float2bfloat16(v.x - __bfloat162float(h0));
    __nv_bfloat16 l1 = __float2bfloat16(v.y - __bfloat162float(h1));
    __nv_bfloat16 l2 = __float2bfloat16(v.z - __bfloat162float(h2));
    __nv_bfloat16 l3 = __float2bfloat16(v.w - __bfloat162float(h3));
    reinterpret_cast<__nv_bfloat162*>(h)[2*i]   = __halves2bfloat162(h0, h1);
    reinterpret_cast<__nv_bfloat162*>(h)[2*i+1] = __halves2bfloat162(h2, h3);
    reinterpret_cast<__nv_bfloat162*>(l)[2*i]   = __halves2bfloat162(l0, l1);
    reinterpret_cast<__nv_bfloat162*>(l)[2*i+1] = __halves2bfloat162(l2, l3);
}

// ============ warp-MMA NT GEMM: C = A*B^T, split bf16 (3 HMMA terms) ==========
// CTA 128x128, 8 warps (2x4), warp tile 64x32. K-slab 32, cp.async double-buffer.
// Smem tile layout: contiguous 8x8 b16 blocks; block(br,kb) at (br*4+kb)*128,
// row r within block at +r*16. One gmem uint4 (8 bf16) == one ldmatrix row.
#define OFF_AH 0
#define OFF_AL 8192
#define OFF_BH 16384
#define OFF_BL 24576
#define STAGE_SZ 32768
#define GSMEM (2*STAGE_SZ)

__global__ void __launch_bounds__(256, 2)
gemm_mma(const __nv_bfloat16* __restrict__ Ah, const __nv_bfloat16* __restrict__ Al,
         const __nv_bfloat16* __restrict__ Bh, const __nv_bfloat16* __restrict__ Bl,
         float* __restrict__ C, int M, int N, int K)
{
    extern __shared__ char smraw[];
    const uint32_t sbase = smem_u32(smraw);
    const int tid  = threadIdx.x;
    const int lane = tid & 31, wid = tid >> 5;
    const int bm = blockIdx.y * 128, bn = blockIdx.x * 128;
    const int wm = (wid >> 2) * 64, wn = (wid & 3) * 32;

    float acc[4][4][4];
#pragma unroll
    for (int mt = 0; mt < 4; mt++)
#pragma unroll
        for (int nt = 0; nt < 4; nt++)
#pragma unroll
            for (int e = 0; e < 4; e++) acc[mt][nt][e] = 0.f;

    // per-thread gmem->smem mapping: idx = tid + i*256; row = idx>>2, kb = idx&3
    const int NS = K >> 5;

    // ldmatrix per-lane offsets (within a matrix, block layout)
    //   A: row = wm + mt*16 + (lane&15), kb = k16*2 + (lane>>4)
    //   B: row = wn + nt*8  + (lane&7),  kb = k16*2 + ((lane>>3)&1)
    const int arow = lane & 15, akbo = lane >> 4;
    const int brow = lane & 7,  bkbo = (lane >> 3) & 1;

#define ISSUE_SLAB(st, kt) do {                                               \
    uint32_t _sb = sbase + (uint32_t)(st) * STAGE_SZ;                         \
    _Pragma("unroll")                                                         \
    for (int _i = 0; _i < 2; _i++) {                                          \
        int _idx = tid + _i * 256;                                            \
        int _row = _idx >> 2, _kb = _idx & 3;                                 \
        uint32_t _so = (uint32_t)((((_row >> 3) * 4 + _kb) * 128) + (_row & 7) * 16); \
        size_t _ga = (size_t)(bm + _row) * K + (kt) + _kb * 8;                \
        CP16(_sb + OFF_AH + _so, Ah + _ga, 16);                               \
        CP16(_sb + OFF_AL + _so, Al + _ga, 16);                               \
        int _nr = bn + _row;                                                  \
        int _ok = (_nr < N) ? 16 : 0;                                         \
        if (_nr >= N) _nr = 0;                                                \
        size_t _gb = (size_t)_nr * K + (kt) + _kb * 8;                        \
        CP16(_sb + OFF_BH + _so, Bh + _gb, _ok);                              \
        CP16(_sb + OFF_BL + _so, Bl + _gb, _ok);                              \
    } } while (0)

    ISSUE_SLAB(0, 0);
    CP_COMMIT();

    for (int s = 0; s < NS; s++) {
        const int cur = s & 1;
        if (s + 1 < NS) {
            ISSUE_SLAB((s + 1) & 1, (s + 1) * 32);
            CP_COMMIT();
            CP_WAIT1();
        } else {
            CP_WAIT0();
        }
        __syncthreads();

        const uint32_t sb = sbase + (uint32_t)cur * STAGE_SZ;
#pragma unroll
        for (int k16 = 0; k16 < 2; k16++) {
            uint32_t bh[4][2], bl[4][2];
#pragma unroll
            for (int nt = 0; nt < 4; nt++) {
                int n  = wn + nt * 8 + brow;
                int kb = k16 * 2 + bkbo;
                uint32_t off = (uint32_t)((((n >> 3) * 4 + kb) * 128) + (n & 7) * 16);
                LDSM_X2(bh[nt], sb + OFF_BH + off);
                LDSM_X2(bl[nt], sb + OFF_BL + off);
            }
#pragma unroll
            for (int mt = 0; mt < 4; mt++) {
                int r  = wm + mt * 16 + arow;
                int kb = k16 * 2 + akbo;
                uint32_t off = (uint32_t)((((r >> 3) * 4 + kb) * 128) + (r & 7) * 16);
                uint32_t ah[4], al[4];
                LDSM_X4(ah, sb + OFF_AH + off);
                LDSM_X4(al, sb + OFF_AL + off);
#pragma unroll
                for (int nt = 0; nt < 4; nt++) {
                    MMA16816(acc[mt][nt], ah, bh[nt]);
                    MMA16816(acc[mt][nt], ah, bl[nt]);
                    MMA16816(acc[mt][nt], al, bh[nt]);
                }
            }
        }
        __syncthreads();
    }

    // epilogue: d0,d1 -> (row, col..col+1); d2,d3 -> (row+8, ...)
    const int erow = lane >> 2, ecol = (lane & 3) * 2;
#pragma unroll
    for (int mt = 0; mt < 4; mt++) {
#pragma unroll
        for (int nt = 0; nt < 4; nt++) {
            int col = bn + wn + nt * 8 + ecol;
            if (col < N) {
                int r0 = bm + wm + mt * 16 + erow;
                *reinterpret_cast<float2*>(C + (size_t)r0 * N + col) =
                    make_float2(acc[mt][nt][0], acc[mt][nt][1]);
                *reinterpret_cast<float2*>(C + (size_t)(r0 + 8) * N + col) =
                    make_float2(acc[mt][nt][2], acc[mt][nt][3]);
            }
        }
    }
}

// ------------- prep: RMSNorm(kv_c), RoPE(k_pe).  NOTE: reference does NOT ----
// ------------- rotate q_pe (it rotates a copy and drops it), so q is untouched.
__global__ void __launch_bounds__(256)
prep_kernel(const float* __restrict__ kv,
            const float* __restrict__ kvnw,
            const float* __restrict__ fcos, const float* __restrict__ fsin,
            float* __restrict__ kvc, float* __restrict__ kpe)
{
    const int token = blockIdx.x;
    const int spos  = token & (SEQ - 1);
    const int tid   = threadIdx.x;
    __shared__ float red[256];

    const float* kvrow = kv + (size_t)token * (KV_LORA + ROPE_D);
    float ss = 0.f;
    for (int i = tid; i < KV_LORA; i += 256) { float v = kvrow[i]; ss += v*v; }
    red[tid] = ss;
    __syncthreads();
    for (int st = 128; st > 0; st >>= 1) {
        if (tid < st) red[tid] += red[tid + st];
        __syncthreads();
    }
    const float rms = rsqrtf(red[0] / (float)KV_LORA + 1e-6f);

    for (int i = tid; i < KV_LORA; i += 256)
        kvc[(size_t)token * KV_LORA + i] = kvrow[i] * rms * kvnw[i];

    if (tid < 32) {
        float re = kvrow[KV_LORA + 2*tid], im = kvrow[KV_LORA + 2*tid + 1];
        float c = fcos[spos*32 + tid], s = fsin[spos*32 + tid];
        kpe[(size_t)token * ROPE_D + 2*tid]     = re*c - im*s;
        kpe[(size_t)token * ROPE_D + 2*tid + 1] = re*s + im*c;
    }
}

// ------------------------------- flash attention -----------------------------
#define AT_BM 64
#define AT_BN 64
#define NSLAB (QKD/8)   // 24

struct AttnSmem {
    float Qs[2][8][68];
    float Ks[2][8][68];
    float Vs[AT_BN][132];
    float Ps[AT_BM][68];
    float corr_s[AT_BM];
    float l_s[AT_BM];
};

__global__ void __launch_bounds__(256, 2)
attn_kernel(const float* __restrict__ q, const float* __restrict__ kvb,
            const float* __restrict__ kpe, float* __restrict__ attn_out,
            float scale)
{
    extern __shared__ char smem_raw[];
    AttnSmem& sm = *reinterpret_cast<AttnSmem*>(smem_raw);
    const int qi = blockIdx.x;
    const int h  = blockIdx.y;
    const int b  = blockIdx.z;
    const int tid = threadIdx.x;
    const int tx = tid & 15, ty = tid >> 4;
    const int r  = tid >> 2, vs = tid & 3;
    const int lmat = tid >> 7;
    const int lrow = (tid & 127) >> 1;
    const int lseg = tid & 1;
    const size_t tokq0 = (size_t)b * SEQ + qi * AT_BM;
    const float* qbase = q + (tokq0 + lrow) * (size_t)(NH*QKD) + h*QKD + lseg*4;

    float o[4][8];
#pragma unroll
    for (int i = 0; i < 4; i++)
#pragma unroll
        for (int j = 0; j < 8; j++) o[i][j] = 0.f;
    float m_r = -1e30f, l_r = 0.f;

    for (int j = 0; j <= qi; j++) {
        __syncthreads();
        const size_t tokk0 = (size_t)b * SEQ + j * AT_BN;

        for (int i = tid; i < AT_BN * (VD/4); i += 256) {
            int row = i >> 5, c4 = i & 31;
            float4 v = *reinterpret_cast<const float4*>(
                &kvb[(tokk0 + row) * (size_t)(NH*(NOPE+VD)) + h*(NOPE+VD) + NOPE + c4*4]);
            sm.Vs[row][c4*4+0] = v.x; sm.Vs[row][c4*4+1] = v.y;
            sm.Vs[row][c4*4+2] = v.z; sm.Vs[row][c4*4+3] = v.w;
        }

        float acc[4][4];
#pragma unroll
        for (int i = 0; i < 4; i++)
#pragma unroll
            for (int jj = 0; jj < 4; jj++) acc[i][jj] = 0.f;

        float4 av;
        {
            if (lmat == 0) {
                av = *reinterpret_cast<const float4*>(qbase);
                av.x *= scale; av.y *= scale; av.z *= scale; av.w *= scale;
            } else {
                int kk0 = lseg*4;
                av = *reinterpret_cast<const float4*>(
                    &kvb[(tokk0 + lrow) * (size_t)(NH*(NOPE+VD)) + h*(NOPE+VD) + kk0]);
            }
            float (*dst)[68] = lmat ? sm.Ks[0] : sm.Qs[0];
            dst[lseg*4+0][lrow] = av.x; dst[lseg*4+1][lrow] = av.y;
            dst[lseg*4+2][lrow] = av.z; dst[lseg*4+3][lrow] = av.w;
        }
        __syncthreads();

        int buf = 0;
        for (int s = 0; s < NSLAB; s++) {
            const bool more = (s + 1) < NSLAB;
            if (more) {
                int kt = (s + 1) * 8;
                if (lmat == 0) {
                    av = *reinterpret_cast<const float4*>(qbase + kt);
                    av.x *= scale; av.y *= scale; av.z *= scale; av.w *= scale;
                } else {
                    int kk0 = kt + lseg*4;
                    if (kk0 < NOPE)
                        av = *reinterpret_cast<const float4*>(
                            &kvb[(tokk0 + lrow) * (size_t)(NH*(NOPE+VD)) + h*(NOPE+VD) + kk0]);
                    else
                        av = *reinterpret_cast<const float4*>(
                            &kpe[(tokk0 + lrow) * (size_t)ROPE_D + (kk0 - NOPE)]);
                }
            }
#pragma unroll
            for (int kk = 0; kk < 8; kk++) {
                float4 a  = *reinterpret_cast<const float4*>(&sm.Qs[buf][kk][ty*4]);
                float4 bb = *reinterpret_cast<const float4*>(&sm.Ks[buf][kk][tx*4]);
                float aa[4] = {a.x, a.y, a.z, a.w};
                float bv[4] = {bb.x, bb.y, bb.z, bb.w};
#pragma unroll
                for (int i = 0; i < 4; i++)
#pragma unroll
                    for (int jj = 0; jj < 4; jj++) acc[i][jj] += aa[i]*bv[jj];
            }
            if (more) {
                int nb = buf ^ 1;
                float (*dst)[68] = lmat ? sm.Ks[nb] : sm.Qs[nb];
                dst[lseg*4+0][lrow] = av.x; dst[lseg*4+1][lrow] = av.y;
                dst[lseg*4+2][lrow] = av.z; dst[lseg*4+3][lrow] = av.w;
                __syncthreads();
                buf = nb;
            }
        }

        const bool diag = (j == qi);
#pragma unroll
        for (int i = 0; i < 4; i++) {
            int lr = ty*4 + i;
            float t0 = (diag && (tx*4+0) > lr) ? -1e30f : acc[i][0];
            float t1 = (diag && (tx*4+1) > lr) ? -1e30f : acc[i][1];
            float t2 = (diag && (tx*4+2) > lr) ? -1e30f : acc[i][2];
            float t3 = (diag && (tx*4+3) > lr) ? -1e30f : acc[i][3];
            *reinterpret_cast<float4*>(&sm.Ps[lr][tx*4]) = make_float4(t0,t1,t2,t3);
        }
        __syncthreads();

        {
            float rmax = -1e30f;
#pragma unroll
            for (int t = 0; t < 16; t++) rmax = fmaxf(rmax, sm.Ps[r][vs*16 + t]);
            rmax = fmaxf(rmax, __shfl_xor_sync(0xffffffffu, rmax, 1));
            rmax = fmaxf(rmax, __shfl_xor_sync(0xffffffffu, rmax, 2));
            float m_new = fmaxf(m_r, rmax);
            float corr  = __expf(m_r - m_new);
            float lp = 0.f;
#pragma unroll
            for (int t = 0; t < 16; t++) {
                float svv = sm.Ps[r][vs*16 + t];
                float p = (svv < -1e29f) ? 0.f : __expf(svv - m_new);
                sm.Ps[r][vs*16 + t] = p;
                lp += p;
            }
            lp += __shfl_xor_sync(0xffffffffu, lp, 1);
            lp += __shfl_xor_sync(0xffffffffu, lp, 2);
            l_r = l_r * corr + lp;
            m_r = m_new;
            if (vs == 0) sm.corr_s[r] = corr;
        }
        __syncthreads();

        {
            float c0 = sm.corr_s[ty*4+0], c1 = sm.corr_s[ty*4+1];
            float c2 = sm.corr_s[ty*4+2], c3 = sm.corr_s[ty*4+3];
#pragma unroll
            for (int jj = 0; jj < 8; jj++) {
                o[0][jj] *= c0; o[1][jj] *= c1; o[2][jj] *= c2; o[3][jj] *= c3;
            }
#pragma unroll 4
            for (int k = 0; k < AT_BN; k++) {
                float4 v0 = *reinterpret_cast<const float4*>(&sm.Vs[k][tx*4]);
                float4 v1 = *reinterpret_cast<const float4*>(&sm.Vs[k][64+tx*4]);
                float vv[8] = {v0.x,v0.y,v0.z,v0.w,v1.x,v1.y,v1.z,v1.w};
                float p0 = sm.Ps[ty*4+0][k];
                float p1 = sm.Ps[ty*4+1][k];
                float p2 = sm.Ps[ty*4+2][k];
                float p3 = sm.Ps[ty*4+3][k];
#pragma unroll
                for (int jj = 0; jj < 8; jj++) {
                    o[0][jj] += p0 * vv[jj];
                    o[1][jj] += p1 * vv[jj];
                    o[2][jj] += p2 * vv[jj];
                    o[3][jj] += p3 * vv[jj];
                }
            }
        }
    }

    if (vs == 0) sm.l_s[r] = l_r;
    __syncthreads();
#pragma unroll
    for (int i = 0; i < 4; i++) {
        int row = ty*4 + i;
        float inv = 1.f / sm.l_s[row];
        float4 w0 = make_float4(o[i][0]*inv, o[i][1]*inv, o[i][2]*inv, o[i][3]*inv);
        float4 w1 = make_float4(o[i][4]*inv, o[i][5]*inv, o[i][6]*inv, o[i][7]*inv);
        float* dst = &attn_out[(tokq0 + row) * (size_t)(NH*VD) + h*VD];
        *reinterpret_cast<float4*>(dst + tx*4)      = w0;
        *reinterpret_cast<float4*>(dst + 64 + tx*4) = w1;
    }
}

// ---------------------------------- launch -----------------------------------
static inline void cvt(const float* s, __nv_bfloat16* h, __nv_bfloat16* l, size_t n) {
    int n4 = (int)(n / 4);
    cvt_hilo<<<(n4 + 255) / 256, 256>>>(s, h, l, n4);
}

extern "C" void kernel_launch(void* const* d_in, const int* in_sizes, int n_in,
                              void* d_out, int out_size)
{
    const float* x     = (const float*)d_in[0];
    const float* wq    = (const float*)d_in[1];
    const float* wkv_a = (const float*)d_in[2];
    const float* kvnw  = (const float*)d_in[3];
    const float* wkv_b = (const float*)d_in[4];
    const float* wo    = (const float*)d_in[5];
    const float* fcos  = (const float*)d_in[6];
    const float* fsin  = (const float*)d_in[7];
    float* out = (float*)d_out;

    float *q, *kv, *kvc, *kpe, *kvb, *attn;
    cudaGetSymbolAddress((void**)&q,    g_q);
    cudaGetSymbolAddress((void**)&kv,   g_kv);
    cudaGetSymbolAddress((void**)&kvc,  g_kvc);
    cudaGetSymbolAddress((void**)&kpe,  g_kpe);
    cudaGetSymbolAddress((void**)&kvb,  g_kvb);
    cudaGetSymbolAddress((void**)&attn, g_attn);

    __nv_bfloat16 *xh,*xl,*wqh,*wql,*wah,*wal,*wbh,*wbl,*woh,*wol,*kvch,*kvcl,*ath,*atl;
    cudaGetSymbolAddress((void**)&xh,  g_xh);   cudaGetSymbolAddress((void**)&xl,  g_xl);
    cudaGetSymbolAddress((void**)&wqh, g_wqh);  cudaGetSymbolAddress((void**)&wql, g_wql);
    cudaGetSymbolAddress((void**)&wah, g_wah);  cudaGetSymbolAddress((void**)&wal, g_wal);
    cudaGetSymbolAddress((void**)&wbh, g_wbh);  cudaGetSymbolAddress((void**)&wbl, g_wbl);
    cudaGetSymbolAddress((void**)&woh, g_woh);  cudaGetSymbolAddress((void**)&wol, g_wol);
    cudaGetSymbolAddress((void**)&kvch,g_kvch); cudaGetSymbolAddress((void**)&kvcl,g_kvcl);
    cudaGetSymbolAddress((void**)&ath, g_ath);  cudaGetSymbolAddress((void**)&atl, g_atl);

    double mm = 0.1 * 1.0 * log(40.0) + 1.0;
    float scale = (float)(mm * mm / sqrt((double)QKD));

    cudaFuncSetAttribute(gemm_mma, cudaFuncAttributeMaxDynamicSharedMemorySize, GSMEM);
    cudaFuncSetAttribute(attn_kernel, cudaFuncAttributeMaxDynamicSharedMemorySize,
                         (int)sizeof(AttnSmem));

    // split inputs / weights to bf16 hi/lo
    cvt(x,     xh,  xl,  (size_t)NTOK * DIM);
    cvt(wq,    wqh, wql, (size_t)NH*QKD * DIM);
    cvt(wkv_a, wah, wal, (size_t)(KV_LORA+ROPE_D) * DIM);
    cvt(wkv_b, wbh, wbl, (size_t)NH*(NOPE+VD) * KV_LORA);
    cvt(wo,    woh, wol, (size_t)DIM * NH*VD);

    // q = x @ wq^T        [4096, 3072]
    gemm_mma<<<dim3(3072/128, 32), 256, GSMEM>>>(xh, xl, wqh, wql, q, NTOK, NH*QKD, DIM);
    // kv = x @ wkv_a^T    [4096, 576]
    gemm_mma<<<dim3(5, 32), 256, GSMEM>>>(xh, xl, wah, wal, kv, NTOK, KV_LORA+ROPE_D, DIM);
    // rmsnorm + k_pe rope (q NOT rotated — matches reference semantics)
    prep_kernel<<<NTOK, 256>>>(kv, kvnw, fcos, fsin, kvc, kpe);
    cvt(kvc, kvch, kvcl, (size_t)NTOK * KV_LORA);
    // kvb = kvc @ wkv_b^T [4096, 4096]
    gemm_mma<<<dim3(4096/128, 32), 256, GSMEM>>>(kvch, kvcl, wbh, wbl, kvb, NTOK, NH*(NOPE+VD), KV_LORA);
    // flash attention
    attn_kernel<<<dim3(SEQ/AT_BM, NH, BATCH), 256, sizeof(AttnSmem)>>>(
        q, kvb, kpe, attn, scale);
    cvt(attn, ath, atl, (size_t)NTOK * NH*VD);
    // out = attn @ wo^T   [4096, 2048]
    gemm_mma<<<dim3(2048/128, 32), 256, GSMEM>>>(ath, atl, woh, wol, out, NTOK, DIM, NH*VD);
}

// round 13
// speedup vs baseline: 2.6989x; 1.4666x over previous
#include <cuda_runtime.h>
#include <cuda_bf16.h>
#include <math.h>
#include <stdint.h>

#define DIM 2048
#define NH 16
#define KV_LORA 512
#define NOPE 128
#define ROPE_D 64
#define VD 128
#define QKD 192
#define BATCH 2
#define SEQ 2048
#define NTOK (BATCH*SEQ)

// ---------------- fp32 scratch ------------------------------------------------
__device__ float g_q[(size_t)NTOK * NH * QKD];
__device__ float g_kv[(size_t)NTOK * (KV_LORA + ROPE_D)];
__device__ float g_kvc[(size_t)NTOK * KV_LORA];
__device__ float g_kpe[(size_t)NTOK * ROPE_D];
__device__ float g_kvb[(size_t)NTOK * NH * (NOPE + VD)];
__device__ float g_attn[(size_t)NTOK * NH * VD];

// ---------------- bf16 hi/lo scratch (GEMM) ------------------------------------
__device__ __nv_bfloat16 g_xh[(size_t)NTOK * DIM],              g_xl[(size_t)NTOK * DIM];
__device__ __nv_bfloat16 g_wqh[(size_t)NH*QKD * DIM],           g_wql[(size_t)NH*QKD * DIM];
__device__ __nv_bfloat16 g_wah[(size_t)(KV_LORA+ROPE_D) * DIM], g_wal[(size_t)(KV_LORA+ROPE_D) * DIM];
__device__ __nv_bfloat16 g_wbh[(size_t)NH*(NOPE+VD) * KV_LORA], g_wbl[(size_t)NH*(NOPE+VD) * KV_LORA];
__device__ __nv_bfloat16 g_woh[(size_t)DIM * NH*VD],            g_wol[(size_t)DIM * NH*VD];
__device__ __nv_bfloat16 g_kvch[(size_t)NTOK * KV_LORA],        g_kvcl[(size_t)NTOK * KV_LORA];
__device__ __nv_bfloat16 g_ath[(size_t)NTOK * NH*VD],           g_atl[(size_t)NTOK * NH*VD];

// ---------------- bf16 hi/lo attention layouts [b][h][s][d] --------------------
__device__ __nv_bfloat16 g_aqh[(size_t)NTOK * NH * QKD], g_aql[(size_t)NTOK * NH * QKD];
__device__ __nv_bfloat16 g_akh[(size_t)NTOK * NH * QKD], g_akl[(size_t)NTOK * NH * QKD];
__device__ __nv_bfloat16 g_avh[(size_t)NTOK * NH * VD],  g_avl[(size_t)NTOK * NH * VD];

// ======================= PTX helpers (baseline sm_103) =========================
__device__ __forceinline__ uint32_t smem_u32(const void* p) {
    uint32_t a;
    asm("{ .reg .u64 t; cvta.to.shared.u64 t, %1; cvt.u32.u64 %0, t; }"
        : "=r"(a) : "l"(p));
    return a;
}
#define CP16(s, g, sz) \
    asm volatile("cp.async.cg.shared.global [%0], [%1], 16, %2;" \
                 :: "r"(s), "l"(g), "r"(sz) : "memory")
#define CP_COMMIT() asm volatile("cp.async.commit_group;" ::: "memory")
#define CP_WAIT1()  asm volatile("cp.async.wait_group 1;" ::: "memory")
#define CP_WAIT0()  asm volatile("cp.async.wait_group 0;" ::: "memory")

#define LDSM_X4(r, a) \
    asm volatile("ldmatrix.sync.aligned.m8n8.x4.shared.b16 {%0,%1,%2,%3}, [%4];" \
                 : "=r"((r)[0]), "=r"((r)[1]), "=r"((r)[2]), "=r"((r)[3]) : "r"(a))
#define LDSM_X2(r, a) \
    asm volatile("ldmatrix.sync.aligned.m8n8.x2.shared.b16 {%0,%1}, [%2];" \
                 : "=r"((r)[0]), "=r"((r)[1]) : "r"(a))
#define LDSM_X2T(r, a) \
    asm volatile("ldmatrix.sync.aligned.m8n8.x2.trans.shared.b16 {%0,%1}, [%2];" \
                 : "=r"((r)[0]), "=r"((r)[1]) : "r"(a))
#define MMA16816(d, a, b) \
    asm volatile("mma.sync.aligned.m16n8k16.row.col.f32.bf16.bf16.f32 " \
                 "{%0,%1,%2,%3}, {%4,%5,%6,%7}, {%8,%9}, {%0,%1,%2,%3};" \
                 : "+f"((d)[0]), "+f"((d)[1]), "+f"((d)[2]), "+f"((d)[3]) \
                 : "r"((a)[0]), "r"((a)[1]), "r"((a)[2]), "r"((a)[3]), \
                   "r"((b)[0]), "r"((b)[1]))

__device__ __forceinline__ uint32_t pkbf2(float a, float b) {
    __nv_bfloat162 t = __floats2bfloat162_rn(a, b);
    return *reinterpret_cast<uint32_t*>(&t);
}

// ---------------- fp32 -> (hi, lo) bf16 split ---------------------------------
__global__ void __launch_bounds__(256)
cvt_hilo(const float* __restrict__ s, __nv_bfloat16* __restrict__ h,
         __nv_bfloat16* __restrict__ l, int n4)
{
    int i = blockIdx.x * 256 + threadIdx.x;
    if (i >= n4) return;
    float4 v = reinterpret_cast<const float4*>(s)[i];
    __nv_bfloat16 h0 = __float2bfloat16(v.x), h1 = __float2bfloat16(v.y);
    __nv_bfloat16 h2 = __float2bfloat16(v.z), h3 = __float2bfloat16(v.w);
    __nv_bfloat16 l0 = __float2bfloat16(v.x - __bfloat162float(h0));
    __nv_bfloat16 l1 = __float2bfloat16(v.y - __bfloat162float(h1));
    __nv_bfloat16 l2 = __float2bfloat16(v.z - __bfloat162float(h2));
    __nv_bfloat16 l3 = __float2bfloat16(v.w - __bfloat162float(h3));
    reinterpret_cast<__nv_bfloat162*>(h)[2*i]   = __halves2bfloat162(h0, h1);
    reinterpret_cast<__nv_bfloat162*>(h)[2*i+1] = __halves2bfloat162(h2, h3);
    reinterpret_cast<__nv_bfloat162*>(l)[2*i]   = __halves2bfloat162(l0, l1);
    reinterpret_cast<__nv_bfloat162*>(l)[2*i+1] = __halves2bfloat162(l2, l3);
}

// --------- build attention operand layouts: Q(scaled), K=(nope|rope), V -------
__global__ void __launch_bounds__(256)
cvt_attn(const float* __restrict__ q, const float* __restrict__ kvb,
         const float* __restrict__ kpe, float scale,
         __nv_bfloat16* __restrict__ qh, __nv_bfloat16* __restrict__ ql,
         __nv_bfloat16* __restrict__ kh, __nv_bfloat16* __restrict__ kl,
         __nv_bfloat16* __restrict__ vh, __nv_bfloat16* __restrict__ vl)
{
    const int t = blockIdx.x;           // token
    const int b = t >> 11, s = t & (SEQ-1);
    const int tid = threadIdx.x;

    for (int i = tid; i < NH*QKD; i += 256) {           // Q, scaled
        int h = i / QKD, d = i - h*QKD;
        float v = q[(size_t)t * (NH*QKD) + i] * scale;
        __nv_bfloat16 hb = __float2bfloat16(v);
        size_t dst = (((size_t)(b*NH + h))*SEQ + s)*QKD + d;
        qh[dst] = hb;
        ql[dst] = __float2bfloat16(v - __bfloat162float(hb));
    }
    for (int i = tid; i < NH*(NOPE+VD); i += 256) {     // K-nope / V
        int h = i >> 8, d = i & 255;
        float v = kvb[(size_t)t * (NH*(NOPE+VD)) + i];
        __nv_bfloat16 hb = __float2bfloat16(v);
        __nv_bfloat16 lb = __float2bfloat16(v - __bfloat162float(hb));
        if (d < NOPE) {
            size_t dst = (((size_t)(b*NH + h))*SEQ + s)*QKD + d;
            kh[dst] = hb; kl[dst] = lb;
        } else {
            size_t dst = (((size_t)(b*NH + h))*SEQ + s)*VD + (d - NOPE);
            vh[dst] = hb; vl[dst] = lb;
        }
    }
    for (int i = tid; i < NH*ROPE_D; i += 256) {        // K-rope (broadcast)
        int h = i >> 6, d = i & 63;
        float v = kpe[(size_t)t * ROPE_D + d];
        __nv_bfloat16 hb = __float2bfloat16(v);
        size_t dst = (((size_t)(b*NH + h))*SEQ + s)*QKD + NOPE + d;
        kh[dst] = hb;
        kl[dst] = __float2bfloat16(v - __bfloat162float(hb));
    }
}

// ============ warp-MMA NT GEMM: C = A*B^T, split bf16 (3 HMMA terms) ==========
#define OFF_AH 0
#define OFF_AL 8192
#define OFF_BH 16384
#define OFF_BL 24576
#define STAGE_SZ 32768
#define GSMEM (2*STAGE_SZ)

__global__ void __launch_bounds__(256, 2)
gemm_mma(const __nv_bfloat16* __restrict__ Ah, const __nv_bfloat16* __restrict__ Al,
         const __nv_bfloat16* __restrict__ Bh, const __nv_bfloat16* __restrict__ Bl,
         float* __restrict__ C, int M, int N, int K)
{
    extern __shared__ char smraw[];
    const uint32_t sbase = smem_u32(smraw);
    const int tid  = threadIdx.x;
    const int lane = tid & 31, wid = tid >> 5;
    const int bm = blockIdx.y * 128, bn = blockIdx.x * 128;
    const int wm = (wid >> 2) * 64, wn = (wid & 3) * 32;

    float acc[4][4][4];
#pragma unroll
    for (int mt = 0; mt < 4; mt++)
#pragma unroll
        for (int nt = 0; nt < 4; nt++)
#pragma unroll
            for (int e = 0; e < 4; e++) acc[mt][nt][e] = 0.f;

    const int NS = K >> 5;
    const int arow = lane & 15, akbo = lane >> 4;
    const int brow = lane & 7,  bkbo = (lane >> 3) & 1;

#define ISSUE_SLAB(st, kt) do {                                               \
    uint32_t _sb = sbase + (uint32_t)(st) * STAGE_SZ;                         \
    _Pragma("unroll")                                                         \
    for (int _i = 0; _i < 2; _i++) {                                          \
        int _idx = tid + _i * 256;                                            \
        int _row = _idx >> 2, _kb = _idx & 3;                                 \
        uint32_t _so = (uint32_t)((((_row >> 3) * 4 + _kb) * 128) + (_row & 7) * 16); \
        size_t _ga = (size_t)(bm + _row) * K + (kt) + _kb * 8;                \
        CP16(_sb + OFF_AH + _so, Ah + _ga, 16);                               \
        CP16(_sb + OFF_AL + _so, Al + _ga, 16);                               \
        int _nr = bn + _row;                                                  \
        int _ok = (_nr < N) ? 16 : 0;                                         \
        if (_nr >= N) _nr = 0;                                                \
        size_t _gb = (size_t)_nr * K + (kt) + _kb * 8;                        \
        CP16(_sb + OFF_BH + _so, Bh + _gb, _ok);                              \
        CP16(_sb + OFF_BL + _so, Bl + _gb, _ok);                              \
    } } while (0)

    ISSUE_SLAB(0, 0);
    CP_COMMIT();

    for (int s = 0; s < NS; s++) {
        const int cur = s & 1;
        if (s + 1 < NS) {
            ISSUE_SLAB((s + 1) & 1, (s + 1) * 32);
            CP_COMMIT();
            CP_WAIT1();
        } else {
            CP_WAIT0();
        }
        __syncthreads();

        const uint32_t sb = sbase + (uint32_t)cur * STAGE_SZ;
#pragma unroll
        for (int k16 = 0; k16 < 2; k16++) {
            uint32_t bh[4][2], bl[4][2];
#pragma unroll
            for (int nt = 0; nt < 4; nt++) {
                int n  = wn + nt * 8 + brow;
                int kb = k16 * 2 + bkbo;
                uint32_t off = (uint32_t)((((n >> 3) * 4 + kb) * 128) + (n & 7) * 16);
                LDSM_X2(bh[nt], sb + OFF_BH + off);
                LDSM_X2(bl[nt], sb + OFF_BL + off);
            }
#pragma unroll
            for (int mt = 0; mt < 4; mt++) {
                int r  = wm + mt * 16 + arow;
                int kb = k16 * 2 + akbo;
                uint32_t off = (uint32_t)((((r >> 3) * 4 + kb) * 128) + (r & 7) * 16);
                uint32_t ah[4], al[4];
                LDSM_X4(ah, sb + OFF_AH + off);
                LDSM_X4(al, sb + OFF_AL + off);
#pragma unroll
                for (int nt = 0; nt < 4; nt++) {
                    MMA16816(acc[mt][nt], ah, bh[nt]);
                    MMA16816(acc[mt][nt], ah, bl[nt]);
                    MMA16816(acc[mt][nt], al, bh[nt]);
                }
            }
        }
        __syncthreads();
    }

    const int erow = lane >> 2, ecol = (lane & 3) * 2;
#pragma unroll
    for (int mt = 0; mt < 4; mt++) {
#pragma unroll
        for (int nt = 0; nt < 4; nt++) {
            int col = bn + wn + nt * 8 + ecol;
            if (col < N) {
                int r0 = bm + wm + mt * 16 + erow;
                *reinterpret_cast<float2*>(C + (size_t)r0 * N + col) =
                    make_float2(acc[mt][nt][0], acc[mt][nt][1]);
                *reinterpret_cast<float2*>(C + (size_t)(r0 + 8) * N + col) =
                    make_float2(acc[mt][nt][2], acc[mt][nt][3]);
            }
        }
    }
}

// ------------- prep: RMSNorm(kv_c), RoPE(k_pe) (q NOT rotated — see reference) -
__global__ void __launch_bounds__(256)
prep_kernel(const float* __restrict__ kv,
            const float* __restrict__ kvnw,
            const float* __restrict__ fcos, const float* __restrict__ fsin,
            float* __restrict__ kvc, float* __restrict__ kpe)
{
    const int token = blockIdx.x;
    const int spos  = token & (SEQ - 1);
    const int tid   = threadIdx.x;
    __shared__ float red[256];

    const float* kvrow = kv + (size_t)token * (KV_LORA + ROPE_D);
    float ss = 0.f;
    for (int i = tid; i < KV_LORA; i += 256) { float v = kvrow[i]; ss += v*v; }
    red[tid] = ss;
    __syncthreads();
    for (int st = 128; st > 0; st >>= 1) {
        if (tid < st) red[tid] += red[tid + st];
        __syncthreads();
    }
    const float rms = rsqrtf(red[0] / (float)KV_LORA + 1e-6f);

    for (int i = tid; i < KV_LORA; i += 256)
        kvc[(size_t)token * KV_LORA + i] = kvrow[i] * rms * kvnw[i];

    if (tid < 32) {
        float re = kvrow[KV_LORA + 2*tid], im = kvrow[KV_LORA + 2*tid + 1];
        float c = fcos[spos*32 + tid], s = fsin[spos*32 + tid];
        kpe[(size_t)token * ROPE_D + 2*tid]     = re*c - im*s;
        kpe[(size_t)token * ROPE_D + 2*tid + 1] = re*s + im*c;
    }
}

// ===================== tensor-core flash attention =============================
// BM=128 (warp = 16 q rows), BN=32 kv chunks, Q resident in smem (hi/lo),
// K/V double-buffered cp.async stages, softmax in register fragments.
#define ATS_Q   0
#define ATS_QL  49152
#define ATS_ST  98304
#define ATS_K   0
#define ATS_KL  12288
#define ATS_V   24576
#define ATS_VL  32768
#define ATS_STAGE 40960
#define ATS_TOTAL (98304 + 2*ATS_STAGE)   // 180224

__global__ void __launch_bounds__(256, 1)
attn_mma(const __nv_bfloat16* __restrict__ qh_, const __nv_bfloat16* __restrict__ ql_,
         const __nv_bfloat16* __restrict__ kh_, const __nv_bfloat16* __restrict__ kl_,
         const __nv_bfloat16* __restrict__ vh_, const __nv_bfloat16* __restrict__ vl_,
         float* __restrict__ attn_out)
{
    extern __shared__ char sm[];
    const uint32_t sb = smem_u32(sm);
    const int tid = threadIdx.x, lane = tid & 31, w = tid >> 5;
    const int qi = (int)gridDim.x - 1 - (int)blockIdx.x;   // heavy tiles first
    const int h = blockIdx.y, b = blockIdx.z;
    const int qb = qi * 128;
    const size_t hoff = ((size_t)(b*NH + h)) * SEQ;
    const __nv_bfloat16* qh = qh_ + (hoff + qb) * QKD;
    const __nv_bfloat16* ql = ql_ + (hoff + qb) * QKD;
    const __nv_bfloat16* kh = kh_ + hoff * QKD;
    const __nv_bfloat16* kl = kl_ + hoff * QKD;
    const __nv_bfloat16* vh = vh_ + hoff * VD;
    const __nv_bfloat16* vl = vl_ + hoff * VD;
    const int NCH = 4*qi + 4;

#define AT_ISSUE(st, jj) do {                                                 \
    uint32_t _s = sb + ATS_ST + (uint32_t)(st) * ATS_STAGE;                   \
    int _p = tid >> 3, _c = tid & 7;                                          \
    _Pragma("unroll")                                                         \
    for (int _it = 0; _it < 3; _it++) {                                       \
        int _kb = _c + _it*8;                                                 \
        uint32_t _o = (uint32_t)((((_p>>3)*24 + _kb)*128) + (_p&7)*16);       \
        size_t _g = ((size_t)(jj)*32 + _p)*QKD + _kb*8;                       \
        CP16(_s + ATS_K  + _o, kh + _g, 16);                                  \
        CP16(_s + ATS_KL + _o, kl + _g, 16);                                  \
    }                                                                         \
    _Pragma("unroll")                                                         \
    for (int _it = 0; _it < 2; _it++) {                                       \
        int _cb = _c + _it*8;                                                 \
        uint32_t _o = (uint32_t)((((_p>>3)*16 + _cb)*128) + (_p&7)*16);       \
        size_t _g = ((size_t)(jj)*32 + _p)*VD + _cb*8;                        \
        CP16(_s + ATS_V  + _o, vh + _g, 16);                                  \
        CP16(_s + ATS_VL + _o, vl + _g, 16);                                  \
    } } while (0)

    AT_ISSUE(0, 0);
    CP_COMMIT();

    // Q resident load (plain; covered by first-loop barrier)
    {
        int m = tid >> 1;
#pragma unroll
        for (int it = 0; it < 12; it++) {
            int kb = (tid & 1) + it*2;
            uint32_t so = (uint32_t)((((m>>3)*24 + kb)*128) + (m&7)*16);
            *reinterpret_cast<uint4*>(sm + ATS_Q + so) =
                *reinterpret_cast<const uint4*>(qh + (size_t)m*QKD + kb*8);
            *reinterpret_cast<uint4*>(sm + ATS_QL + so) =
                *reinterpret_cast<const uint4*>(ql + (size_t)m*QKD + kb*8);
        }
    }

    float o[16][4];
#pragma unroll
    for (int nf = 0; nf < 16; nf++)
#pragma unroll
        for (int e = 0; e < 4; e++) o[nf][e] = 0.f;
    float m0 = -1e30f, m1 = -1e30f, l0 = 0.f, l1 = 0.f;

    const int rg0 = qb + w*16 + (lane >> 2);
    const int rg1 = rg0 + 8;

    for (int j = 0; j < NCH; j++) {
        if (j + 1 < NCH) { AT_ISSUE((j+1)&1, j+1); CP_COMMIT(); CP_WAIT1(); }
        else             { CP_WAIT0(); }
        __syncthreads();
        const uint32_t st = sb + ATS_ST + (uint32_t)(j & 1) * ATS_STAGE;

        // ---- S = Q K^T (12 k16 steps x 3 split terms) ----
        float s4[4][4];
#pragma unroll
        for (int nf = 0; nf < 4; nf++)
#pragma unroll
            for (int e = 0; e < 4; e++) s4[nf][e] = 0.f;

#pragma unroll
        for (int kk = 0; kk < 12; kk++) {
            int am = w*16 + (lane & 15);
            int akb = kk*2 + (lane >> 4);
            uint32_t aoff = (uint32_t)((((am>>3)*24 + akb)*128) + (am&7)*16);
            uint32_t aqh[4], aql[4];
            LDSM_X4(aqh, sb + ATS_Q  + aoff);
            LDSM_X4(aql, sb + ATS_QL + aoff);
            int bn = lane & 7;
            int bkb = kk*2 + ((lane >> 3) & 1);
#pragma unroll
            for (int nf = 0; nf < 4; nf++) {
                int n = nf*8 + bn;
                uint32_t boff = (uint32_t)((((n>>3)*24 + bkb)*128) + (n&7)*16);
                uint32_t bkh[2], bkl[2];
                LDSM_X2(bkh, st + ATS_K  + boff);
                LDSM_X2(bkl, st + ATS_KL + boff);
                MMA16816(s4[nf], aqh, bkh);
                MMA16816(s4[nf], aqh, bkl);
                MMA16816(s4[nf], aql, bkh);
            }
        }

        // ---- causal mask (diagonal band chunks only) ----
        if (j >= 4*qi) {
            int cb = j*32 + (lane & 3)*2;
#pragma unroll
            for (int nf = 0; nf < 4; nf++) {
                int c = cb + nf*8;
                if (c     > rg0) s4[nf][0] = -1e30f;
                if (c + 1 > rg0) s4[nf][1] = -1e30f;
                if (c     > rg1) s4[nf][2] = -1e30f;
                if (c + 1 > rg1) s4[nf][3] = -1e30f;
            }
        }

        // ---- online softmax in registers ----
        float mx0 = -1e30f, mx1 = -1e30f;
#pragma unroll
        for (int nf = 0; nf < 4; nf++) {
            mx0 = fmaxf(mx0, fmaxf(s4[nf][0], s4[nf][1]));
            mx1 = fmaxf(mx1, fmaxf(s4[nf][2], s4[nf][3]));
        }
        mx0 = fmaxf(mx0, __shfl_xor_sync(0xffffffffu, mx0, 1));
        mx0 = fmaxf(mx0, __shfl_xor_sync(0xffffffffu, mx0, 2));
        mx1 = fmaxf(mx1, __shfl_xor_sync(0xffffffffu, mx1, 1));
        mx1 = fmaxf(mx1, __shfl_xor_sync(0xffffffffu, mx1, 2));
        float mn0 = fmaxf(m0, mx0), mn1 = fmaxf(m1, mx1);
        float c0 = __expf(m0 - mn0), c1 = __expf(m1 - mn1);
        m0 = mn0; m1 = mn1;
        float sum0 = 0.f, sum1 = 0.f;
#pragma unroll
        for (int nf = 0; nf < 4; nf++) {
            s4[nf][0] = __expf(s4[nf][0] - mn0);
            s4[nf][1] = __expf(s4[nf][1] - mn0);
            s4[nf][2] = __expf(s4[nf][2] - mn1);
            s4[nf][3] = __expf(s4[nf][3] - mn1);
            sum0 += s4[nf][0] + s4[nf][1];
            sum1 += s4[nf][2] + s4[nf][3];
        }
        sum0 += __shfl_xor_sync(0xffffffffu, sum0, 1);
        sum0 += __shfl_xor_sync(0xffffffffu, sum0, 2);
        sum1 += __shfl_xor_sync(0xffffffffu, sum1, 1);
        sum1 += __shfl_xor_sync(0xffffffffu, sum1, 2);
        l0 = l0*c0 + sum0;
        l1 = l1*c1 + sum1;
#pragma unroll
        for (int nf = 0; nf < 16; nf++) {
            o[nf][0] *= c0; o[nf][1] *= c0; o[nf][2] *= c1; o[nf][3] *= c1;
        }

        // ---- O += P V (2 k16 steps x 3 split terms) ----
#pragma unroll
        for (int kk = 0; kk < 2; kk++) {
            float eh[8], el[8];
#pragma unroll
            for (int e = 0; e < 8; e++) {
                float p = (e < 4) ? s4[2*kk][e] : s4[2*kk+1][e-4];
                __nv_bfloat16 hb = __float2bfloat16(p);
                eh[e] = __bfloat162float(hb);
                el[e] = p - eh[e];
            }
            uint32_t aph[4] = {pkbf2(eh[0],eh[1]), pkbf2(eh[2],eh[3]),
                               pkbf2(eh[4],eh[5]), pkbf2(eh[6],eh[7])};
            uint32_t apl[4] = {pkbf2(el[0],el[1]), pkbf2(el[2],el[3]),
                               pkbf2(el[4],el[5]), pkbf2(el[6],el[7])};
            int r = kk*16 + (lane & 15);
#pragma unroll
            for (int nf = 0; nf < 16; nf++) {
                uint32_t voff = (uint32_t)((((r>>3)*16 + nf)*128) + (r&7)*16);
                uint32_t bvh[2], bvl[2];
                LDSM_X2T(bvh, st + ATS_V  + voff);
                LDSM_X2T(bvl, st + ATS_VL + voff);
                MMA16816(o[nf], aph, bvh);
                MMA16816(o[nf], aph, bvl);
                MMA16816(o[nf], apl, bvh);
            }
        }
        __syncthreads();   // all warps done with stage j before it's refilled
    }

    // ---- epilogue ----
    const float i0 = 1.f / l0, i1 = 1.f / l1;
    const size_t t0 = (size_t)b*SEQ + rg0;
#pragma unroll
    for (int nf = 0; nf < 16; nf++) {
        int col = h*VD + nf*8 + (lane & 3)*2;
        *reinterpret_cast<float2*>(attn_out + t0*(NH*VD) + col) =
            make_float2(o[nf][0]*i0, o[nf][1]*i0);
        *reinterpret_cast<float2*>(attn_out + (t0+8)*(NH*VD) + col) =
            make_float2(o[nf][2]*i1, o[nf][3]*i1);
    }
}

// ---------------------------------- launch -----------------------------------
static inline void cvt(const float* s, __nv_bfloat16* h, __nv_bfloat16* l, size_t n) {
    int n4 = (int)(n / 4);
    cvt_hilo<<<(n4 + 255) / 256, 256>>>(s, h, l, n4);
}

extern "C" void kernel_launch(void* const* d_in, const int* in_sizes, int n_in,
                              void* d_out, int out_size)
{
    const float* x     = (const float*)d_in[0];
    const float* wq    = (const float*)d_in[1];
    const float* wkv_a = (const float*)d_in[2];
    const float* kvnw  = (const float*)d_in[3];
    const float* wkv_b = (const float*)d_in[4];
    const float* wo    = (const float*)d_in[5];
    const float* fcos  = (const float*)d_in[6];
    const float* fsin  = (const float*)d_in[7];
    float* out = (float*)d_out;

    float *q, *kv, *kvc, *kpe, *kvb, *attn;
    cudaGetSymbolAddress((void**)&q,    g_q);
    cudaGetSymbolAddress((void**)&kv,   g_kv);
    cudaGetSymbolAddress((void**)&kvc,  g_kvc);
    cudaGetSymbolAddress((void**)&kpe,  g_kpe);
    cudaGetSymbolAddress((void**)&kvb,  g_kvb);
    cudaGetSymbolAddress((void**)&attn, g_attn);

    __nv_bfloat16 *xh,*xl,*wqh,*wql,*wah,*wal,*wbh,*wbl,*woh,*wol,*kvch,*kvcl,*ath,*atl;
    __nv_bfloat16 *aqh,*aql,*akh,*akl,*avh,*avl;
    cudaGetSymbolAddress((void**)&xh,  g_xh);   cudaGetSymbolAddress((void**)&xl,  g_xl);
    cudaGetSymbolAddress((void**)&wqh, g_wqh);  cudaGetSymbolAddress((void**)&wql, g_wql);
    cudaGetSymbolAddress((void**)&wah, g_wah);  cudaGetSymbolAddress((void**)&wal, g_wal);
    cudaGetSymbolAddress((void**)&wbh, g_wbh);  cudaGetSymbolAddress((void**)&wbl, g_wbl);
    cudaGetSymbolAddress((void**)&woh, g_woh);  cudaGetSymbolAddress((void**)&wol, g_wol);
    cudaGetSymbolAddress((void**)&kvch,g_kvch); cudaGetSymbolAddress((void**)&kvcl,g_kvcl);
    cudaGetSymbolAddress((void**)&ath, g_ath);  cudaGetSymbolAddress((void**)&atl, g_atl);
    cudaGetSymbolAddress((void**)&aqh, g_aqh);  cudaGetSymbolAddress((void**)&aql, g_aql);
    cudaGetSymbolAddress((void**)&akh, g_akh);  cudaGetSymbolAddress((void**)&akl, g_akl);
    cudaGetSymbolAddress((void**)&avh, g_avh);  cudaGetSymbolAddress((void**)&avl, g_avl);

    double mm = 0.1 * 1.0 * log(40.0) + 1.0;
    float scale = (float)(mm * mm / sqrt((double)QKD));

    cudaFuncSetAttribute(gemm_mma, cudaFuncAttributeMaxDynamicSharedMemorySize, GSMEM);
    cudaFuncSetAttribute(attn_mma, cudaFuncAttributeMaxDynamicSharedMemorySize, ATS_TOTAL);

    cvt(x,     xh,  xl,  (size_t)NTOK * DIM);
    cvt(wq,    wqh, wql, (size_t)NH*QKD * DIM);
    cvt(wkv_a, wah, wal, (size_t)(KV_LORA+ROPE_D) * DIM);
    cvt(wkv_b, wbh, wbl, (size_t)NH*(NOPE+VD) * KV_LORA);
    cvt(wo,    woh, wol, (size_t)DIM * NH*VD);

    // q = x @ wq^T        [4096, 3072]
    gemm_mma<<<dim3(3072/128, 32), 256, GSMEM>>>(xh, xl, wqh, wql, q, NTOK, NH*QKD, DIM);
    // kv = x @ wkv_a^T    [4096, 576]
    gemm_mma<<<dim3(5, 32), 256, GSMEM>>>(xh, xl, wah, wal, kv, NTOK, KV_LORA+ROPE_D, DIM);
    // rmsnorm + k_pe rope (q NOT rotated — matches reference semantics)
    prep_kernel<<<NTOK, 256>>>(kv, kvnw, fcos, fsin, kvc, kpe);
    cvt(kvc, kvch, kvcl, (size_t)NTOK * KV_LORA);
    // kvb = kvc @ wkv_b^T [4096, 4096]
    gemm_mma<<<dim3(4096/128, 32), 256, GSMEM>>>(kvch, kvcl, wbh, wbl, kvb, NTOK, NH*(NOPE+VD), KV_LORA);
    // attention operand layouts (Q scaled, K = nope|rope, V), split bf16
    cvt_attn<<<NTOK, 256>>>(q, kvb, kpe, scale, aqh, aql, akh, akl, avh, avl);
    // tensor-core flash attention
    attn_mma<<<dim3(SEQ/128, NH, BATCH), 256, ATS_TOTAL>>>(
        aqh, aql, akh, akl, avh, avl, attn);
    cvt(attn, ath, atl, (size_t)NTOK * NH*VD);
    // out = attn @ wo^T   [4096, 2048]
    gemm_mma<<<dim3(2048/128, 32), 256, GSMEM>>>(ath, atl, woh, wol, out, NTOK, DIM, NH*VD);
}

// round 14
// speedup vs baseline: 2.7740x; 1.0278x over previous
#include <cuda_runtime.h>
#include <cuda_bf16.h>
#include <math.h>
#include <stdint.h>

#define DIM 2048
#define NH 16
#define KV_LORA 512
#define NOPE 128
#define ROPE_D 64
#define VD 128
#define QKD 192
#define BATCH 2
#define SEQ 2048
#define NTOK (BATCH*SEQ)

// ---------------- fp32 scratch ------------------------------------------------
__device__ float g_kv[(size_t)NTOK * (KV_LORA + ROPE_D)];

// ---------------- bf16 hi/lo scratch (GEMM operands) ---------------------------
__device__ __nv_bfloat16 g_xh[(size_t)NTOK * DIM],              g_xl[(size_t)NTOK * DIM];
__device__ __nv_bfloat16 g_wqh[(size_t)NH*QKD * DIM],           g_wql[(size_t)NH*QKD * DIM];
__device__ __nv_bfloat16 g_wah[(size_t)(KV_LORA+ROPE_D) * DIM], g_wal[(size_t)(KV_LORA+ROPE_D) * DIM];
__device__ __nv_bfloat16 g_wbh[(size_t)NH*(NOPE+VD) * KV_LORA], g_wbl[(size_t)NH*(NOPE+VD) * KV_LORA];
__device__ __nv_bfloat16 g_woh[(size_t)DIM * NH*VD],            g_wol[(size_t)DIM * NH*VD];
__device__ __nv_bfloat16 g_kvch[(size_t)NTOK * KV_LORA],        g_kvcl[(size_t)NTOK * KV_LORA];
__device__ __nv_bfloat16 g_ath[(size_t)NTOK * NH*VD],           g_atl[(size_t)NTOK * NH*VD];

// ---------------- bf16 hi/lo attention layouts [b][h][s][d] --------------------
__device__ __nv_bfloat16 g_aqh[(size_t)NTOK * NH * QKD], g_aql[(size_t)NTOK * NH * QKD];
__device__ __nv_bfloat16 g_akh[(size_t)NTOK * NH * QKD], g_akl[(size_t)NTOK * NH * QKD];
__device__ __nv_bfloat16 g_avh[(size_t)NTOK * NH * VD],  g_avl[(size_t)NTOK * NH * VD];

// ======================= PTX helpers (baseline sm_103) =========================
__device__ __forceinline__ uint32_t smem_u32(const void* p) {
    uint32_t a;
    asm("{ .reg .u64 t; cvta.to.shared.u64 t, %1; cvt.u32.u64 %0, t; }"
        : "=r"(a) : "l"(p));
    return a;
}
#define CP16(s, g, sz) \
    asm volatile("cp.async.cg.shared.global [%0], [%1], 16, %2;" \
                 :: "r"(s), "l"(g), "r"(sz) : "memory")
#define CP_COMMIT() asm volatile("cp.async.commit_group;" ::: "memory")
#define CP_WAIT1()  asm volatile("cp.async.wait_group 1;" ::: "memory")
#define CP_WAIT0()  asm volatile("cp.async.wait_group 0;" ::: "memory")

#define LDSM_X4(r, a) \
    asm volatile("ldmatrix.sync.aligned.m8n8.x4.shared.b16 {%0,%1,%2,%3}, [%4];" \
                 : "=r"((r)[0]), "=r"((r)[1]), "=r"((r)[2]), "=r"((r)[3]) : "r"(a))
#define LDSM_X2(r, a) \
    asm volatile("ldmatrix.sync.aligned.m8n8.x2.shared.b16 {%0,%1}, [%2];" \
                 : "=r"((r)[0]), "=r"((r)[1]) : "r"(a))
#define LDSM_X2T(r, a) \
    asm volatile("ldmatrix.sync.aligned.m8n8.x2.trans.shared.b16 {%0,%1}, [%2];" \
                 : "=r"((r)[0]), "=r"((r)[1]) : "r"(a))
#define MMA16816(d, a, b) \
    asm volatile("mma.sync.aligned.m16n8k16.row.col.f32.bf16.bf16.f32 " \
                 "{%0,%1,%2,%3}, {%4,%5,%6,%7}, {%8,%9}, {%0,%1,%2,%3};" \
                 : "+f"((d)[0]), "+f"((d)[1]), "+f"((d)[2]), "+f"((d)[3]) \
                 : "r"((a)[0]), "r"((a)[1]), "r"((a)[2]), "r"((a)[3]), \
                   "r"((b)[0]), "r"((b)[1]))

__device__ __forceinline__ uint32_t pkbf2(float a, float b) {
    __nv_bfloat162 t = __floats2bfloat162_rn(a, b);
    return *reinterpret_cast<uint32_t*>(&t);
}
// split-store a pair of fp32 into hi/lo bf162 at 4B-aligned destinations
__device__ __forceinline__ void split_store2(float v0, float v1,
                                             __nv_bfloat16* ph, __nv_bfloat16* pl) {
    __nv_bfloat16 h0 = __float2bfloat16(v0), h1 = __float2bfloat16(v1);
    __nv_bfloat16 l0 = __float2bfloat16(v0 - __bfloat162float(h0));
    __nv_bfloat16 l1 = __float2bfloat16(v1 - __bfloat162float(h1));
    *reinterpret_cast<__nv_bfloat162*>(ph) = __halves2bfloat162(h0, h1);
    *reinterpret_cast<__nv_bfloat162*>(pl) = __halves2bfloat162(l0, l1);
}

// ---------------- fp32 -> (hi, lo) bf16 split ---------------------------------
__global__ void __launch_bounds__(256)
cvt_hilo(const float* __restrict__ s, __nv_bfloat16* __restrict__ h,
         __nv_bfloat16* __restrict__ l, int n4)
{
    int i = blockIdx.x * 256 + threadIdx.x;
    if (i >= n4) return;
    float4 v = reinterpret_cast<const float4*>(s)[i];
    __nv_bfloat16 h0 = __float2bfloat16(v.x), h1 = __float2bfloat16(v.y);
    __nv_bfloat16 h2 = __float2bfloat16(v.z), h3 = __float2bfloat16(v.w);
    __nv_bfloat16 l0 = __float2bfloat16(v.x - __bfloat162float(h0));
    __nv_bfloat16 l1 = __float2bfloat16(v.y - __bfloat162float(h1));
    __nv_bfloat16 l2 = __float2bfloat16(v.z - __bfloat162float(h2));
    __nv_bfloat16 l3 = __float2bfloat16(v.w - __bfloat162float(h3));
    reinterpret_cast<__nv_bfloat162*>(h)[2*i]   = __halves2bfloat162(h0, h1);
    reinterpret_cast<__nv_bfloat162*>(h)[2*i+1] = __halves2bfloat162(h2, h3);
    reinterpret_cast<__nv_bfloat162*>(l)[2*i]   = __halves2bfloat162(l0, l1);
    reinterpret_cast<__nv_bfloat162*>(l)[2*i+1] = __halves2bfloat162(l2, l3);
}

// ============ warp-MMA NT GEMM: C = A*B^T, split bf16 (3 HMMA terms) ==========
// MODE 0: fp32 C.  MODE 1: q epilogue (scale + split, [b,h,s,d] QKD layout).
// MODE 2: kvb epilogue (split; d<128 -> K-nope layout, d>=128 -> V layout).
#define OFF_AH 0
#define OFF_AL 8192
#define OFF_BH 16384
#define OFF_BL 24576
#define STAGE_SZ 32768
#define GSMEM (2*STAGE_SZ)

template<int MODE>
__global__ void __launch_bounds__(256, 2)
gemm_mma(const __nv_bfloat16* __restrict__ Ah, const __nv_bfloat16* __restrict__ Al,
         const __nv_bfloat16* __restrict__ Bh, const __nv_bfloat16* __restrict__ Bl,
         float* __restrict__ C,
         __nv_bfloat16* __restrict__ P0, __nv_bfloat16* __restrict__ P1,
         __nv_bfloat16* __restrict__ P2, __nv_bfloat16* __restrict__ P3,
         float scale, int M, int N, int K)
{
    extern __shared__ char smraw[];
    const uint32_t sbase = smem_u32(smraw);
    const int tid  = threadIdx.x;
    const int lane = tid & 31, wid = tid >> 5;
    const int bm = blockIdx.y * 128, bn = blockIdx.x * 128;
    const int wm = (wid >> 2) * 64, wn = (wid & 3) * 32;

    float acc[4][4][4];
#pragma unroll
    for (int mt = 0; mt < 4; mt++)
#pragma unroll
        for (int nt = 0; nt < 4; nt++)
#pragma unroll
            for (int e = 0; e < 4; e++) acc[mt][nt][e] = 0.f;

    const int NS = K >> 5;
    const int arow = lane & 15, akbo = lane >> 4;
    const int brow = lane & 7,  bkbo = (lane >> 3) & 1;

#define ISSUE_SLAB(st, kt) do {                                               \
    uint32_t _sb = sbase + (uint32_t)(st) * STAGE_SZ;                         \
    _Pragma("unroll")                                                         \
    for (int _i = 0; _i < 2; _i++) {                                          \
        int _idx = tid + _i * 256;                                            \
        int _row = _idx >> 2, _kb = _idx & 3;                                 \
        uint32_t _so = (uint32_t)((((_row >> 3) * 4 + _kb) * 128) + (_row & 7) * 16); \
        size_t _ga = (size_t)(bm + _row) * K + (kt) + _kb * 8;                \
        CP16(_sb + OFF_AH + _so, Ah + _ga, 16);                               \
        CP16(_sb + OFF_AL + _so, Al + _ga, 16);                               \
        int _nr = bn + _row;                                                  \
        int _ok = (_nr < N) ? 16 : 0;                                         \
        if (_nr >= N) _nr = 0;                                                \
        size_t _gb = (size_t)_nr * K + (kt) + _kb * 8;                        \
        CP16(_sb + OFF_BH + _so, Bh + _gb, _ok);                              \
        CP16(_sb + OFF_BL + _so, Bl + _gb, _ok);                              \
    } } while (0)

    ISSUE_SLAB(0, 0);
    CP_COMMIT();

    for (int s = 0; s < NS; s++) {
        const int cur = s & 1;
        if (s + 1 < NS) {
            ISSUE_SLAB((s + 1) & 1, (s + 1) * 32);
            CP_COMMIT();
            CP_WAIT1();
        } else {
            CP_WAIT0();
        }
        __syncthreads();

        const uint32_t sb = sbase + (uint32_t)cur * STAGE_SZ;
#pragma unroll
        for (int k16 = 0; k16 < 2; k16++) {
            uint32_t bh[4][2], bl[4][2];
#pragma unroll
            for (int nt = 0; nt < 4; nt++) {
                int n  = wn + nt * 8 + brow;
                int kb = k16 * 2 + bkbo;
                uint32_t off = (uint32_t)((((n >> 3) * 4 + kb) * 128) + (n & 7) * 16);
                LDSM_X2(bh[nt], sb + OFF_BH + off);
                LDSM_X2(bl[nt], sb + OFF_BL + off);
            }
#pragma unroll
            for (int mt = 0; mt < 4; mt++) {
                int r  = wm + mt * 16 + arow;
                int kb = k16 * 2 + akbo;
                uint32_t off = (uint32_t)((((r >> 3) * 4 + kb) * 128) + (r & 7) * 16);
                uint32_t ah[4], al[4];
                LDSM_X4(ah, sb + OFF_AH + off);
                LDSM_X4(al, sb + OFF_AL + off);
#pragma unroll
                for (int nt = 0; nt < 4; nt++) {
                    MMA16816(acc[mt][nt], ah, bh[nt]);
                    MMA16816(acc[mt][nt], ah, bl[nt]);
                    MMA16816(acc[mt][nt], al, bh[nt]);
                }
            }
        }
        __syncthreads();
    }

    const int erow = lane >> 2, ecol = (lane & 3) * 2;
#pragma unroll
    for (int mt = 0; mt < 4; mt++) {
#pragma unroll
        for (int nt = 0; nt < 4; nt++) {
            int col = bn + wn + nt * 8 + ecol;
            if (col >= N) continue;
            int r0 = bm + wm + mt * 16 + erow;
#pragma unroll
            for (int half = 0; half < 2; half++) {
                int row = r0 + half * 8;
                float v0 = acc[mt][nt][2*half+0], v1 = acc[mt][nt][2*half+1];
                if (MODE == 0) {
                    *reinterpret_cast<float2*>(C + (size_t)row * N + col) =
                        make_float2(v0, v1);
                } else if (MODE == 1) {
                    // q: scale + split into [b,h,s,d] (d pairs stay in-head)
                    int h = col / QKD, d = col - h * QKD;
                    size_t dst = (((size_t)((row >> 11)*NH + h))*SEQ + (row & (SEQ-1)))*QKD + d;
                    split_store2(v0*scale, v1*scale, P0 + dst, P1 + dst);
                } else {
                    // kvb: split; d<128 -> K-nope, else V
                    int h = col >> 8, d = col & 255;
                    size_t tb = ((size_t)((row >> 11)*NH + h))*SEQ + (row & (SEQ-1));
                    if (d < NOPE) {
                        size_t dst = tb*QKD + d;
                        split_store2(v0, v1, P0 + dst, P1 + dst);
                    } else {
                        size_t dst = tb*VD + (d - NOPE);
                        split_store2(v0, v1, P2 + dst, P3 + dst);
                    }
                }
            }
        }
    }
}

// ------------- prep: RMSNorm(kv_c) -> split, RoPE(k_pe) -> split K layout -----
// (q NOT rotated — reference rotates a copy and drops it)
__global__ void __launch_bounds__(256)
prep_kernel(const float* __restrict__ kv,
            const float* __restrict__ kvnw,
            const float* __restrict__ fcos, const float* __restrict__ fsin,
            __nv_bfloat16* __restrict__ kvch, __nv_bfloat16* __restrict__ kvcl,
            __nv_bfloat16* __restrict__ akh,  __nv_bfloat16* __restrict__ akl)
{
    const int token = blockIdx.x;
    const int b     = token >> 11;
    const int spos  = token & (SEQ - 1);
    const int tid   = threadIdx.x;
    __shared__ float red[256];
    __shared__ float rope[ROPE_D];

    const float* kvrow = kv + (size_t)token * (KV_LORA + ROPE_D);
    float ss = 0.f;
    for (int i = tid; i < KV_LORA; i += 256) { float v = kvrow[i]; ss += v*v; }
    red[tid] = ss;
    __syncthreads();
    for (int st = 128; st > 0; st >>= 1) {
        if (tid < st) red[tid] += red[tid + st];
        __syncthreads();
    }
    const float rms = rsqrtf(red[0] / (float)KV_LORA + 1e-6f);

    for (int i = tid; i < KV_LORA; i += 256) {
        float v = kvrow[i] * rms * kvnw[i];
        __nv_bfloat16 hb = __float2bfloat16(v);
        kvch[(size_t)token * KV_LORA + i] = hb;
        kvcl[(size_t)token * KV_LORA + i] = __float2bfloat16(v - __bfloat162float(hb));
    }

    if (tid < 32) {
        float re = kvrow[KV_LORA + 2*tid], im = kvrow[KV_LORA + 2*tid + 1];
        float c = fcos[spos*32 + tid], s = fsin[spos*32 + tid];
        rope[2*tid]     = re*c - im*s;
        rope[2*tid + 1] = re*s + im*c;
    }
    __syncthreads();

    // broadcast roped k_pe into all heads' K layout (d = 128..191)
    for (int i = tid; i < NH * ROPE_D; i += 256) {
        int h = i >> 6, d = i & 63;
        float v = rope[d];
        __nv_bfloat16 hb = __float2bfloat16(v);
        size_t dst = (((size_t)(b*NH + h))*SEQ + spos)*QKD + NOPE + d;
        akh[dst] = hb;
        akl[dst] = __float2bfloat16(v - __bfloat162float(hb));
    }
}

// ===================== tensor-core flash attention =============================
#define ATS_Q   0
#define ATS_QL  49152
#define ATS_ST  98304
#define ATS_K   0
#define ATS_KL  12288
#define ATS_V   24576
#define ATS_VL  32768
#define ATS_STAGE 40960
#define ATS_TOTAL (98304 + 2*ATS_STAGE)   // 180224

__global__ void __launch_bounds__(256, 1)
attn_mma(const __nv_bfloat16* __restrict__ qh_, const __nv_bfloat16* __restrict__ ql_,
         const __nv_bfloat16* __restrict__ kh_, const __nv_bfloat16* __restrict__ kl_,
         const __nv_bfloat16* __restrict__ vh_, const __nv_bfloat16* __restrict__ vl_,
         __nv_bfloat16* __restrict__ outh, __nv_bfloat16* __restrict__ outl)
{
    extern __shared__ char sm[];
    const uint32_t sb = smem_u32(sm);
    const int tid = threadIdx.x, lane = tid & 31, w = tid >> 5;
    const int qi = (int)gridDim.x - 1 - (int)blockIdx.x;   // heavy tiles first
    const int h = blockIdx.y, b = blockIdx.z;
    const int qb = qi * 128;
    const size_t hoff = ((size_t)(b*NH + h)) * SEQ;
    const __nv_bfloat16* qh = qh_ + (hoff + qb) * QKD;
    const __nv_bfloat16* ql = ql_ + (hoff + qb) * QKD;
    const __nv_bfloat16* kh = kh_ + hoff * QKD;
    const __nv_bfloat16* kl = kl_ + hoff * QKD;
    const __nv_bfloat16* vh = vh_ + hoff * VD;
    const __nv_bfloat16* vl = vl_ + hoff * VD;
    const int NCH = 4*qi + 4;

#define AT_ISSUE(st, jj) do {                                                 \
    uint32_t _s = sb + ATS_ST + (uint32_t)(st) * ATS_STAGE;                   \
    int _p = tid >> 3, _c = tid & 7;                                          \
    _Pragma("unroll")                                                         \
    for (int _it = 0; _it < 3; _it++) {                                       \
        int _kb = _c + _it*8;                                                 \
        uint32_t _o = (uint32_t)((((_p>>3)*24 + _kb)*128) + (_p&7)*16);       \
        size_t _g = ((size_t)(jj)*32 + _p)*QKD + _kb*8;                       \
        CP16(_s + ATS_K  + _o, kh + _g, 16);                                  \
        CP16(_s + ATS_KL + _o, kl + _g, 16);                                  \
    }                                                                         \
    _Pragma("unroll")                                                         \
    for (int _it = 0; _it < 2; _it++) {                                       \
        int _cb = _c + _it*8;                                                 \
        uint32_t _o = (uint32_t)((((_p>>3)*16 + _cb)*128) + (_p&7)*16);       \
        size_t _g = ((size_t)(jj)*32 + _p)*VD + _cb*8;                        \
        CP16(_s + ATS_V  + _o, vh + _g, 16);                                  \
        CP16(_s + ATS_VL + _o, vl + _g, 16);                                  \
    } } while (0)

    AT_ISSUE(0, 0);
    CP_COMMIT();

    // Q resident load (plain; covered by first-loop barrier)
    {
        int m = tid >> 1;
#pragma unroll
        for (int it = 0; it < 12; it++) {
            int kb = (tid & 1) + it*2;
            uint32_t so = (uint32_t)((((m>>3)*24 + kb)*128) + (m&7)*16);
            *reinterpret_cast<uint4*>(sm + ATS_Q + so) =
                *reinterpret_cast<const uint4*>(qh + (size_t)m*QKD + kb*8);
            *reinterpret_cast<uint4*>(sm + ATS_QL + so) =
                *reinterpret_cast<const uint4*>(ql + (size_t)m*QKD + kb*8);
        }
    }

    float o[16][4];
#pragma unroll
    for (int nf = 0; nf < 16; nf++)
#pragma unroll
        for (int e = 0; e < 4; e++) o[nf][e] = 0.f;
    float m0 = -1e30f, m1 = -1e30f, l0 = 0.f, l1 = 0.f;

    const int rg0 = qb + w*16 + (lane >> 2);
    const int rg1 = rg0 + 8;

    for (int j = 0; j < NCH; j++) {
        if (j + 1 < NCH) { AT_ISSUE((j+1)&1, j+1); CP_COMMIT(); CP_WAIT1(); }
        else             { CP_WAIT0(); }
        __syncthreads();
        const uint32_t st = sb + ATS_ST + (uint32_t)(j & 1) * ATS_STAGE;

        // ---- S = Q K^T (12 k16 steps x 3 split terms) ----
        float s4[4][4];
#pragma unroll
        for (int nf = 0; nf < 4; nf++)
#pragma unroll
            for (int e = 0; e < 4; e++) s4[nf][e] = 0.f;

#pragma unroll
        for (int kk = 0; kk < 12; kk++) {
            int am = w*16 + (lane & 15);
            int akb = kk*2 + (lane >> 4);
            uint32_t aoff = (uint32_t)((((am>>3)*24 + akb)*128) + (am&7)*16);
            uint32_t aqh[4], aql[4];
            LDSM_X4(aqh, sb + ATS_Q  + aoff);
            LDSM_X4(aql, sb + ATS_QL + aoff);
            int bn = lane & 7;
            int bkb = kk*2 + ((lane >> 3) & 1);
#pragma unroll
            for (int nf = 0; nf < 4; nf++) {
                int n = nf*8 + bn;
                uint32_t boff = (uint32_t)((((n>>3)*24 + bkb)*128) + (n&7)*16);
                uint32_t bkh[2], bkl[2];
                LDSM_X2(bkh, st + ATS_K  + boff);
                LDSM_X2(bkl, st + ATS_KL + boff);
                MMA16816(s4[nf], aqh, bkh);
                MMA16816(s4[nf], aqh, bkl);
                MMA16816(s4[nf], aql, bkh);
            }
        }

        // ---- causal mask (diagonal band chunks only) ----
        if (j >= 4*qi) {
            int cb = j*32 + (lane & 3)*2;
#pragma unroll
            for (int nf = 0; nf < 4; nf++) {
                int c = cb + nf*8;
                if (c     > rg0) s4[nf][0] = -1e30f;
                if (c + 1 > rg0) s4[nf][1] = -1e30f;
                if (c     > rg1) s4[nf][2] = -1e30f;
                if (c + 1 > rg1) s4[nf][3] = -1e30f;
            }
        }

        // ---- online softmax in registers ----
        float mx0 = -1e30f, mx1 = -1e30f;
#pragma unroll
        for (int nf = 0; nf < 4; nf++) {
            mx0 = fmaxf(mx0, fmaxf(s4[nf][0], s4[nf][1]));
            mx1 = fmaxf(mx1, fmaxf(s4[nf][2], s4[nf][3]));
        }
        mx0 = fmaxf(mx0, __shfl_xor_sync(0xffffffffu, mx0, 1));
        mx0 = fmaxf(mx0, __shfl_xor_sync(0xffffffffu, mx0, 2));
        mx1 = fmaxf(mx1, __shfl_xor_sync(0xffffffffu, mx1, 1));
        mx1 = fmaxf(mx1, __shfl_xor_sync(0xffffffffu, mx1, 2));
        float mn0 = fmaxf(m0, mx0), mn1 = fmaxf(m1, mx1);
        float c0 = __expf(m0 - mn0), c1 = __expf(m1 - mn1);
        m0 = mn0; m1 = mn1;
        float sum0 = 0.f, sum1 = 0.f;
#pragma unroll
        for (int nf = 0; nf < 4; nf++) {
            s4[nf][0] = __expf(s4[nf][0] - mn0);
            s4[nf][1] = __expf(s4[nf][1] - mn0);
            s4[nf][2] = __expf(s4[nf][2] - mn1);
            s4[nf][3] = __expf(s4[nf][3] - mn1);
            sum0 += s4[nf][0] + s4[nf][1];
            sum1 += s4[nf][2] + s4[nf][3];
        }
        sum0 += __shfl_xor_sync(0xffffffffu, sum0, 1);
        sum0 += __shfl_xor_sync(0xffffffffu, sum0, 2);
        sum1 += __shfl_xor_sync(0xffffffffu, sum1, 1);
        sum1 += __shfl_xor_sync(0xffffffffu, sum1, 2);
        l0 = l0*c0 + sum0;
        l1 = l1*c1 + sum1;
#pragma unroll
        for (int nf = 0; nf < 16; nf++) {
            o[nf][0] *= c0; o[nf][1] *= c0; o[nf][2] *= c1; o[nf][3] *= c1;
        }

        // ---- O += P V (2 k16 steps x 3 split terms) ----
#pragma unroll
        for (int kk = 0; kk < 2; kk++) {
            float eh[8], el[8];
#pragma unroll
            for (int e = 0; e < 8; e++) {
                float p = (e < 4) ? s4[2*kk][e] : s4[2*kk+1][e-4];
                __nv_bfloat16 hb = __float2bfloat16(p);
                eh[e] = __bfloat162float(hb);
                el[e] = p - eh[e];
            }
            uint32_t aph[4] = {pkbf2(eh[0],eh[1]), pkbf2(eh[2],eh[3]),
                               pkbf2(eh[4],eh[5]), pkbf2(eh[6],eh[7])};
            uint32_t apl[4] = {pkbf2(el[0],el[1]), pkbf2(el[2],el[3]),
                               pkbf2(el[4],el[5]), pkbf2(el[6],el[7])};
            int r = kk*16 + (lane & 15);
#pragma unroll
            for (int nf = 0; nf < 16; nf++) {
                uint32_t voff = (uint32_t)((((r>>3)*16 + nf)*128) + (r&7)*16);
                uint32_t bvh[2], bvl[2];
                LDSM_X2T(bvh, st + ATS_V  + voff);
                LDSM_X2T(bvl, st + ATS_VL + voff);
                MMA16816(o[nf], aph, bvh);
                MMA16816(o[nf], aph, bvl);
                MMA16816(o[nf], apl, bvh);
            }
        }
        __syncthreads();   // all warps done with stage j before it's refilled
    }

    // ---- epilogue: normalize + split-store directly (feeds wo GEMM) ----
    const float i0 = 1.f / l0, i1 = 1.f / l1;
    const size_t t0 = (size_t)b*SEQ + rg0;
#pragma unroll
    for (int nf = 0; nf < 16; nf++) {
        int col = h*VD + nf*8 + (lane & 3)*2;
        size_t d0 = t0*(size_t)(NH*VD) + col;
        size_t d1 = (t0+8)*(size_t)(NH*VD) + col;
        split_store2(o[nf][0]*i0, o[nf][1]*i0, outh + d0, outl + d0);
        split_store2(o[nf][2]*i1, o[nf][3]*i1, outh + d1, outl + d1);
    }
}

// ---------------------------------- launch -----------------------------------
static inline void cvt(const float* s, __nv_bfloat16* h, __nv_bfloat16* l, size_t n) {
    int n4 = (int)(n / 4);
    cvt_hilo<<<(n4 + 255) / 256, 256>>>(s, h, l, n4);
}

extern "C" void kernel_launch(void* const* d_in, const int* in_sizes, int n_in,
                              void* d_out, int out_size)
{
    const float* x     = (const float*)d_in[0];
    const float* wq    = (const float*)d_in[1];
    const float* wkv_a = (const float*)d_in[2];
    const float* kvnw  = (const float*)d_in[3];
    const float* wkv_b = (const float*)d_in[4];
    const float* wo    = (const float*)d_in[5];
    const float* fcos  = (const float*)d_in[6];
    const float* fsin  = (const float*)d_in[7];
    float* out = (float*)d_out;

    float *kv;
    cudaGetSymbolAddress((void**)&kv, g_kv);

    __nv_bfloat16 *xh,*xl,*wqh,*wql,*wah,*wal,*wbh,*wbl,*woh,*wol,*kvch,*kvcl,*ath,*atl;
    __nv_bfloat16 *aqh,*aql,*akh,*akl,*avh,*avl;
    cudaGetSymbolAddress((void**)&xh,  g_xh);   cudaGetSymbolAddress((void**)&xl,  g_xl);
    cudaGetSymbolAddress((void**)&wqh, g_wqh);  cudaGetSymbolAddress((void**)&wql, g_wql);
    cudaGetSymbolAddress((void**)&wah, g_wah);  cudaGetSymbolAddress((void**)&wal, g_wal);
    cudaGetSymbolAddress((void**)&wbh, g_wbh);  cudaGetSymbolAddress((void**)&wbl, g_wbl);
    cudaGetSymbolAddress((void**)&woh, g_woh);  cudaGetSymbolAddress((void**)&wol, g_wol);
    cudaGetSymbolAddress((void**)&kvch,g_kvch); cudaGetSymbolAddress((void**)&kvcl,g_kvcl);
    cudaGetSymbolAddress((void**)&ath, g_ath);  cudaGetSymbolAddress((void**)&atl, g_atl);
    cudaGetSymbolAddress((void**)&aqh, g_aqh);  cudaGetSymbolAddress((void**)&aql, g_aql);
    cudaGetSymbolAddress((void**)&akh, g_akh);  cudaGetSymbolAddress((void**)&akl, g_akl);
    cudaGetSymbolAddress((void**)&avh, g_avh);  cudaGetSymbolAddress((void**)&avl, g_avl);

    double mm = 0.1 * 1.0 * log(40.0) + 1.0;
    float scale = (float)(mm * mm / sqrt((double)QKD));

    cudaFuncSetAttribute(gemm_mma<0>, cudaFuncAttributeMaxDynamicSharedMemorySize, GSMEM);
    cudaFuncSetAttribute(gemm_mma<1>, cudaFuncAttributeMaxDynamicSharedMemorySize, GSMEM);
    cudaFuncSetAttribute(gemm_mma<2>, cudaFuncAttributeMaxDynamicSharedMemorySize, GSMEM);
    cudaFuncSetAttribute(attn_mma, cudaFuncAttributeMaxDynamicSharedMemorySize, ATS_TOTAL);

    // split inputs / weights
    cvt(x,     xh,  xl,  (size_t)NTOK * DIM);
    cvt(wq,    wqh, wql, (size_t)NH*QKD * DIM);
    cvt(wkv_a, wah, wal, (size_t)(KV_LORA+ROPE_D) * DIM);
    cvt(wkv_b, wbh, wbl, (size_t)NH*(NOPE+VD) * KV_LORA);
    cvt(wo,    woh, wol, (size_t)DIM * NH*VD);

    // q = x @ wq^T -> scaled split Q in attention layout (no fp32 intermediate)
    gemm_mma<1><<<dim3(3072/128, 32), 256, GSMEM>>>(
        xh, xl, wqh, wql, nullptr, aqh, aql, nullptr, nullptr, scale,
        NTOK, NH*QKD, DIM);
    // kv = x @ wkv_a^T (fp32; prep consumes it)
    gemm_mma<0><<<dim3(5, 32), 256, GSMEM>>>(
        xh, xl, wah, wal, kv, nullptr, nullptr, nullptr, nullptr, 1.f,
        NTOK, KV_LORA+ROPE_D, DIM);
    // rmsnorm -> split kvc; rope -> split K[:,128:192] all heads (q NOT rotated)
    prep_kernel<<<NTOK, 256>>>(kv, kvnw, fcos, fsin, kvch, kvcl, akh, akl);
    // kvb = kvc @ wkv_b^T -> split K-nope / V in attention layouts
    gemm_mma<2><<<dim3(4096/128, 32), 256, GSMEM>>>(
        kvch, kvcl, wbh, wbl, nullptr, akh, akl, avh, avl, 1.f,
        NTOK, NH*(NOPE+VD), KV_LORA);
    // tensor-core flash attention -> split output (feeds wo GEMM directly)
    attn_mma<<<dim3(SEQ/128, NH, BATCH), 256, ATS_TOTAL>>>(
        aqh, aql, akh, akl, avh, avl, ath, atl);
    // out = attn @ wo^T
    gemm_mma<0><<<dim3(2048/128, 32), 256, GSMEM>>>(
        ath, atl, woh, wol, out, nullptr, nullptr, nullptr, nullptr, 1.f,
        NTOK, DIM, NH*VD);
}

// round 15
// speedup vs baseline: 2.8017x; 1.0100x over previous
#include <cuda_runtime.h>
#include <cuda_bf16.h>
#include <math.h>
#include <stdint.h>

#define DIM 2048
#define NH 16
#define KV_LORA 512
#define NOPE 128
#define ROPE_D 64
#define VD 128
#define QKD 192
#define BATCH 2
#define SEQ 2048
#define NTOK (BATCH*SEQ)

// ---------------- fp32 scratch ------------------------------------------------
__device__ float g_kv[(size_t)NTOK * (KV_LORA + ROPE_D)];

// ---------------- bf16 hi/lo scratch (GEMM operands) ---------------------------
__device__ __nv_bfloat16 g_xh[(size_t)NTOK * DIM],              g_xl[(size_t)NTOK * DIM];
__device__ __nv_bfloat16 g_wqh[(size_t)NH*QKD * DIM],           g_wql[(size_t)NH*QKD * DIM];
__device__ __nv_bfloat16 g_wah[(size_t)(KV_LORA+ROPE_D) * DIM], g_wal[(size_t)(KV_LORA+ROPE_D) * DIM];
__device__ __nv_bfloat16 g_wbh[(size_t)NH*(NOPE+VD) * KV_LORA], g_wbl[(size_t)NH*(NOPE+VD) * KV_LORA];
__device__ __nv_bfloat16 g_woh[(size_t)DIM * NH*VD],            g_wol[(size_t)DIM * NH*VD];
__device__ __nv_bfloat16 g_kvch[(size_t)NTOK * KV_LORA],        g_kvcl[(size_t)NTOK * KV_LORA];
__device__ __nv_bfloat16 g_ath[(size_t)NTOK * NH*VD],           g_atl[(size_t)NTOK * NH*VD];

// ---------------- bf16 hi/lo attention layouts [b][h][s][d] --------------------
__device__ __nv_bfloat16 g_aqh[(size_t)NTOK * NH * QKD], g_aql[(size_t)NTOK * NH * QKD];
__device__ __nv_bfloat16 g_akh[(size_t)NTOK * NH * QKD], g_akl[(size_t)NTOK * NH * QKD];
__device__ __nv_bfloat16 g_avh[(size_t)NTOK * NH * VD],  g_avl[(size_t)NTOK * NH * VD];

// ======================= PTX helpers (baseline sm_103) =========================
__device__ __forceinline__ uint32_t smem_u32(const void* p) {
    uint32_t a;
    asm("{ .reg .u64 t; cvta.to.shared.u64 t, %1; cvt.u32.u64 %0, t; }"
        : "=r"(a) : "l"(p));
    return a;
}
#define CP16(s, g, sz) \
    asm volatile("cp.async.cg.shared.global [%0], [%1], 16, %2;" \
                 :: "r"(s), "l"(g), "r"(sz) : "memory")
#define CP_COMMIT() asm volatile("cp.async.commit_group;" ::: "memory")
#define CP_WAIT1()  asm volatile("cp.async.wait_group 1;" ::: "memory")
#define CP_WAIT0()  asm volatile("cp.async.wait_group 0;" ::: "memory")

#define LDSM_X4(r, a) \
    asm volatile("ldmatrix.sync.aligned.m8n8.x4.shared.b16 {%0,%1,%2,%3}, [%4];" \
                 : "=r"((r)[0]), "=r"((r)[1]), "=r"((r)[2]), "=r"((r)[3]) : "r"(a))
#define LDSM_X4T(r, a) \
    asm volatile("ldmatrix.sync.aligned.m8n8.x4.trans.shared.b16 {%0,%1,%2,%3}, [%4];" \
                 : "=r"((r)[0]), "=r"((r)[1]), "=r"((r)[2]), "=r"((r)[3]) : "r"(a))
#define MMA16816(d, a, b) \
    asm volatile("mma.sync.aligned.m16n8k16.row.col.f32.bf16.bf16.f32 " \
                 "{%0,%1,%2,%3}, {%4,%5,%6,%7}, {%8,%9}, {%0,%1,%2,%3};" \
                 : "+f"((d)[0]), "+f"((d)[1]), "+f"((d)[2]), "+f"((d)[3]) \
                 : "r"((a)[0]), "r"((a)[1]), "r"((a)[2]), "r"((a)[3]), \
                   "r"((b)[0]), "r"((b)[1]))

__device__ __forceinline__ uint32_t pkbf2(float a, float b) {
    __nv_bfloat162 t = __floats2bfloat162_rn(a, b);
    return *reinterpret_cast<uint32_t*>(&t);
}
__device__ __forceinline__ void split_store2(float v0, float v1,
                                             __nv_bfloat16* ph, __nv_bfloat16* pl) {
    __nv_bfloat16 h0 = __float2bfloat16(v0), h1 = __float2bfloat16(v1);
    __nv_bfloat16 l0 = __float2bfloat16(v0 - __bfloat162float(h0));
    __nv_bfloat16 l1 = __float2bfloat16(v1 - __bfloat162float(h1));
    *reinterpret_cast<__nv_bfloat162*>(ph) = __halves2bfloat162(h0, h1);
    *reinterpret_cast<__nv_bfloat162*>(pl) = __halves2bfloat162(l0, l1);
}

// ---------------- fp32 -> (hi, lo) bf16 split ---------------------------------
__global__ void __launch_bounds__(256)
cvt_hilo(const float* __restrict__ s, __nv_bfloat16* __restrict__ h,
         __nv_bfloat16* __restrict__ l, int n4)
{
    int i = blockIdx.x * 256 + threadIdx.x;
    if (i >= n4) return;
    float4 v = reinterpret_cast<const float4*>(s)[i];
    __nv_bfloat16 h0 = __float2bfloat16(v.x), h1 = __float2bfloat16(v.y);
    __nv_bfloat16 h2 = __float2bfloat16(v.z), h3 = __float2bfloat16(v.w);
    __nv_bfloat16 l0 = __float2bfloat16(v.x - __bfloat162float(h0));
    __nv_bfloat16 l1 = __float2bfloat16(v.y - __bfloat162float(h1));
    __nv_bfloat16 l2 = __float2bfloat16(v.z - __bfloat162float(h2));
    __nv_bfloat16 l3 = __float2bfloat16(v.w - __bfloat162float(h3));
    reinterpret_cast<__nv_bfloat162*>(h)[2*i]   = __halves2bfloat162(h0, h1);
    reinterpret_cast<__nv_bfloat162*>(h)[2*i+1] = __halves2bfloat162(h2, h3);
    reinterpret_cast<__nv_bfloat162*>(l)[2*i]   = __halves2bfloat162(l0, l1);
    reinterpret_cast<__nv_bfloat162*>(l)[2*i+1] = __halves2bfloat162(l2, l3);
}

// ============ warp-MMA NT GEMM: C = A*B^T, split bf16 (3 HMMA terms) ==========
// MODE 0: fp32 C.  MODE 1: q epilogue.  MODE 2: kvb epilogue.
#define OFF_AH 0
#define OFF_AL 8192
#define OFF_BH 16384
#define OFF_BL 24576
#define STAGE_SZ 32768
#define GSMEM (2*STAGE_SZ)

template<int MODE>
__global__ void __launch_bounds__(256, 2)
gemm_mma(const __nv_bfloat16* __restrict__ Ah, const __nv_bfloat16* __restrict__ Al,
         const __nv_bfloat16* __restrict__ Bh, const __nv_bfloat16* __restrict__ Bl,
         float* __restrict__ C,
         __nv_bfloat16* __restrict__ P0, __nv_bfloat16* __restrict__ P1,
         __nv_bfloat16* __restrict__ P2, __nv_bfloat16* __restrict__ P3,
         float scale, int M, int N, int K)
{
    extern __shared__ char smraw[];
    const uint32_t sbase = smem_u32(smraw);
    const int tid  = threadIdx.x;
    const int lane = tid & 31, wid = tid >> 5;
    const int bm = blockIdx.y * 128, bn = blockIdx.x * 128;
    const int wm = (wid >> 2) * 64, wn = (wid & 3) * 32;

    float acc[4][4][4];
#pragma unroll
    for (int mt = 0; mt < 4; mt++)
#pragma unroll
        for (int nt = 0; nt < 4; nt++)
#pragma unroll
            for (int e = 0; e < 4; e++) acc[mt][nt][e] = 0.f;

    const int NS = K >> 5;
    const int arow = lane & 15, akbo = lane >> 4;

#define ISSUE_SLAB(st, kt) do {                                               \
    uint32_t _sb = sbase + (uint32_t)(st) * STAGE_SZ;                         \
    _Pragma("unroll")                                                         \
    for (int _i = 0; _i < 2; _i++) {                                          \
        int _idx = tid + _i * 256;                                            \
        int _row = _idx >> 2, _kb = _idx & 3;                                 \
        uint32_t _so = (uint32_t)((((_row >> 3) * 4 + _kb) * 128) + (_row & 7) * 16); \
        size_t _ga = (size_t)(bm + _row) * K + (kt) + _kb * 8;                \
        CP16(_sb + OFF_AH + _so, Ah + _ga, 16);                               \
        CP16(_sb + OFF_AL + _so, Al + _ga, 16);                               \
        int _nr = bn + _row;                                                  \
        int _ok = (_nr < N) ? 16 : 0;                                         \
        if (_nr >= N) _nr = 0;                                                \
        size_t _gb = (size_t)_nr * K + (kt) + _kb * 8;                        \
        CP16(_sb + OFF_BH + _so, Bh + _gb, _ok);                              \
        CP16(_sb + OFF_BL + _so, Bl + _gb, _ok);                              \
    } } while (0)

    ISSUE_SLAB(0, 0);
    CP_COMMIT();

    for (int s = 0; s < NS; s++) {
        const int cur = s & 1;
        if (s + 1 < NS) {
            ISSUE_SLAB((s + 1) & 1, (s + 1) * 32);
            CP_COMMIT();
            CP_WAIT1();
        } else {
            CP_WAIT0();
        }
        __syncthreads();

        const uint32_t sb = sbase + (uint32_t)cur * STAGE_SZ;
#pragma unroll
        for (int k16 = 0; k16 < 2; k16++) {
            // B fragments via paired ldmatrix.x4 (2 n-blocks per instruction)
            uint32_t bh[4][2], bl[4][2];
#pragma unroll
            for (int np = 0; np < 2; np++) {
                int nt = np*2 + (lane >> 4);
                int n  = wn + nt * 8 + (lane & 7);
                int kb = k16 * 2 + ((lane >> 3) & 1);
                uint32_t off = (uint32_t)((((n >> 3) * 4 + kb) * 128) + (n & 7) * 16);
                uint32_t r[4];
                LDSM_X4(r, sb + OFF_BH + off);
                bh[np*2][0]=r[0]; bh[np*2][1]=r[1];
                bh[np*2+1][0]=r[2]; bh[np*2+1][1]=r[3];
                LDSM_X4(r, sb + OFF_BL + off);
                bl[np*2][0]=r[0]; bl[np*2][1]=r[1];
                bl[np*2+1][0]=r[2]; bl[np*2+1][1]=r[3];
            }
#pragma unroll
            for (int mt = 0; mt < 4; mt++) {
                int r  = wm + mt * 16 + arow;
                int kb = k16 * 2 + akbo;
                uint32_t off = (uint32_t)((((r >> 3) * 4 + kb) * 128) + (r & 7) * 16);
                uint32_t ah[4], al[4];
                LDSM_X4(ah, sb + OFF_AH + off);
                LDSM_X4(al, sb + OFF_AL + off);
                // term-outer ordering: same-accumulator spacing = 4
#pragma unroll
                for (int nt = 0; nt < 4; nt++) MMA16816(acc[mt][nt], ah, bh[nt]);
#pragma unroll
                for (int nt = 0; nt < 4; nt++) MMA16816(acc[mt][nt], ah, bl[nt]);
#pragma unroll
                for (int nt = 0; nt < 4; nt++) MMA16816(acc[mt][nt], al, bh[nt]);
            }
        }
        __syncthreads();
    }

    const int erow = lane >> 2, ecol = (lane & 3) * 2;
#pragma unroll
    for (int mt = 0; mt < 4; mt++) {
#pragma unroll
        for (int nt = 0; nt < 4; nt++) {
            int col = bn + wn + nt * 8 + ecol;
            if (col >= N) continue;
            int r0 = bm + wm + mt * 16 + erow;
#pragma unroll
            for (int half = 0; half < 2; half++) {
                int row = r0 + half * 8;
                float v0 = acc[mt][nt][2*half+0], v1 = acc[mt][nt][2*half+1];
                if (MODE == 0) {
                    *reinterpret_cast<float2*>(C + (size_t)row * N + col) =
                        make_float2(v0, v1);
                } else if (MODE == 1) {
                    int h = col / QKD, d = col - h * QKD;
                    size_t dst = (((size_t)((row >> 11)*NH + h))*SEQ + (row & (SEQ-1)))*QKD + d;
                    split_store2(v0*scale, v1*scale, P0 + dst, P1 + dst);
                } else {
                    int h = col >> 8, d = col & 255;
                    size_t tb = ((size_t)((row >> 11)*NH + h))*SEQ + (row & (SEQ-1));
                    if (d < NOPE) {
                        size_t dst = tb*QKD + d;
                        split_store2(v0, v1, P0 + dst, P1 + dst);
                    } else {
                        size_t dst = tb*VD + (d - NOPE);
                        split_store2(v0, v1, P2 + dst, P3 + dst);
                    }
                }
            }
        }
    }
}

// ------------- prep: RMSNorm(kv_c) -> split, RoPE(k_pe) -> split K layout -----
// (q NOT rotated — reference rotates a copy and drops it)
__global__ void __launch_bounds__(256)
prep_kernel(const float* __restrict__ kv,
            const float* __restrict__ kvnw,
            const float* __restrict__ fcos, const float* __restrict__ fsin,
            __nv_bfloat16* __restrict__ kvch, __nv_bfloat16* __restrict__ kvcl,
            __nv_bfloat16* __restrict__ akh,  __nv_bfloat16* __restrict__ akl)
{
    const int token = blockIdx.x;
    const int b     = token >> 11;
    const int spos  = token & (SEQ - 1);
    const int tid   = threadIdx.x;
    __shared__ float red[256];
    __shared__ float rope[ROPE_D];

    const float* kvrow = kv + (size_t)token * (KV_LORA + ROPE_D);
    float ss = 0.f;
    for (int i = tid; i < KV_LORA; i += 256) { float v = kvrow[i]; ss += v*v; }
    red[tid] = ss;
    __syncthreads();
    for (int st = 128; st > 0; st >>= 1) {
        if (tid < st) red[tid] += red[tid + st];
        __syncthreads();
    }
    const float rms = rsqrtf(red[0] / (float)KV_LORA + 1e-6f);

    for (int i = tid; i < KV_LORA; i += 256) {
        float v = kvrow[i] * rms * kvnw[i];
        __nv_bfloat16 hb = __float2bfloat16(v);
        kvch[(size_t)token * KV_LORA + i] = hb;
        kvcl[(size_t)token * KV_LORA + i] = __float2bfloat16(v - __bfloat162float(hb));
    }

    if (tid < 32) {
        float re = kvrow[KV_LORA + 2*tid], im = kvrow[KV_LORA + 2*tid + 1];
        float c = fcos[spos*32 + tid], s = fsin[spos*32 + tid];
        rope[2*tid]     = re*c - im*s;
        rope[2*tid + 1] = re*s + im*c;
    }
    __syncthreads();

    for (int i = tid; i < NH * ROPE_D; i += 256) {
        int h = i >> 6, d = i & 63;
        float v = rope[d];
        __nv_bfloat16 hb = __float2bfloat16(v);
        size_t dst = (((size_t)(b*NH + h))*SEQ + spos)*QKD + NOPE + d;
        akh[dst] = hb;
        akl[dst] = __float2bfloat16(v - __bfloat162float(hb));
    }
}

// ===================== tensor-core flash attention =============================
#define ATS_Q   0
#define ATS_QL  49152
#define ATS_ST  98304
#define ATS_K   0
#define ATS_KL  12288
#define ATS_V   24576
#define ATS_VL  32768
#define ATS_STAGE 40960
#define ATS_TOTAL (98304 + 2*ATS_STAGE)   // 180224

__global__ void __launch_bounds__(256, 1)
attn_mma(const __nv_bfloat16* __restrict__ qh_, const __nv_bfloat16* __restrict__ ql_,
         const __nv_bfloat16* __restrict__ kh_, const __nv_bfloat16* __restrict__ kl_,
         const __nv_bfloat16* __restrict__ vh_, const __nv_bfloat16* __restrict__ vl_,
         __nv_bfloat16* __restrict__ outh, __nv_bfloat16* __restrict__ outl)
{
    extern __shared__ char sm[];
    const uint32_t sb = smem_u32(sm);
    const int tid = threadIdx.x, lane = tid & 31, w = tid >> 5;
    const int qi = (int)gridDim.x - 1 - (int)blockIdx.x;   // heavy tiles first
    const int h = blockIdx.y, b = blockIdx.z;
    const int qb = qi * 128;
    const size_t hoff = ((size_t)(b*NH + h)) * SEQ;
    const __nv_bfloat16* qh = qh_ + (hoff + qb) * QKD;
    const __nv_bfloat16* ql = ql_ + (hoff + qb) * QKD;
    const __nv_bfloat16* kh = kh_ + hoff * QKD;
    const __nv_bfloat16* kl = kl_ + hoff * QKD;
    const __nv_bfloat16* vh = vh_ + hoff * VD;
    const __nv_bfloat16* vl = vl_ + hoff * VD;
    const int NCH = 4*qi + 4;

#define AT_ISSUE(st, jj) do {                                                 \
    uint32_t _s = sb + ATS_ST + (uint32_t)(st) * ATS_STAGE;                   \
    int _p = tid >> 3, _c = tid & 7;                                          \
    _Pragma("unroll")                                                         \
    for (int _it = 0; _it < 3; _it++) {                                       \
        int _kb = _c + _it*8;                                                 \
        uint32_t _o = (uint32_t)((((_p>>3)*24 + _kb)*128) + (_p&7)*16);       \
        size_t _g = ((size_t)(jj)*32 + _p)*QKD + _kb*8;                       \
        CP16(_s + ATS_K  + _o, kh + _g, 16);                                  \
        CP16(_s + ATS_KL + _o, kl + _g, 16);                                  \
    }                                                                         \
    _Pragma("unroll")                                                         \
    for (int _it = 0; _it < 2; _it++) {                                       \
        int _cb = _c + _it*8;                                                 \
        uint32_t _o = (uint32_t)((((_p>>3)*16 + _cb)*128) + (_p&7)*16);       \
        size_t _g = ((size_t)(jj)*32 + _p)*VD + _cb*8;                        \
        CP16(_s + ATS_V  + _o, vh + _g, 16);                                  \
        CP16(_s + ATS_VL + _o, vl + _g, 16);                                  \
    } } while (0)

    AT_ISSUE(0, 0);
    CP_COMMIT();

    // Q resident load (plain; covered by first-loop barrier)
    {
        int m = tid >> 1;
#pragma unroll
        for (int it = 0; it < 12; it++) {
            int kb = (tid & 1) + it*2;
            uint32_t so = (uint32_t)((((m>>3)*24 + kb)*128) + (m&7)*16);
            *reinterpret_cast<uint4*>(sm + ATS_Q + so) =
                *reinterpret_cast<const uint4*>(qh + (size_t)m*QKD + kb*8);
            *reinterpret_cast<uint4*>(sm + ATS_QL + so) =
                *reinterpret_cast<const uint4*>(ql + (size_t)m*QKD + kb*8);
        }
    }

    float o[16][4];
#pragma unroll
    for (int nf = 0; nf < 16; nf++)
#pragma unroll
        for (int e = 0; e < 4; e++) o[nf][e] = 0.f;
    float m0 = -1e30f, m1 = -1e30f, l0 = 0.f, l1 = 0.f;

    const int rg0 = qb + w*16 + (lane >> 2);
    const int rg1 = rg0 + 8;

    for (int j = 0; j < NCH; j++) {
        if (j + 1 < NCH) { AT_ISSUE((j+1)&1, j+1); CP_COMMIT(); CP_WAIT1(); }
        else             { CP_WAIT0(); }
        __syncthreads();
        const uint32_t st = sb + ATS_ST + (uint32_t)(j & 1) * ATS_STAGE;

        // ---- S = Q K^T: split accumulators + term-outer ordering ----
        float s4h[4][4], s4l[4][4];
#pragma unroll
        for (int nf = 0; nf < 4; nf++)
#pragma unroll
            for (int e = 0; e < 4; e++) { s4h[nf][e] = 0.f; s4l[nf][e] = 0.f; }

#pragma unroll
        for (int kk = 0; kk < 12; kk++) {
            // K fragments via paired x4 (2 n-blocks each)
            uint32_t bkh[4][2], bkl[4][2];
            int bn_ = lane & 7;
            int bkb = kk*2 + ((lane >> 3) & 1);
#pragma unroll
            for (int np = 0; np < 2; np++) {
                int nf = np*2 + (lane >> 4);
                int n = nf*8 + bn_;
                uint32_t boff = (uint32_t)((((n>>3)*24 + bkb)*128) + (n&7)*16);
                uint32_t r[4];
                LDSM_X4(r, st + ATS_K + boff);
                bkh[np*2][0]=r[0]; bkh[np*2][1]=r[1];
                bkh[np*2+1][0]=r[2]; bkh[np*2+1][1]=r[3];
                LDSM_X4(r, st + ATS_KL + boff);
                bkl[np*2][0]=r[0]; bkl[np*2][1]=r[1];
                bkl[np*2+1][0]=r[2]; bkl[np*2+1][1]=r[3];
            }
            int am = w*16 + (lane & 15);
            int akb = kk*2 + (lane >> 4);
            uint32_t aoff = (uint32_t)((((am>>3)*24 + akb)*128) + (am&7)*16);
            uint32_t aqh[4], aql[4];
            LDSM_X4(aqh, sb + ATS_Q  + aoff);
            LDSM_X4(aql, sb + ATS_QL + aoff);
#pragma unroll
            for (int nf = 0; nf < 4; nf++) MMA16816(s4h[nf], aqh, bkh[nf]);
#pragma unroll
            for (int nf = 0; nf < 4; nf++) MMA16816(s4l[nf], aqh, bkl[nf]);
#pragma unroll
            for (int nf = 0; nf < 4; nf++) MMA16816(s4l[nf], aql, bkh[nf]);
        }
        // combine split accumulators
        float s4[4][4];
#pragma unroll
        for (int nf = 0; nf < 4; nf++)
#pragma unroll
            for (int e = 0; e < 4; e++) s4[nf][e] = s4h[nf][e] + s4l[nf][e];

        // ---- causal mask (diagonal band chunks only) ----
        if (j >= 4*qi) {
            int cb = j*32 + (lane & 3)*2;
#pragma unroll
            for (int nf = 0; nf < 4; nf++) {
                int c = cb + nf*8;
                if (c     > rg0) s4[nf][0] = -1e30f;
                if (c + 1 > rg0) s4[nf][1] = -1e30f;
                if (c     > rg1) s4[nf][2] = -1e30f;
                if (c + 1 > rg1) s4[nf][3] = -1e30f;
            }
        }

        // ---- online softmax in registers ----
        float mx0 = -1e30f, mx1 = -1e30f;
#pragma unroll
        for (int nf = 0; nf < 4; nf++) {
            mx0 = fmaxf(mx0, fmaxf(s4[nf][0], s4[nf][1]));
            mx1 = fmaxf(mx1, fmaxf(s4[nf][2], s4[nf][3]));
        }
        mx0 = fmaxf(mx0, __shfl_xor_sync(0xffffffffu, mx0, 1));
        mx0 = fmaxf(mx0, __shfl_xor_sync(0xffffffffu, mx0, 2));
        mx1 = fmaxf(mx1, __shfl_xor_sync(0xffffffffu, mx1, 1));
        mx1 = fmaxf(mx1, __shfl_xor_sync(0xffffffffu, mx1, 2));
        float mn0 = fmaxf(m0, mx0), mn1 = fmaxf(m1, mx1);
        float c0 = __expf(m0 - mn0), c1 = __expf(m1 - mn1);
        m0 = mn0; m1 = mn1;
        float sum0 = 0.f, sum1 = 0.f;
#pragma unroll
        for (int nf = 0; nf < 4; nf++) {
            s4[nf][0] = __expf(s4[nf][0] - mn0);
            s4[nf][1] = __expf(s4[nf][1] - mn0);
            s4[nf][2] = __expf(s4[nf][2] - mn1);
            s4[nf][3] = __expf(s4[nf][3] - mn1);
            sum0 += s4[nf][0] + s4[nf][1];
            sum1 += s4[nf][2] + s4[nf][3];
        }
        sum0 += __shfl_xor_sync(0xffffffffu, sum0, 1);
        sum0 += __shfl_xor_sync(0xffffffffu, sum0, 2);
        sum1 += __shfl_xor_sync(0xffffffffu, sum1, 1);
        sum1 += __shfl_xor_sync(0xffffffffu, sum1, 2);
        l0 = l0*c0 + sum0;
        l1 = l1*c1 + sum1;
#pragma unroll
        for (int nf = 0; nf < 16; nf++) {
            o[nf][0] *= c0; o[nf][1] *= c0; o[nf][2] *= c1; o[nf][3] *= c1;
        }

        // ---- O += P V (x4 trans loads, paired n-blocks) ----
#pragma unroll
        for (int kk = 0; kk < 2; kk++) {
            float eh[8], el[8];
#pragma unroll
            for (int e = 0; e < 8; e++) {
                float p = (e < 4) ? s4[2*kk][e] : s4[2*kk+1][e-4];
                __nv_bfloat16 hb = __float2bfloat16(p);
                eh[e] = __bfloat162float(hb);
                el[e] = p - eh[e];
            }
            uint32_t aph[4] = {pkbf2(eh[0],eh[1]), pkbf2(eh[2],eh[3]),
                               pkbf2(eh[4],eh[5]), pkbf2(eh[6],eh[7])};
            uint32_t apl[4] = {pkbf2(el[0],el[1]), pkbf2(el[2],el[3]),
                               pkbf2(el[4],el[5]), pkbf2(el[6],el[7])};
            int r = kk*16 + (lane & 15);
#pragma unroll
            for (int np = 0; np < 8; np++) {
                int nf = np*2 + (lane >> 4);
                uint32_t voff = (uint32_t)((((r>>3)*16 + nf)*128) + (r&7)*16);
                uint32_t rh[4], rl[4];
                LDSM_X4T(rh, st + ATS_V  + voff);
                LDSM_X4T(rl, st + ATS_VL + voff);
                // interleave the two accumulators of this pair
                MMA16816(o[np*2],   aph, rh);
                MMA16816(o[np*2+1], aph, rh+2);
                MMA16816(o[np*2],   aph, rl);
                MMA16816(o[np*2+1], aph, rl+2);
                MMA16816(o[np*2],   apl, rh);
                MMA16816(o[np*2+1], apl, rh+2);
            }
        }
        __syncthreads();   // all warps done with stage j before it's refilled
    }

    // ---- epilogue: normalize + split-store directly (feeds wo GEMM) ----
    const float i0 = 1.f / l0, i1 = 1.f / l1;
    const size_t t0 = (size_t)b*SEQ + rg0;
#pragma unroll
    for (int nf = 0; nf < 16; nf++) {
        int col = h*VD + nf*8 + (lane & 3)*2;
        size_t d0 = t0*(size_t)(NH*VD) + col;
        size_t d1 = (t0+8)*(size_t)(NH*VD) + col;
        split_store2(o[nf][0]*i0, o[nf][1]*i0, outh + d0, outl + d0);
        split_store2(o[nf][2]*i1, o[nf][3]*i1, outh + d1, outl + d1);
    }
}

// ---------------------------------- launch -----------------------------------
static inline void cvt(const float* s, __nv_bfloat16* h, __nv_bfloat16* l, size_t n) {
    int n4 = (int)(n / 4);
    cvt_hilo<<<(n4 + 255) / 256, 256>>>(s, h, l, n4);
}

extern "C" void kernel_launch(void* const* d_in, const int* in_sizes, int n_in,
                              void* d_out, int out_size)
{
    const float* x     = (const float*)d_in[0];
    const float* wq    = (const float*)d_in[1];
    const float* wkv_a = (const float*)d_in[2];
    const float* kvnw  = (const float*)d_in[3];
    const float* wkv_b = (const float*)d_in[4];
    const float* wo    = (const float*)d_in[5];
    const float* fcos  = (const float*)d_in[6];
    const float* fsin  = (const float*)d_in[7];
    float* out = (float*)d_out;

    float *kv;
    cudaGetSymbolAddress((void**)&kv, g_kv);

    __nv_bfloat16 *xh,*xl,*wqh,*wql,*wah,*wal,*wbh,*wbl,*woh,*wol,*kvch,*kvcl,*ath,*atl;
    __nv_bfloat16 *aqh,*aql,*akh,*akl,*avh,*avl;
    cudaGetSymbolAddress((void**)&xh,  g_xh);   cudaGetSymbolAddress((void**)&xl,  g_xl);
    cudaGetSymbolAddress((void**)&wqh, g_wqh);  cudaGetSymbolAddress((void**)&wql, g_wql);
    cudaGetSymbolAddress((void**)&wah, g_wah);  cudaGetSymbolAddress((void**)&wal, g_wal);
    cudaGetSymbolAddress((void**)&wbh, g_wbh);  cudaGetSymbolAddress((void**)&wbl, g_wbl);
    cudaGetSymbolAddress((void**)&woh, g_woh);  cudaGetSymbolAddress((void**)&wol, g_wol);
    cudaGetSymbolAddress((void**)&kvch,g_kvch); cudaGetSymbolAddress((void**)&kvcl,g_kvcl);
    cudaGetSymbolAddress((void**)&ath, g_ath);  cudaGetSymbolAddress((void**)&atl, g_atl);
    cudaGetSymbolAddress((void**)&aqh, g_aqh);  cudaGetSymbolAddress((void**)&aql, g_aql);
    cudaGetSymbolAddress((void**)&akh, g_akh);  cudaGetSymbolAddress((void**)&akl, g_akl);
    cudaGetSymbolAddress((void**)&avh, g_avh);  cudaGetSymbolAddress((void**)&avl, g_avl);

    double mm = 0.1 * 1.0 * log(40.0) + 1.0;
    float scale = (float)(mm * mm / sqrt((double)QKD));

    cudaFuncSetAttribute(gemm_mma<0>, cudaFuncAttributeMaxDynamicSharedMemorySize, GSMEM);
    cudaFuncSetAttribute(gemm_mma<1>, cudaFuncAttributeMaxDynamicSharedMemorySize, GSMEM);
    cudaFuncSetAttribute(gemm_mma<2>, cudaFuncAttributeMaxDynamicSharedMemorySize, GSMEM);
    cudaFuncSetAttribute(attn_mma, cudaFuncAttributeMaxDynamicSharedMemorySize, ATS_TOTAL);

    // split inputs / weights
    cvt(x,     xh,  xl,  (size_t)NTOK * DIM);
    cvt(wq,    wqh, wql, (size_t)NH*QKD * DIM);
    cvt(wkv_a, wah, wal, (size_t)(KV_LORA+ROPE_D) * DIM);
    cvt(wkv_b, wbh, wbl, (size_t)NH*(NOPE+VD) * KV_LORA);
    cvt(wo,    woh, wol, (size_t)DIM * NH*VD);

    // q = x @ wq^T -> scaled split Q in attention layout
    gemm_mma<1><<<dim3(3072/128, 32), 256, GSMEM>>>(
        xh, xl, wqh, wql, nullptr, aqh, aql, nullptr, nullptr, scale,
        NTOK, NH*QKD, DIM);
    // kv = x @ wkv_a^T (fp32; prep consumes it)
    gemm_mma<0><<<dim3(5, 32), 256, GSMEM>>>(
        xh, xl, wah, wal, kv, nullptr, nullptr, nullptr, nullptr, 1.f,
        NTOK, KV_LORA+ROPE_D, DIM);
    // rmsnorm -> split kvc; rope -> split K[:,128:192] all heads (q NOT rotated)
    prep_kernel<<<NTOK, 256>>>(kv, kvnw, fcos, fsin, kvch, kvcl, akh, akl);
    // kvb = kvc @ wkv_b^T -> split K-nope / V in attention layouts
    gemm_mma<2><<<dim3(4096/128, 32), 256, GSMEM>>>(
        kvch, kvcl, wbh, wbl, nullptr, akh, akl, avh, avl, 1.f,
        NTOK, NH*(NOPE+VD), KV_LORA);
    // tensor-core flash attention -> split output (feeds wo GEMM directly)
    attn_mma<<<dim3(SEQ/128, NH, BATCH), 256, ATS_TOTAL>>>(
        aqh, aql, akh, akl, avh, avl, ath, atl);
    // out = attn @ wo^T
    gemm_mma<0><<<dim3(2048/128, 32), 256, GSMEM>>>(
        ath, atl, woh, wol, out, nullptr, nullptr, nullptr, nullptr, 1.f,
        NTOK, DIM, NH*VD);
}

// round 16
// speedup vs baseline: 2.8111x; 1.0033x over previous
#include <cuda_runtime.h>
#include <cuda_bf16.h>
#include <math.h>
#include <stdint.h>

#define DIM 2048
#define NH 16
#define KV_LORA 512
#define NOPE 128
#define ROPE_D 64
#define VD 128
#define QKD 192
#define BATCH 2
#define SEQ 2048
#define NTOK (BATCH*SEQ)

// ---------------- fp32 scratch ------------------------------------------------
__device__ float g_kv[(size_t)NTOK * (KV_LORA + ROPE_D)];

// ---------------- bf16 hi/lo scratch (GEMM operands) ---------------------------
__device__ __nv_bfloat16 g_xh[(size_t)NTOK * DIM],              g_xl[(size_t)NTOK * DIM];
__device__ __nv_bfloat16 g_wqh[(size_t)NH*QKD * DIM],           g_wql[(size_t)NH*QKD * DIM];
__device__ __nv_bfloat16 g_wah[(size_t)(KV_LORA+ROPE_D) * DIM], g_wal[(size_t)(KV_LORA+ROPE_D) * DIM];
__device__ __nv_bfloat16 g_wbh[(size_t)NH*(NOPE+VD) * KV_LORA], g_wbl[(size_t)NH*(NOPE+VD) * KV_LORA];
__device__ __nv_bfloat16 g_woh[(size_t)DIM * NH*VD],            g_wol[(size_t)DIM * NH*VD];
__device__ __nv_bfloat16 g_kvch[(size_t)NTOK * KV_LORA],        g_kvcl[(size_t)NTOK * KV_LORA];
__device__ __nv_bfloat16 g_ath[(size_t)NTOK * NH*VD],           g_atl[(size_t)NTOK * NH*VD];

// ---------------- bf16 hi/lo attention layouts [b][h][s][d] --------------------
__device__ __nv_bfloat16 g_aqh[(size_t)NTOK * NH * QKD], g_aql[(size_t)NTOK * NH * QKD];
__device__ __nv_bfloat16 g_akh[(size_t)NTOK * NH * QKD], g_akl[(size_t)NTOK * NH * QKD];
__device__ __nv_bfloat16 g_avh[(size_t)NTOK * NH * VD],  g_avl[(size_t)NTOK * NH * VD];

// ======================= PTX helpers (baseline sm_103) =========================
__device__ __forceinline__ uint32_t smem_u32(const void* p) {
    uint32_t a;
    asm("{ .reg .u64 t; cvta.to.shared.u64 t, %1; cvt.u32.u64 %0, t; }"
        : "=r"(a) : "l"(p));
    return a;
}
#define CP16(s, g, sz) \
    asm volatile("cp.async.cg.shared.global [%0], [%1], 16, %2;" \
                 :: "r"(s), "l"(g), "r"(sz) : "memory")
#define CP_COMMIT() asm volatile("cp.async.commit_group;" ::: "memory")
#define CP_WAIT1()  asm volatile("cp.async.wait_group 1;" ::: "memory")
#define CP_WAIT0()  asm volatile("cp.async.wait_group 0;" ::: "memory")

#define LDSM_X4(r, a) \
    asm volatile("ldmatrix.sync.aligned.m8n8.x4.shared.b16 {%0,%1,%2,%3}, [%4];" \
                 : "=r"((r)[0]), "=r"((r)[1]), "=r"((r)[2]), "=r"((r)[3]) : "r"(a))
#define LDSM_X4T(r, a) \
    asm volatile("ldmatrix.sync.aligned.m8n8.x4.trans.shared.b16 {%0,%1,%2,%3}, [%4];" \
                 : "=r"((r)[0]), "=r"((r)[1]), "=r"((r)[2]), "=r"((r)[3]) : "r"(a))
#define MMA16816(d, a, b) \
    asm volatile("mma.sync.aligned.m16n8k16.row.col.f32.bf16.bf16.f32 " \
                 "{%0,%1,%2,%3}, {%4,%5,%6,%7}, {%8,%9}, {%0,%1,%2,%3};" \
                 : "+f"((d)[0]), "+f"((d)[1]), "+f"((d)[2]), "+f"((d)[3]) \
                 : "r"((a)[0]), "r"((a)[1]), "r"((a)[2]), "r"((a)[3]), \
                   "r"((b)[0]), "r"((b)[1]))

__device__ __forceinline__ uint32_t pkbf2(float a, float b) {
    __nv_bfloat162 t = __floats2bfloat162_rn(a, b);
    return *reinterpret_cast<uint32_t*>(&t);
}
__device__ __forceinline__ void split_store2(float v0, float v1,
                                             __nv_bfloat16* ph, __nv_bfloat16* pl) {
    __nv_bfloat16 h0 = __float2bfloat16(v0), h1 = __float2bfloat16(v1);
    __nv_bfloat16 l0 = __float2bfloat16(v0 - __bfloat162float(h0));
    __nv_bfloat16 l1 = __float2bfloat16(v1 - __bfloat162float(h1));
    *reinterpret_cast<__nv_bfloat162*>(ph) = __halves2bfloat162(h0, h1);
    *reinterpret_cast<__nv_bfloat162*>(pl) = __halves2bfloat162(l0, l1);
}

// ---------------- fused fp32 -> (hi, lo) split for all 5 tensors --------------
__global__ void __launch_bounds__(256)
cvt_all(const float* __restrict__ s0, __nv_bfloat16* __restrict__ h0, __nv_bfloat16* __restrict__ l0, int e0,
        const float* __restrict__ s1, __nv_bfloat16* __restrict__ h1, __nv_bfloat16* __restrict__ l1, int e1,
        const float* __restrict__ s2, __nv_bfloat16* __restrict__ h2, __nv_bfloat16* __restrict__ l2, int e2,
        const float* __restrict__ s3, __nv_bfloat16* __restrict__ h3, __nv_bfloat16* __restrict__ l3, int e3,
        const float* __restrict__ s4, __nv_bfloat16* __restrict__ h4, __nv_bfloat16* __restrict__ l4, int e4)
{
    int blk = blockIdx.x;
    const float* s; __nv_bfloat16 *h, *l; int base;
    if      (blk < e0) { s = s0; h = h0; l = l0; base = 0;  }
    else if (blk < e1) { s = s1; h = h1; l = l1; base = e0; }
    else if (blk < e2) { s = s2; h = h2; l = l2; base = e1; }
    else if (blk < e3) { s = s3; h = h3; l = l3; base = e2; }
    else               { s = s4; h = h4; l = l4; base = e3; }
    int i = (blk - base) * 256 + threadIdx.x;   // all sizes are exact multiples
    float4 v = reinterpret_cast<const float4*>(s)[i];
    __nv_bfloat16 a0 = __float2bfloat16(v.x), a1 = __float2bfloat16(v.y);
    __nv_bfloat16 a2 = __float2bfloat16(v.z), a3 = __float2bfloat16(v.w);
    __nv_bfloat16 b0 = __float2bfloat16(v.x - __bfloat162float(a0));
    __nv_bfloat16 b1 = __float2bfloat16(v.y - __bfloat162float(a1));
    __nv_bfloat16 b2 = __float2bfloat16(v.z - __bfloat162float(a2));
    __nv_bfloat16 b3 = __float2bfloat16(v.w - __bfloat162float(a3));
    reinterpret_cast<__nv_bfloat162*>(h)[2*i]   = __halves2bfloat162(a0, a1);
    reinterpret_cast<__nv_bfloat162*>(h)[2*i+1] = __halves2bfloat162(a2, a3);
    reinterpret_cast<__nv_bfloat162*>(l)[2*i]   = __halves2bfloat162(b0, b1);
    reinterpret_cast<__nv_bfloat162*>(l)[2*i+1] = __halves2bfloat162(b2, b3);
}

// =========== small NT GEMM (128x128 tile) — used for kv (N=576) ===============
#define OFF_AH 0
#define OFF_AL 8192
#define OFF_BH 16384
#define OFF_BL 24576
#define STAGE_SZ 32768
#define GSMEM (2*STAGE_SZ)

template<int MODE>
__global__ void __launch_bounds__(256, 2)
gemm_sm(const __nv_bfloat16* __restrict__ Ah, const __nv_bfloat16* __restrict__ Al,
        const __nv_bfloat16* __restrict__ Bh, const __nv_bfloat16* __restrict__ Bl,
        float* __restrict__ C, float scale, int M, int N, int K)
{
    extern __shared__ char smraw[];
    const uint32_t sbase = smem_u32(smraw);
    const int tid  = threadIdx.x;
    const int lane = tid & 31, wid = tid >> 5;
    const int bm = blockIdx.y * 128, bn = blockIdx.x * 128;
    const int wm = (wid >> 2) * 64, wn = (wid & 3) * 32;

    float acc[4][4][4];
#pragma unroll
    for (int mt = 0; mt < 4; mt++)
#pragma unroll
        for (int nt = 0; nt < 4; nt++)
#pragma unroll
            for (int e = 0; e < 4; e++) acc[mt][nt][e] = 0.f;

    const int NS = K >> 5;
    const int arow = lane & 15, akbo = lane >> 4;

#define S_ISSUE(st, kt) do {                                                  \
    uint32_t _sb = sbase + (uint32_t)(st) * STAGE_SZ;                         \
    _Pragma("unroll")                                                         \
    for (int _i = 0; _i < 2; _i++) {                                          \
        int _idx = tid + _i * 256;                                            \
        int _row = _idx >> 2, _kb = _idx & 3;                                 \
        uint32_t _so = (uint32_t)((((_row >> 3) * 4 + _kb) * 128) + (_row & 7) * 16); \
        size_t _ga = (size_t)(bm + _row) * K + (kt) + _kb * 8;                \
        CP16(_sb + OFF_AH + _so, Ah + _ga, 16);                               \
        CP16(_sb + OFF_AL + _so, Al + _ga, 16);                               \
        int _nr = bn + _row;                                                  \
        int _ok = (_nr < N) ? 16 : 0;                                         \
        if (_nr >= N) _nr = 0;                                                \
        size_t _gb = (size_t)_nr * K + (kt) + _kb * 8;                        \
        CP16(_sb + OFF_BH + _so, Bh + _gb, _ok);                              \
        CP16(_sb + OFF_BL + _so, Bl + _gb, _ok);                              \
    } } while (0)

    S_ISSUE(0, 0);
    CP_COMMIT();

    for (int s = 0; s < NS; s++) {
        const int cur = s & 1;
        if (s + 1 < NS) { S_ISSUE((s + 1) & 1, (s + 1) * 32); CP_COMMIT(); CP_WAIT1(); }
        else            { CP_WAIT0(); }
        __syncthreads();

        const uint32_t sb = sbase + (uint32_t)cur * STAGE_SZ;
#pragma unroll
        for (int k16 = 0; k16 < 2; k16++) {
            uint32_t bh[4][2], bl[4][2];
#pragma unroll
            for (int np = 0; np < 2; np++) {
                int nt = np*2 + (lane >> 4);
                int n  = wn + nt * 8 + (lane & 7);
                int kb = k16 * 2 + ((lane >> 3) & 1);
                uint32_t off = (uint32_t)((((n >> 3) * 4 + kb) * 128) + (n & 7) * 16);
                uint32_t r[4];
                LDSM_X4(r, sb + OFF_BH + off);
                bh[np*2][0]=r[0]; bh[np*2][1]=r[1];
                bh[np*2+1][0]=r[2]; bh[np*2+1][1]=r[3];
                LDSM_X4(r, sb + OFF_BL + off);
                bl[np*2][0]=r[0]; bl[np*2][1]=r[1];
                bl[np*2+1][0]=r[2]; bl[np*2+1][1]=r[3];
            }
#pragma unroll
            for (int mt = 0; mt < 4; mt++) {
                int r  = wm + mt * 16 + arow;
                int kb = k16 * 2 + akbo;
                uint32_t off = (uint32_t)((((r >> 3) * 4 + kb) * 128) + (r & 7) * 16);
                uint32_t ah[4], al[4];
                LDSM_X4(ah, sb + OFF_AH + off);
                LDSM_X4(al, sb + OFF_AL + off);
#pragma unroll
                for (int nt = 0; nt < 4; nt++) MMA16816(acc[mt][nt], ah, bh[nt]);
#pragma unroll
                for (int nt = 0; nt < 4; nt++) MMA16816(acc[mt][nt], ah, bl[nt]);
#pragma unroll
                for (int nt = 0; nt < 4; nt++) MMA16816(acc[mt][nt], al, bh[nt]);
            }
        }
        __syncthreads();
    }

    const int erow = lane >> 2, ecol = (lane & 3) * 2;
#pragma unroll
    for (int mt = 0; mt < 4; mt++) {
#pragma unroll
        for (int nt = 0; nt < 4; nt++) {
            int col = bn + wn + nt * 8 + ecol;
            if (col >= N) continue;
            int r0 = bm + wm + mt * 16 + erow;
            *reinterpret_cast<float2*>(C + (size_t)r0 * N + col) =
                make_float2(acc[mt][nt][0], acc[mt][nt][1]);
            *reinterpret_cast<float2*>(C + (size_t)(r0 + 8) * N + col) =
                make_float2(acc[mt][nt][2], acc[mt][nt][3]);
        }
    }
}

// ====== big NT GEMM: 256x128 CTA tile, 64x64 warp tile (85 B smem / MMA) ======
// Requires M % 256 == 0 and N % 128 == 0.
// MODE 0: fp32 C.  MODE 1: q epilogue.  MODE 2: kvb epilogue.
#define BOFF_AH 0
#define BOFF_AL 16384
#define BOFF_BH 32768
#define BOFF_BL 40960
#define BSTAGE  49152
#define BSMEM   (2*BSTAGE)   // 98304

template<int MODE>
__global__ void __launch_bounds__(256, 1)
gemm_big(const __nv_bfloat16* __restrict__ Ah, const __nv_bfloat16* __restrict__ Al,
         const __nv_bfloat16* __restrict__ Bh, const __nv_bfloat16* __restrict__ Bl,
         float* __restrict__ C,
         __nv_bfloat16* __restrict__ P0, __nv_bfloat16* __restrict__ P1,
         __nv_bfloat16* __restrict__ P2, __nv_bfloat16* __restrict__ P3,
         float scale, int M, int N, int K)
{
    extern __shared__ char smraw[];
    const uint32_t sbase = smem_u32(smraw);
    const int tid  = threadIdx.x;
    const int lane = tid & 31, wid = tid >> 5;
    const int bm = blockIdx.y * 256, bn = blockIdx.x * 128;
    const int wm = (wid >> 1) * 64, wn = (wid & 1) * 64;   // 4 m-warps x 2 n-warps

    float acc[4][8][4];
#pragma unroll
    for (int mt = 0; mt < 4; mt++)
#pragma unroll
        for (int nt = 0; nt < 8; nt++)
#pragma unroll
            for (int e = 0; e < 4; e++) acc[mt][nt][e] = 0.f;

    const int NS = K >> 5;
    const int arow = lane & 15, akbo = lane >> 4;

#define B_ISSUE(st, kt) do {                                                  \
    uint32_t _sb = sbase + (uint32_t)(st) * BSTAGE;                           \
    _Pragma("unroll")                                                         \
    for (int _i = 0; _i < 4; _i++) {      /* A: 256 rows */                   \
        int _idx = tid + _i * 256;                                            \
        int _row = _idx >> 2, _kb = _idx & 3;                                 \
        uint32_t _so = (uint32_t)((((_row >> 3) * 4 + _kb) * 128) + (_row & 7) * 16); \
        size_t _ga = (size_t)(bm + _row) * K + (kt) + _kb * 8;                \
        CP16(_sb + BOFF_AH + _so, Ah + _ga, 16);                              \
        CP16(_sb + BOFF_AL + _so, Al + _ga, 16);                              \
    }                                                                         \
    _Pragma("unroll")                                                         \
    for (int _i = 0; _i < 2; _i++) {      /* B: 128 rows */                   \
        int _idx = tid + _i * 256;                                            \
        int _row = _idx >> 2, _kb = _idx & 3;                                 \
        uint32_t _so = (uint32_t)((((_row >> 3) * 4 + _kb) * 128) + (_row & 7) * 16); \
        size_t _gb = (size_t)(bn + _row) * K + (kt) + _kb * 8;                \
        CP16(_sb + BOFF_BH + _so, Bh + _gb, 16);                              \
        CP16(_sb + BOFF_BL + _so, Bl + _gb, 16);                              \
    } } while (0)

    B_ISSUE(0, 0);
    CP_COMMIT();

    for (int s = 0; s < NS; s++) {
        const int cur = s & 1;
        if (s + 1 < NS) { B_ISSUE((s + 1) & 1, (s + 1) * 32); CP_COMMIT(); CP_WAIT1(); }
        else            { CP_WAIT0(); }
        __syncthreads();

        const uint32_t sb = sbase + (uint32_t)cur * BSTAGE;
#pragma unroll
        for (int k16 = 0; k16 < 2; k16++) {
            // B fragments: 8 n-blocks via 4 paired ldmatrix.x4 per matrix
            uint32_t bh[8][2], bl[8][2];
            int bn_l = lane & 7;
            int bkb  = k16 * 2 + ((lane >> 3) & 1);
#pragma unroll
            for (int np = 0; np < 4; np++) {
                int nt = np*2 + (lane >> 4);
                int n  = wn + nt * 8 + bn_l;
                uint32_t off = (uint32_t)((((n >> 3) * 4 + bkb) * 128) + (n & 7) * 16);
                uint32_t r[4];
                LDSM_X4(r, sb + BOFF_BH + off);
                bh[np*2][0]=r[0]; bh[np*2][1]=r[1];
                bh[np*2+1][0]=r[2]; bh[np*2+1][1]=r[3];
                LDSM_X4(r, sb + BOFF_BL + off);
                bl[np*2][0]=r[0]; bl[np*2][1]=r[1];
                bl[np*2+1][0]=r[2]; bl[np*2+1][1]=r[3];
            }
#pragma unroll
            for (int mt = 0; mt < 4; mt++) {
                int r  = wm + mt * 16 + arow;
                int kb = k16 * 2 + akbo;
                uint32_t off = (uint32_t)((((r >> 3) * 4 + kb) * 128) + (r & 7) * 16);
                uint32_t ah[4], al[4];
                LDSM_X4(ah, sb + BOFF_AH + off);
                LDSM_X4(al, sb + BOFF_AL + off);
#pragma unroll
                for (int nt = 0; nt < 8; nt++) MMA16816(acc[mt][nt], ah, bh[nt]);
#pragma unroll
                for (int nt = 0; nt < 8; nt++) MMA16816(acc[mt][nt], ah, bl[nt]);
#pragma unroll
                for (int nt = 0; nt < 8; nt++) MMA16816(acc[mt][nt], al, bh[nt]);
            }
        }
        __syncthreads();
    }

    const int erow = lane >> 2, ecol = (lane & 3) * 2;
#pragma unroll
    for (int mt = 0; mt < 4; mt++) {
#pragma unroll
        for (int nt = 0; nt < 8; nt++) {
            int col = bn + wn + nt * 8 + ecol;          // always < N (N%128==0)
            int r0  = bm + wm + mt * 16 + erow;
#pragma unroll
            for (int half = 0; half < 2; half++) {
                int row = r0 + half * 8;
                float v0 = acc[mt][nt][2*half+0], v1 = acc[mt][nt][2*half+1];
                if (MODE == 0) {
                    *reinterpret_cast<float2*>(C + (size_t)row * N + col) =
                        make_float2(v0, v1);
                } else if (MODE == 1) {
                    int h = col / QKD, d = col - h * QKD;
                    size_t dst = (((size_t)((row >> 11)*NH + h))*SEQ + (row & (SEQ-1)))*QKD + d;
                    split_store2(v0*scale, v1*scale, P0 + dst, P1 + dst);
                } else {
                    int h = col >> 8, d = col & 255;
                    size_t tb = ((size_t)((row >> 11)*NH + h))*SEQ + (row & (SEQ-1));
                    if (d < NOPE) {
                        size_t dst = tb*QKD + d;
                        split_store2(v0, v1, P0 + dst, P1 + dst);
                    } else {
                        size_t dst = tb*VD + (d - NOPE);
                        split_store2(v0, v1, P2 + dst, P3 + dst);
                    }
                }
            }
        }
    }
}

// ------------- prep: RMSNorm(kv_c) -> split, RoPE(k_pe) -> split K layout -----
// (q NOT rotated — reference rotates a copy and drops it)
__global__ void __launch_bounds__(256)
prep_kernel(const float* __restrict__ kv,
            const float* __restrict__ kvnw,
            const float* __restrict__ fcos, const float* __restrict__ fsin,
            __nv_bfloat16* __restrict__ kvch, __nv_bfloat16* __restrict__ kvcl,
            __nv_bfloat16* __restrict__ akh,  __nv_bfloat16* __restrict__ akl)
{
    const int token = blockIdx.x;
    const int b     = token >> 11;
    const int spos  = token & (SEQ - 1);
    const int tid   = threadIdx.x;
    __shared__ float red[256];
    __shared__ float rope[ROPE_D];

    const float* kvrow = kv + (size_t)token * (KV_LORA + ROPE_D);
    float ss = 0.f;
    for (int i = tid; i < KV_LORA; i += 256) { float v = kvrow[i]; ss += v*v; }
    red[tid] = ss;
    __syncthreads();
    for (int st = 128; st > 0; st >>= 1) {
        if (tid < st) red[tid] += red[tid + st];
        __syncthreads();
    }
    const float rms = rsqrtf(red[0] / (float)KV_LORA + 1e-6f);

    for (int i = tid; i < KV_LORA; i += 256) {
        float v = kvrow[i] * rms * kvnw[i];
        __nv_bfloat16 hb = __float2bfloat16(v);
        kvch[(size_t)token * KV_LORA + i] = hb;
        kvcl[(size_t)token * KV_LORA + i] = __float2bfloat16(v - __bfloat162float(hb));
    }

    if (tid < 32) {
        float re = kvrow[KV_LORA + 2*tid], im = kvrow[KV_LORA + 2*tid + 1];
        float c = fcos[spos*32 + tid], s = fsin[spos*32 + tid];
        rope[2*tid]     = re*c - im*s;
        rope[2*tid + 1] = re*s + im*c;
    }
    __syncthreads();

    for (int i = tid; i < NH * ROPE_D; i += 256) {
        int h = i >> 6, d = i & 63;
        float v = rope[d];
        __nv_bfloat16 hb = __float2bfloat16(v);
        size_t dst = (((size_t)(b*NH + h))*SEQ + spos)*QKD + NOPE + d;
        akh[dst] = hb;
        akl[dst] = __float2bfloat16(v - __bfloat162float(hb));
    }
}

// ===================== tensor-core flash attention =============================
#define ATS_Q   0
#define ATS_QL  49152
#define ATS_ST  98304
#define ATS_K   0
#define ATS_KL  12288
#define ATS_V   24576
#define ATS_VL  32768
#define ATS_STAGE 40960
#define ATS_TOTAL (98304 + 2*ATS_STAGE)   // 180224

__global__ void __launch_bounds__(256, 1)
attn_mma(const __nv_bfloat16* __restrict__ qh_, const __nv_bfloat16* __restrict__ ql_,
         const __nv_bfloat16* __restrict__ kh_, const __nv_bfloat16* __restrict__ kl_,
         const __nv_bfloat16* __restrict__ vh_, const __nv_bfloat16* __restrict__ vl_,
         __nv_bfloat16* __restrict__ outh, __nv_bfloat16* __restrict__ outl)
{
    extern __shared__ char sm[];
    const uint32_t sb = smem_u32(sm);
    const int tid = threadIdx.x, lane = tid & 31, w = tid >> 5;
    const int qi = (int)gridDim.x - 1 - (int)blockIdx.x;   // heavy tiles first
    const int h = blockIdx.y, b = blockIdx.z;
    const int qb = qi * 128;
    const size_t hoff = ((size_t)(b*NH + h)) * SEQ;
    const __nv_bfloat16* qh = qh_ + (hoff + qb) * QKD;
    const __nv_bfloat16* ql = ql_ + (hoff + qb) * QKD;
    const __nv_bfloat16* kh = kh_ + hoff * QKD;
    const __nv_bfloat16* kl = kl_ + hoff * QKD;
    const __nv_bfloat16* vh = vh_ + hoff * VD;
    const __nv_bfloat16* vl = vl_ + hoff * VD;
    const int NCH = 4*qi + 4;

#define AT_ISSUE(st, jj) do {                                                 \
    uint32_t _s = sb + ATS_ST + (uint32_t)(st) * ATS_STAGE;                   \
    int _p = tid >> 3, _c = tid & 7;                                          \
    _Pragma("unroll")                                                         \
    for (int _it = 0; _it < 3; _it++) {                                       \
        int _kb = _c + _it*8;                                                 \
        uint32_t _o = (uint32_t)((((_p>>3)*24 + _kb)*128) + (_p&7)*16);       \
        size_t _g = ((size_t)(jj)*32 + _p)*QKD + _kb*8;                       \
        CP16(_s + ATS_K  + _o, kh + _g, 16);                                  \
        CP16(_s + ATS_KL + _o, kl + _g, 16);                                  \
    }                                                                         \
    _Pragma("unroll")                                                         \
    for (int _it = 0; _it < 2; _it++) {                                       \
        int _cb = _c + _it*8;                                                 \
        uint32_t _o = (uint32_t)((((_p>>3)*16 + _cb)*128) + (_p&7)*16);       \
        size_t _g = ((size_t)(jj)*32 + _p)*VD + _cb*8;                        \
        CP16(_s + ATS_V  + _o, vh + _g, 16);                                  \
        CP16(_s + ATS_VL + _o, vl + _g, 16);                                  \
    } } while (0)

    AT_ISSUE(0, 0);
    CP_COMMIT();

    // Q resident load (plain; covered by first-loop barrier)
    {
        int m = tid >> 1;
#pragma unroll
        for (int it = 0; it < 12; it++) {
            int kb = (tid & 1) + it*2;
            uint32_t so = (uint32_t)((((m>>3)*24 + kb)*128) + (m&7)*16);
            *reinterpret_cast<uint4*>(sm + ATS_Q + so) =
                *reinterpret_cast<const uint4*>(qh + (size_t)m*QKD + kb*8);
            *reinterpret_cast<uint4*>(sm + ATS_QL + so) =
                *reinterpret_cast<const uint4*>(ql + (size_t)m*QKD + kb*8);
        }
    }

    float o[16][4];
#pragma unroll
    for (int nf = 0; nf < 16; nf++)
#pragma unroll
        for (int e = 0; e < 4; e++) o[nf][e] = 0.f;
    float m0 = -1e30f, m1 = -1e30f, l0 = 0.f, l1 = 0.f;

    const int rg0 = qb + w*16 + (lane >> 2);
    const int rg1 = rg0 + 8;

    for (int j = 0; j < NCH; j++) {
        if (j + 1 < NCH) { AT_ISSUE((j+1)&1, j+1); CP_COMMIT(); CP_WAIT1(); }
        else             { CP_WAIT0(); }
        __syncthreads();
        const uint32_t st = sb + ATS_ST + (uint32_t)(j & 1) * ATS_STAGE;

        // ---- S = Q K^T ----
        float s4[4][4];
#pragma unroll
        for (int nf = 0; nf < 4; nf++)
#pragma unroll
            for (int e = 0; e < 4; e++) s4[nf][e] = 0.f;

#pragma unroll
        for (int kk = 0; kk < 12; kk++) {
            uint32_t bkh[4][2], bkl[4][2];
            int bn_ = lane & 7;
            int bkb = kk*2 + ((lane >> 3) & 1);
#pragma unroll
            for (int np = 0; np < 2; np++) {
                int nf = np*2 + (lane >> 4);
                int n = nf*8 + bn_;
                uint32_t boff = (uint32_t)((((n>>3)*24 + bkb)*128) + (n&7)*16);
                uint32_t r[4];
                LDSM_X4(r, st + ATS_K + boff);
                bkh[np*2][0]=r[0]; bkh[np*2][1]=r[1];
                bkh[np*2+1][0]=r[2]; bkh[np*2+1][1]=r[3];
                LDSM_X4(r, st + ATS_KL + boff);
                bkl[np*2][0]=r[0]; bkl[np*2][1]=r[1];
                bkl[np*2+1][0]=r[2]; bkl[np*2+1][1]=r[3];
            }
            int am = w*16 + (lane & 15);
            int akb = kk*2 + (lane >> 4);
            uint32_t aoff = (uint32_t)((((am>>3)*24 + akb)*128) + (am&7)*16);
            uint32_t aqh[4], aql[4];
            LDSM_X4(aqh, sb + ATS_Q  + aoff);
            LDSM_X4(aql, sb + ATS_QL + aoff);
#pragma unroll
            for (int nf = 0; nf < 4; nf++) MMA16816(s4[nf], aqh, bkh[nf]);
#pragma unroll
            for (int nf = 0; nf < 4; nf++) MMA16816(s4[nf], aqh, bkl[nf]);
#pragma unroll
            for (int nf = 0; nf < 4; nf++) MMA16816(s4[nf], aql, bkh[nf]);
        }

        // ---- causal mask (diagonal band chunks only) ----
        if (j >= 4*qi) {
            int cb = j*32 + (lane & 3)*2;
#pragma unroll
            for (int nf = 0; nf < 4; nf++) {
                int c = cb + nf*8;
                if (c     > rg0) s4[nf][0] = -1e30f;
                if (c + 1 > rg0) s4[nf][1] = -1e30f;
                if (c     > rg1) s4[nf][2] = -1e30f;
                if (c + 1 > rg1) s4[nf][3] = -1e30f;
            }
        }

        // ---- online softmax in registers ----
        float mx0 = -1e30f, mx1 = -1e30f;
#pragma unroll
        for (int nf = 0; nf < 4; nf++) {
            mx0 = fmaxf(mx0, fmaxf(s4[nf][0], s4[nf][1]));
            mx1 = fmaxf(mx1, fmaxf(s4[nf][2], s4[nf][3]));
        }
        mx0 = fmaxf(mx0, __shfl_xor_sync(0xffffffffu, mx0, 1));
        mx0 = fmaxf(mx0, __shfl_xor_sync(0xffffffffu, mx0, 2));
        mx1 = fmaxf(mx1, __shfl_xor_sync(0xffffffffu, mx1, 1));
        mx1 = fmaxf(mx1, __shfl_xor_sync(0xffffffffu, mx1, 2));
        float mn0 = fmaxf(m0, mx0), mn1 = fmaxf(m1, mx1);
        float c0 = __expf(m0 - mn0), c1 = __expf(m1 - mn1);
        m0 = mn0; m1 = mn1;
        float sum0 = 0.f, sum1 = 0.f;
#pragma unroll
        for (int nf = 0; nf < 4; nf++) {
            s4[nf][0] = __expf(s4[nf][0] - mn0);
            s4[nf][1] = __expf(s4[nf][1] - mn0);
            s4[nf][2] = __expf(s4[nf][2] - mn1);
            s4[nf][3] = __expf(s4[nf][3] - mn1);
            sum0 += s4[nf][0] + s4[nf][1];
            sum1 += s4[nf][2] + s4[nf][3];
        }
        sum0 += __shfl_xor_sync(0xffffffffu, sum0, 1);
        sum0 += __shfl_xor_sync(0xffffffffu, sum0, 2);
        sum1 += __shfl_xor_sync(0xffffffffu, sum1, 1);
        sum1 += __shfl_xor_sync(0xffffffffu, sum1, 2);
        l0 = l0*c0 + sum0;
        l1 = l1*c1 + sum1;
#pragma unroll
        for (int nf = 0; nf < 16; nf++) {
            o[nf][0] *= c0; o[nf][1] *= c0; o[nf][2] *= c1; o[nf][3] *= c1;
        }

        // ---- O += P V ----
#pragma unroll
        for (int kk = 0; kk < 2; kk++) {
            float eh[8], el[8];
#pragma unroll
            for (int e = 0; e < 8; e++) {
                float p = (e < 4) ? s4[2*kk][e] : s4[2*kk+1][e-4];
                __nv_bfloat16 hb = __float2bfloat16(p);
                eh[e] = __bfloat162float(hb);
                el[e] = p - eh[e];
            }
            uint32_t aph[4] = {pkbf2(eh[0],eh[1]), pkbf2(eh[2],eh[3]),
                               pkbf2(eh[4],eh[5]), pkbf2(eh[6],eh[7])};
            uint32_t apl[4] = {pkbf2(el[0],el[1]), pkbf2(el[2],el[3]),
                               pkbf2(el[4],el[5]), pkbf2(el[6],el[7])};
            int r = kk*16 + (lane & 15);
#pragma unroll
            for (int np = 0; np < 8; np++) {
                int nf = np*2 + (lane >> 4);
                uint32_t voff = (uint32_t)((((r>>3)*16 + nf)*128) + (r&7)*16);
                uint32_t rh[4], rl[4];
                LDSM_X4T(rh, st + ATS_V  + voff);
                LDSM_X4T(rl, st + ATS_VL + voff);
                MMA16816(o[np*2],   aph, rh);
                MMA16816(o[np*2+1], aph, rh+2);
                MMA16816(o[np*2],   aph, rl);
                MMA16816(o[np*2+1], aph, rl+2);
                MMA16816(o[np*2],   apl, rh);
                MMA16816(o[np*2+1], apl, rh+2);
            }
        }
        __syncthreads();   // all warps done with stage j before it's refilled
    }

    // ---- epilogue: normalize + split-store directly (feeds wo GEMM) ----
    const float i0 = 1.f / l0, i1 = 1.f / l1;
    const size_t t0 = (size_t)b*SEQ + rg0;
#pragma unroll
    for (int nf = 0; nf < 16; nf++) {
        int col = h*VD + nf*8 + (lane & 3)*2;
        size_t d0 = t0*(size_t)(NH*VD) + col;
        size_t d1 = (t0+8)*(size_t)(NH*VD) + col;
        split_store2(o[nf][0]*i0, o[nf][1]*i0, outh + d0, outl + d0);
        split_store2(o[nf][2]*i1, o[nf][3]*i1, outh + d1, outl + d1);
    }
}

// ---------------------------------- launch -----------------------------------
extern "C" void kernel_launch(void* const* d_in, const int* in_sizes, int n_in,
                              void* d_out, int out_size)
{
    const float* x     = (const float*)d_in[0];
    const float* wq    = (const float*)d_in[1];
    const float* wkv_a = (const float*)d_in[2];
    const float* kvnw  = (const float*)d_in[3];
    const float* wkv_b = (const float*)d_in[4];
    const float* wo    = (const float*)d_in[5];
    const float* fcos  = (const float*)d_in[6];
    const float* fsin  = (const float*)d_in[7];
    float* out = (float*)d_out;

    float *kv;
    cudaGetSymbolAddress((void**)&kv, g_kv);

    __nv_bfloat16 *xh,*xl,*wqh,*wql,*wah,*wal,*wbh,*wbl,*woh,*wol,*kvch,*kvcl,*ath,*atl;
    __nv_bfloat16 *aqh,*aql,*akh,*akl,*avh,*avl;
    cudaGetSymbolAddress((void**)&xh,  g_xh);   cudaGetSymbolAddress((void**)&xl,  g_xl);
    cudaGetSymbolAddress((void**)&wqh, g_wqh);  cudaGetSymbolAddress((void**)&wql, g_wql);
    cudaGetSymbolAddress((void**)&wah, g_wah);  cudaGetSymbolAddress((void**)&wal, g_wal);
    cudaGetSymbolAddress((void**)&wbh, g_wbh);  cudaGetSymbolAddress((void**)&wbl, g_wbl);
    cudaGetSymbolAddress((void**)&woh, g_woh);  cudaGetSymbolAddress((void**)&wol, g_wol);
    cudaGetSymbolAddress((void**)&kvch,g_kvch); cudaGetSymbolAddress((void**)&kvcl,g_kvcl);
    cudaGetSymbolAddress((void**)&ath, g_ath);  cudaGetSymbolAddress((void**)&atl, g_atl);
    cudaGetSymbolAddress((void**)&aqh, g_aqh);  cudaGetSymbolAddress((void**)&aql, g_aql);
    cudaGetSymbolAddress((void**)&akh, g_akh);  cudaGetSymbolAddress((void**)&akl, g_akl);
    cudaGetSymbolAddress((void**)&avh, g_avh);  cudaGetSymbolAddress((void**)&avl, g_avl);

    double mm = 0.1 * 1.0 * log(40.0) + 1.0;
    float scale = (float)(mm * mm / sqrt((double)QKD));

    cudaFuncSetAttribute(gemm_sm<0>,  cudaFuncAttributeMaxDynamicSharedMemorySize, GSMEM);
    cudaFuncSetAttribute(gemm_big<0>, cudaFuncAttributeMaxDynamicSharedMemorySize, BSMEM);
    cudaFuncSetAttribute(gemm_big<1>, cudaFuncAttributeMaxDynamicSharedMemorySize, BSMEM);
    cudaFuncSetAttribute(gemm_big<2>, cudaFuncAttributeMaxDynamicSharedMemorySize, BSMEM);
    cudaFuncSetAttribute(attn_mma, cudaFuncAttributeMaxDynamicSharedMemorySize, ATS_TOTAL);

    // one fused split pass over all inputs/weights (also fixes ncu launch index)
    const int n0 = (NTOK*DIM)/1024;                       // x     : 8192
    const int n1 = (NH*QKD*DIM)/1024;                     // wq    : 6144
    const int n2 = ((KV_LORA+ROPE_D)*DIM)/1024;           // wkv_a : 1152
    const int n3 = (NH*(NOPE+VD)*KV_LORA)/1024;           // wkv_b : 2048
    const int n4 = (DIM*NH*VD)/1024;                      // wo    : 4096
    cvt_all<<<n0+n1+n2+n3+n4, 256>>>(
        x,     xh,  xl,  n0,
        wq,    wqh, wql, n0+n1,
        wkv_a, wah, wal, n0+n1+n2,
        wkv_b, wbh, wbl, n0+n1+n2+n3,
        wo,    woh, wol, n0+n1+n2+n3+n4);

    // q = x @ wq^T -> scaled split Q in attention layout
    gemm_big<1><<<dim3(3072/128, 4096/256), 256, BSMEM>>>(
        xh, xl, wqh, wql, nullptr, aqh, aql, nullptr, nullptr, scale,
        NTOK, NH*QKD, DIM);
    // kv = x @ wkv_a^T (fp32; prep consumes it) — N=576 needs guarded kernel
    gemm_sm<0><<<dim3(5, 32), 256, GSMEM>>>(
        xh, xl, wah, wal, kv, 1.f, NTOK, KV_LORA+ROPE_D, DIM);
    // rmsnorm -> split kvc; rope -> split K[:,128:192] all heads (q NOT rotated)
    prep_kernel<<<NTOK, 256>>>(kv, kvnw, fcos, fsin, kvch, kvcl, akh, akl);
    // kvb = kvc @ wkv_b^T -> split K-nope / V in attention layouts
    gemm_big<2><<<dim3(4096/128, 4096/256), 256, BSMEM>>>(
        kvch, kvcl, wbh, wbl, nullptr, akh, akl, avh, avl, 1.f,
        NTOK, NH*(NOPE+VD), KV_LORA);
    // tensor-core flash attention -> split output (feeds wo GEMM directly)
    attn_mma<<<dim3(SEQ/128, NH, BATCH), 256, ATS_TOTAL>>>(
        aqh, aql, akh, akl, avh, avl, ath, atl);
    // out = attn @ wo^T
    gemm_big<0><<<dim3(2048/128, 4096/256), 256, BSMEM>>>(
        ath, atl, woh, wol, out, nullptr, nullptr, nullptr, nullptr, 1.f,
        NTOK, DIM, NH*VD);
}

// round 17
// speedup vs baseline: 3.2879x; 1.1696x over previous
#include <cuda_runtime.h>
#include <cuda_bf16.h>
#include <cuda_fp16.h>
#include <math.h>
#include <stdint.h>

#define DIM 2048
#define NH 16
#define KV_LORA 512
#define NOPE 128
#define ROPE_D 64
#define VD 128
#define QKD 192
#define BATCH 2
#define SEQ 2048
#define NTOK (BATCH*SEQ)

// ---------------- fp32 scratch ------------------------------------------------
__device__ float g_kv[(size_t)NTOK * (KV_LORA + ROPE_D)];

// ---------------- bf16 hi/lo scratch (GEMM operands) ---------------------------
__device__ __nv_bfloat16 g_xh[(size_t)NTOK * DIM],              g_xl[(size_t)NTOK * DIM];
__device__ __nv_bfloat16 g_wqh[(size_t)NH*QKD * DIM],           g_wql[(size_t)NH*QKD * DIM];
__device__ __nv_bfloat16 g_wah[(size_t)(KV_LORA+ROPE_D) * DIM], g_wal[(size_t)(KV_LORA+ROPE_D) * DIM];
__device__ __nv_bfloat16 g_wbh[(size_t)NH*(NOPE+VD) * KV_LORA], g_wbl[(size_t)NH*(NOPE+VD) * KV_LORA];
__device__ __nv_bfloat16 g_woh[(size_t)DIM * NH*VD],            g_wol[(size_t)DIM * NH*VD];
__device__ __nv_bfloat16 g_kvch[(size_t)NTOK * KV_LORA],        g_kvcl[(size_t)NTOK * KV_LORA];
__device__ __nv_bfloat16 g_ath[(size_t)NTOK * NH*VD],           g_atl[(size_t)NTOK * NH*VD];

// ---------------- fp16 attention operands [b][h][s][d] -------------------------
__device__ __half g_aq[(size_t)NTOK * NH * QKD];
__device__ __half g_ak[(size_t)NTOK * NH * QKD];
__device__ __half g_av[(size_t)NTOK * NH * VD];

// ======================= PTX helpers (baseline sm_103) =========================
__device__ __forceinline__ uint32_t smem_u32(const void* p) {
    uint32_t a;
    asm("{ .reg .u64 t; cvta.to.shared.u64 t, %1; cvt.u32.u64 %0, t; }"
        : "=r"(a) : "l"(p));
    return a;
}
#define CP16(s, g, sz) \
    asm volatile("cp.async.cg.shared.global [%0], [%1], 16, %2;" \
                 :: "r"(s), "l"(g), "r"(sz) : "memory")
#define CP_COMMIT() asm volatile("cp.async.commit_group;" ::: "memory")
#define CP_WAIT1()  asm volatile("cp.async.wait_group 1;" ::: "memory")
#define CP_WAIT0()  asm volatile("cp.async.wait_group 0;" ::: "memory")

#define LDSM_X4(r, a) \
    asm volatile("ldmatrix.sync.aligned.m8n8.x4.shared.b16 {%0,%1,%2,%3}, [%4];" \
                 : "=r"((r)[0]), "=r"((r)[1]), "=r"((r)[2]), "=r"((r)[3]) : "r"(a))
#define LDSM_X4T(r, a) \
    asm volatile("ldmatrix.sync.aligned.m8n8.x4.trans.shared.b16 {%0,%1,%2,%3}, [%4];" \
                 : "=r"((r)[0]), "=r"((r)[1]), "=r"((r)[2]), "=r"((r)[3]) : "r"(a))
#define MMA16816(d, a, b) \
    asm volatile("mma.sync.aligned.m16n8k16.row.col.f32.bf16.bf16.f32 " \
                 "{%0,%1,%2,%3}, {%4,%5,%6,%7}, {%8,%9}, {%0,%1,%2,%3};" \
                 : "+f"((d)[0]), "+f"((d)[1]), "+f"((d)[2]), "+f"((d)[3]) \
                 : "r"((a)[0]), "r"((a)[1]), "r"((a)[2]), "r"((a)[3]), \
                   "r"((b)[0]), "r"((b)[1]))
#define MMAH16816(d, a, b) \
    asm volatile("mma.sync.aligned.m16n8k16.row.col.f32.f16.f16.f32 " \
                 "{%0,%1,%2,%3}, {%4,%5,%6,%7}, {%8,%9}, {%0,%1,%2,%3};" \
                 : "+f"((d)[0]), "+f"((d)[1]), "+f"((d)[2]), "+f"((d)[3]) \
                 : "r"((a)[0]), "r"((a)[1]), "r"((a)[2]), "r"((a)[3]), \
                   "r"((b)[0]), "r"((b)[1]))

__device__ __forceinline__ uint32_t pkh2(float a, float b) {
    __half2 t = __floats2half2_rn(a, b);
    return *reinterpret_cast<uint32_t*>(&t);
}
__device__ __forceinline__ void split_store2(float v0, float v1,
                                             __nv_bfloat16* ph, __nv_bfloat16* pl) {
    __nv_bfloat16 h0 = __float2bfloat16(v0), h1 = __float2bfloat16(v1);
    __nv_bfloat16 l0 = __float2bfloat16(v0 - __bfloat162float(h0));
    __nv_bfloat16 l1 = __float2bfloat16(v1 - __bfloat162float(h1));
    *reinterpret_cast<__nv_bfloat162*>(ph) = __halves2bfloat162(h0, h1);
    *reinterpret_cast<__nv_bfloat162*>(pl) = __halves2bfloat162(l0, l1);
}

// ---------------- fused fp32 -> (hi, lo) split for all 5 tensors --------------
__global__ void __launch_bounds__(256)
cvt_all(const float* __restrict__ s0, __nv_bfloat16* __restrict__ h0, __nv_bfloat16* __restrict__ l0, int e0,
        const float* __restrict__ s1, __nv_bfloat16* __restrict__ h1, __nv_bfloat16* __restrict__ l1, int e1,
        const float* __restrict__ s2, __nv_bfloat16* __restrict__ h2, __nv_bfloat16* __restrict__ l2, int e2,
        const float* __restrict__ s3, __nv_bfloat16* __restrict__ h3, __nv_bfloat16* __restrict__ l3, int e3,
        const float* __restrict__ s4, __nv_bfloat16* __restrict__ h4, __nv_bfloat16* __restrict__ l4, int e4)
{
    int blk = blockIdx.x;
    const float* s; __nv_bfloat16 *h, *l; int base;
    if      (blk < e0) { s = s0; h = h0; l = l0; base = 0;  }
    else if (blk < e1) { s = s1; h = h1; l = l1; base = e0; }
    else if (blk < e2) { s = s2; h = h2; l = l2; base = e1; }
    else if (blk < e3) { s = s3; h = h3; l = l3; base = e2; }
    else               { s = s4; h = h4; l = l4; base = e3; }
    int i = (blk - base) * 256 + threadIdx.x;
    float4 v = reinterpret_cast<const float4*>(s)[i];
    __nv_bfloat16 a0 = __float2bfloat16(v.x), a1 = __float2bfloat16(v.y);
    __nv_bfloat16 a2 = __float2bfloat16(v.z), a3 = __float2bfloat16(v.w);
    __nv_bfloat16 b0 = __float2bfloat16(v.x - __bfloat162float(a0));
    __nv_bfloat16 b1 = __float2bfloat16(v.y - __bfloat162float(a1));
    __nv_bfloat16 b2 = __float2bfloat16(v.z - __bfloat162float(a2));
    __nv_bfloat16 b3 = __float2bfloat16(v.w - __bfloat162float(a3));
    reinterpret_cast<__nv_bfloat162*>(h)[2*i]   = __halves2bfloat162(a0, a1);
    reinterpret_cast<__nv_bfloat162*>(h)[2*i+1] = __halves2bfloat162(a2, a3);
    reinterpret_cast<__nv_bfloat162*>(l)[2*i]   = __halves2bfloat162(b0, b1);
    reinterpret_cast<__nv_bfloat162*>(l)[2*i+1] = __halves2bfloat162(b2, b3);
}

// =========== small NT GEMM (128x128 tile) — used for kv (N=576) ===============
#define OFF_AH 0
#define OFF_AL 8192
#define OFF_BH 16384
#define OFF_BL 24576
#define STAGE_SZ 32768
#define GSMEM (2*STAGE_SZ)

__global__ void __launch_bounds__(256, 2)
gemm_sm(const __nv_bfloat16* __restrict__ Ah, const __nv_bfloat16* __restrict__ Al,
        const __nv_bfloat16* __restrict__ Bh, const __nv_bfloat16* __restrict__ Bl,
        float* __restrict__ C, int M, int N, int K)
{
    extern __shared__ char smraw[];
    const uint32_t sbase = smem_u32(smraw);
    const int tid  = threadIdx.x;
    const int lane = tid & 31, wid = tid >> 5;
    const int bm = blockIdx.y * 128, bn = blockIdx.x * 128;
    const int wm = (wid >> 2) * 64, wn = (wid & 3) * 32;

    float acc[4][4][4];
#pragma unroll
    for (int mt = 0; mt < 4; mt++)
#pragma unroll
        for (int nt = 0; nt < 4; nt++)
#pragma unroll
            for (int e = 0; e < 4; e++) acc[mt][nt][e] = 0.f;

    const int NS = K >> 5;
    const int arow = lane & 15, akbo = lane >> 4;

#define S_ISSUE(st, kt) do {                                                  \
    uint32_t _sb = sbase + (uint32_t)(st) * STAGE_SZ;                         \
    _Pragma("unroll")                                                         \
    for (int _i = 0; _i < 2; _i++) {                                          \
        int _idx = tid + _i * 256;                                            \
        int _row = _idx >> 2, _kb = _idx & 3;                                 \
        uint32_t _so = (uint32_t)((((_row >> 3) * 4 + _kb) * 128) + (_row & 7) * 16); \
        size_t _ga = (size_t)(bm + _row) * K + (kt) + _kb * 8;                \
        CP16(_sb + OFF_AH + _so, Ah + _ga, 16);                               \
        CP16(_sb + OFF_AL + _so, Al + _ga, 16);                               \
        int _nr = bn + _row;                                                  \
        int _ok = (_nr < N) ? 16 : 0;                                         \
        if (_nr >= N) _nr = 0;                                                \
        size_t _gb = (size_t)_nr * K + (kt) + _kb * 8;                        \
        CP16(_sb + OFF_BH + _so, Bh + _gb, _ok);                              \
        CP16(_sb + OFF_BL + _so, Bl + _gb, _ok);                              \
    } } while (0)

    S_ISSUE(0, 0);
    CP_COMMIT();

    for (int s = 0; s < NS; s++) {
        const int cur = s & 1;
        if (s + 1 < NS) { S_ISSUE((s + 1) & 1, (s + 1) * 32); CP_COMMIT(); CP_WAIT1(); }
        else            { CP_WAIT0(); }
        __syncthreads();

        const uint32_t sb = sbase + (uint32_t)cur * STAGE_SZ;
#pragma unroll
        for (int k16 = 0; k16 < 2; k16++) {
            uint32_t bh[4][2], bl[4][2];
#pragma unroll
            for (int np = 0; np < 2; np++) {
                int nt = np*2 + (lane >> 4);
                int n  = wn + nt * 8 + (lane & 7);
                int kb = k16 * 2 + ((lane >> 3) & 1);
                uint32_t off = (uint32_t)((((n >> 3) * 4 + kb) * 128) + (n & 7) * 16);
                uint32_t r[4];
                LDSM_X4(r, sb + OFF_BH + off);
                bh[np*2][0]=r[0]; bh[np*2][1]=r[1];
                bh[np*2+1][0]=r[2]; bh[np*2+1][1]=r[3];
                LDSM_X4(r, sb + OFF_BL + off);
                bl[np*2][0]=r[0]; bl[np*2][1]=r[1];
                bl[np*2+1][0]=r[2]; bl[np*2+1][1]=r[3];
            }
#pragma unroll
            for (int mt = 0; mt < 4; mt++) {
                int r  = wm + mt * 16 + arow;
                int kb = k16 * 2 + akbo;
                uint32_t off = (uint32_t)((((r >> 3) * 4 + kb) * 128) + (r & 7) * 16);
                uint32_t ah[4], al[4];
                LDSM_X4(ah, sb + OFF_AH + off);
                LDSM_X4(al, sb + OFF_AL + off);
#pragma unroll
                for (int nt = 0; nt < 4; nt++) MMA16816(acc[mt][nt], ah, bh[nt]);
#pragma unroll
                for (int nt = 0; nt < 4; nt++) MMA16816(acc[mt][nt], ah, bl[nt]);
#pragma unroll
                for (int nt = 0; nt < 4; nt++) MMA16816(acc[mt][nt], al, bh[nt]);
            }
        }
        __syncthreads();
    }

    const int erow = lane >> 2, ecol = (lane & 3) * 2;
#pragma unroll
    for (int mt = 0; mt < 4; mt++) {
#pragma unroll
        for (int nt = 0; nt < 4; nt++) {
            int col = bn + wn + nt * 8 + ecol;
            if (col >= N) continue;
            int r0 = bm + wm + mt * 16 + erow;
            *reinterpret_cast<float2*>(C + (size_t)r0 * N + col) =
                make_float2(acc[mt][nt][0], acc[mt][nt][1]);
            *reinterpret_cast<float2*>(C + (size_t)(r0 + 8) * N + col) =
                make_float2(acc[mt][nt][2], acc[mt][nt][3]);
        }
    }
}

// ====== big NT GEMM: 256x128 CTA tile, 64x64 warp tile ========================
// MODE 0: fp32 C.  MODE 1: q -> fp16 attention layout (scaled).
// MODE 2: kvb -> fp16 K-nope / V attention layouts.
#define BOFF_AH 0
#define BOFF_AL 16384
#define BOFF_BH 32768
#define BOFF_BL 40960
#define BSTAGE  49152
#define BSMEM   (2*BSTAGE)

template<int MODE>
__global__ void __launch_bounds__(256, 1)
gemm_big(const __nv_bfloat16* __restrict__ Ah, const __nv_bfloat16* __restrict__ Al,
         const __nv_bfloat16* __restrict__ Bh, const __nv_bfloat16* __restrict__ Bl,
         float* __restrict__ C,
         __half* __restrict__ P0, __half* __restrict__ P1,
         float scale, int M, int N, int K)
{
    extern __shared__ char smraw[];
    const uint32_t sbase = smem_u32(smraw);
    const int tid  = threadIdx.x;
    const int lane = tid & 31, wid = tid >> 5;
    const int bm = blockIdx.y * 256, bn = blockIdx.x * 128;
    const int wm = (wid >> 1) * 64, wn = (wid & 1) * 64;

    float acc[4][8][4];
#pragma unroll
    for (int mt = 0; mt < 4; mt++)
#pragma unroll
        for (int nt = 0; nt < 8; nt++)
#pragma unroll
            for (int e = 0; e < 4; e++) acc[mt][nt][e] = 0.f;

    const int NS = K >> 5;
    const int arow = lane & 15, akbo = lane >> 4;

#define B_ISSUE(st, kt) do {                                                  \
    uint32_t _sb = sbase + (uint32_t)(st) * BSTAGE;                           \
    _Pragma("unroll")                                                         \
    for (int _i = 0; _i < 4; _i++) {                                          \
        int _idx = tid + _i * 256;                                            \
        int _row = _idx >> 2, _kb = _idx & 3;                                 \
        uint32_t _so = (uint32_t)((((_row >> 3) * 4 + _kb) * 128) + (_row & 7) * 16); \
        size_t _ga = (size_t)(bm + _row) * K + (kt) + _kb * 8;                \
        CP16(_sb + BOFF_AH + _so, Ah + _ga, 16);                              \
        CP16(_sb + BOFF_AL + _so, Al + _ga, 16);                              \
    }                                                                         \
    _Pragma("unroll")                                                         \
    for (int _i = 0; _i < 2; _i++) {                                          \
        int _idx = tid + _i * 256;                                            \
        int _row = _idx >> 2, _kb = _idx & 3;                                 \
        uint32_t _so = (uint32_t)((((_row >> 3) * 4 + _kb) * 128) + (_row & 7) * 16); \
        size_t _gb = (size_t)(bn + _row) * K + (kt) + _kb * 8;                \
        CP16(_sb + BOFF_BH + _so, Bh + _gb, 16);                              \
        CP16(_sb + BOFF_BL + _so, Bl + _gb, 16);                              \
    } } while (0)

    B_ISSUE(0, 0);
    CP_COMMIT();

    for (int s = 0; s < NS; s++) {
        const int cur = s & 1;
        if (s + 1 < NS) { B_ISSUE((s + 1) & 1, (s + 1) * 32); CP_COMMIT(); CP_WAIT1(); }
        else            { CP_WAIT0(); }
        __syncthreads();

        const uint32_t sb = sbase + (uint32_t)cur * BSTAGE;
#pragma unroll
        for (int k16 = 0; k16 < 2; k16++) {
            uint32_t bh[8][2], bl[8][2];
            int bn_l = lane & 7;
            int bkb  = k16 * 2 + ((lane >> 3) & 1);
#pragma unroll
            for (int np = 0; np < 4; np++) {
                int nt = np*2 + (lane >> 4);
                int n  = wn + nt * 8 + bn_l;
                uint32_t off = (uint32_t)((((n >> 3) * 4 + bkb) * 128) + (n & 7) * 16);
                uint32_t r[4];
                LDSM_X4(r, sb + BOFF_BH + off);
                bh[np*2][0]=r[0]; bh[np*2][1]=r[1];
                bh[np*2+1][0]=r[2]; bh[np*2+1][1]=r[3];
                LDSM_X4(r, sb + BOFF_BL + off);
                bl[np*2][0]=r[0]; bl[np*2][1]=r[1];
                bl[np*2+1][0]=r[2]; bl[np*2+1][1]=r[3];
            }
#pragma unroll
            for (int mt = 0; mt < 4; mt++) {
                int r  = wm + mt * 16 + arow;
                int kb = k16 * 2 + akbo;
                uint32_t off = (uint32_t)((((r >> 3) * 4 + kb) * 128) + (r & 7) * 16);
                uint32_t ah[4], al[4];
                LDSM_X4(ah, sb + BOFF_AH + off);
                LDSM_X4(al, sb + BOFF_AL + off);
#pragma unroll
                for (int nt = 0; nt < 8; nt++) MMA16816(acc[mt][nt], ah, bh[nt]);
#pragma unroll
                for (int nt = 0; nt < 8; nt++) MMA16816(acc[mt][nt], ah, bl[nt]);
#pragma unroll
                for (int nt = 0; nt < 8; nt++) MMA16816(acc[mt][nt], al, bh[nt]);
            }
        }
        __syncthreads();
    }

    const int erow = lane >> 2, ecol = (lane & 3) * 2;
#pragma unroll
    for (int mt = 0; mt < 4; mt++) {
#pragma unroll
        for (int nt = 0; nt < 8; nt++) {
            int col = bn + wn + nt * 8 + ecol;
            int r0  = bm + wm + mt * 16 + erow;
#pragma unroll
            for (int half = 0; half < 2; half++) {
                int row = r0 + half * 8;
                float v0 = acc[mt][nt][2*half+0], v1 = acc[mt][nt][2*half+1];
                if (MODE == 0) {
                    *reinterpret_cast<float2*>(C + (size_t)row * N + col) =
                        make_float2(v0, v1);
                } else if (MODE == 1) {
                    // q: scale, fp16, [b,h,s,d]
                    int h = col / QKD, d = col - h * QKD;
                    size_t dst = (((size_t)((row >> 11)*NH + h))*SEQ + (row & (SEQ-1)))*QKD + d;
                    *reinterpret_cast<__half2*>(P0 + dst) =
                        __floats2half2_rn(v0*scale, v1*scale);
                } else {
                    // kvb: fp16; d<128 -> K-nope (P0), else V (P1)
                    int h = col >> 8, d = col & 255;
                    size_t tb = ((size_t)((row >> 11)*NH + h))*SEQ + (row & (SEQ-1));
                    if (d < NOPE) {
                        *reinterpret_cast<__half2*>(P0 + tb*QKD + d) =
                            __floats2half2_rn(v0, v1);
                    } else {
                        *reinterpret_cast<__half2*>(P1 + tb*VD + (d - NOPE)) =
                            __floats2half2_rn(v0, v1);
                    }
                }
            }
        }
    }
}

// ------------- prep: RMSNorm(kv_c) -> split bf16, RoPE(k_pe) -> fp16 K layout --
// (q NOT rotated — reference rotates a copy and drops it)
__global__ void __launch_bounds__(256)
prep_kernel(const float* __restrict__ kv,
            const float* __restrict__ kvnw,
            const float* __restrict__ fcos, const float* __restrict__ fsin,
            __nv_bfloat16* __restrict__ kvch, __nv_bfloat16* __restrict__ kvcl,
            __half* __restrict__ ak)
{
    const int token = blockIdx.x;
    const int b     = token >> 11;
    const int spos  = token & (SEQ - 1);
    const int tid   = threadIdx.x;
    __shared__ float red[256];
    __shared__ float rope[ROPE_D];

    const float* kvrow = kv + (size_t)token * (KV_LORA + ROPE_D);
    float ss = 0.f;
    for (int i = tid; i < KV_LORA; i += 256) { float v = kvrow[i]; ss += v*v; }
    red[tid] = ss;
    __syncthreads();
    for (int st = 128; st > 0; st >>= 1) {
        if (tid < st) red[tid] += red[tid + st];
        __syncthreads();
    }
    const float rms = rsqrtf(red[0] / (float)KV_LORA + 1e-6f);

    for (int i = tid; i < KV_LORA; i += 256) {
        float v = kvrow[i] * rms * kvnw[i];
        __nv_bfloat16 hb = __float2bfloat16(v);
        kvch[(size_t)token * KV_LORA + i] = hb;
        kvcl[(size_t)token * KV_LORA + i] = __float2bfloat16(v - __bfloat162float(hb));
    }

    if (tid < 32) {
        float re = kvrow[KV_LORA + 2*tid], im = kvrow[KV_LORA + 2*tid + 1];
        float c = fcos[spos*32 + tid], s = fsin[spos*32 + tid];
        rope[2*tid]     = re*c - im*s;
        rope[2*tid + 1] = re*s + im*c;
    }
    __syncthreads();

    for (int i = tid; i < NH * ROPE_D; i += 256) {
        int h = i >> 6, d = i & 63;
        size_t dst = (((size_t)(b*NH + h))*SEQ + spos)*QKD + NOPE + d;
        ak[dst] = __float2half(rope[d]);
    }
}

// ============== tensor-core flash attention (fp16, 1-term) ====================
#define ATS_Q   0            // 49152 B (128 x 192 fp16)
#define ATS_ST  49152
#define ATS_K   0            // 12288 B (32 x 192 fp16)
#define ATS_V   12288        // 8192  B (32 x 128 fp16)
#define ATS_STAGE 20480
#define ATS_TOTAL (49152 + 2*ATS_STAGE)   // 90112 -> 2 CTAs/SM

__global__ void __launch_bounds__(256, 2)
attn_mma(const __half* __restrict__ q_, const __half* __restrict__ k_,
         const __half* __restrict__ v_,
         __nv_bfloat16* __restrict__ outh, __nv_bfloat16* __restrict__ outl)
{
    extern __shared__ char sm[];
    const uint32_t sb = smem_u32(sm);
    const int tid = threadIdx.x, lane = tid & 31, w = tid >> 5;
    const int qi = (int)gridDim.x - 1 - (int)blockIdx.x;   // heavy tiles first
    const int h = blockIdx.y, b = blockIdx.z;
    const int qb = qi * 128;
    const size_t hoff = ((size_t)(b*NH + h)) * SEQ;
    const __half* qp = q_ + (hoff + qb) * QKD;
    const __half* kp = k_ + hoff * QKD;
    const __half* vp = v_ + hoff * VD;
    const int NCH = 4*qi + 4;

#define AT_ISSUE(st, jj) do {                                                 \
    uint32_t _s = sb + ATS_ST + (uint32_t)(st) * ATS_STAGE;                   \
    int _p = tid >> 3, _c = tid & 7;                                          \
    _Pragma("unroll")                                                         \
    for (int _it = 0; _it < 3; _it++) {                                       \
        int _kb = _c + _it*8;                                                 \
        uint32_t _o = (uint32_t)((((_p>>3)*24 + _kb)*128) + (_p&7)*16);       \
        CP16(_s + ATS_K + _o, kp + ((size_t)(jj)*32 + _p)*QKD + _kb*8, 16);   \
    }                                                                         \
    _Pragma("unroll")                                                         \
    for (int _it = 0; _it < 2; _it++) {                                       \
        int _cb = _c + _it*8;                                                 \
        uint32_t _o = (uint32_t)((((_p>>3)*16 + _cb)*128) + (_p&7)*16);       \
        CP16(_s + ATS_V + _o, vp + ((size_t)(jj)*32 + _p)*VD + _cb*8, 16);    \
    } } while (0)

    AT_ISSUE(0, 0);
    CP_COMMIT();

    // Q resident load (plain; covered by first-loop barrier)
    {
        int m = tid >> 1;
#pragma unroll
        for (int it = 0; it < 12; it++) {
            int kb = (tid & 1) + it*2;
            uint32_t so = (uint32_t)((((m>>3)*24 + kb)*128) + (m&7)*16);
            *reinterpret_cast<uint4*>(sm + ATS_Q + so) =
                *reinterpret_cast<const uint4*>(qp + (size_t)m*QKD + kb*8);
        }
    }

    float o[16][4];
#pragma unroll
    for (int nf = 0; nf < 16; nf++)
#pragma unroll
        for (int e = 0; e < 4; e++) o[nf][e] = 0.f;
    float m0 = -1e30f, m1 = -1e30f, l0 = 0.f, l1 = 0.f;

    const int rg0 = qb + w*16 + (lane >> 2);
    const int rg1 = rg0 + 8;

    for (int j = 0; j < NCH; j++) {
        if (j + 1 < NCH) { AT_ISSUE((j+1)&1, j+1); CP_COMMIT(); CP_WAIT1(); }
        else             { CP_WAIT0(); }
        __syncthreads();
        const uint32_t st = sb + ATS_ST + (uint32_t)(j & 1) * ATS_STAGE;

        // ---- S = Q K^T (fp16, 1 MMA per fragment) ----
        float s4[4][4];
#pragma unroll
        for (int nf = 0; nf < 4; nf++)
#pragma unroll
            for (int e = 0; e < 4; e++) s4[nf][e] = 0.f;

#pragma unroll
        for (int kk = 0; kk < 12; kk++) {
            uint32_t bk[4][2];
            int bn_ = lane & 7;
            int bkb = kk*2 + ((lane >> 3) & 1);
#pragma unroll
            for (int np = 0; np < 2; np++) {
                int nf = np*2 + (lane >> 4);
                int n = nf*8 + bn_;
                uint32_t boff = (uint32_t)((((n>>3)*24 + bkb)*128) + (n&7)*16);
                uint32_t r[4];
                LDSM_X4(r, st + ATS_K + boff);
                bk[np*2][0]=r[0]; bk[np*2][1]=r[1];
                bk[np*2+1][0]=r[2]; bk[np*2+1][1]=r[3];
            }
            int am = w*16 + (lane & 15);
            int akb = kk*2 + (lane >> 4);
            uint32_t aoff = (uint32_t)((((am>>3)*24 + akb)*128) + (am&7)*16);
            uint32_t aq[4];
            LDSM_X4(aq, sb + ATS_Q + aoff);
#pragma unroll
            for (int nf = 0; nf < 4; nf++) MMAH16816(s4[nf], aq, bk[nf]);
        }

        // ---- causal mask (diagonal band chunks only) ----
        if (j >= 4*qi) {
            int cb = j*32 + (lane & 3)*2;
#pragma unroll
            for (int nf = 0; nf < 4; nf++) {
                int c = cb + nf*8;
                if (c     > rg0) s4[nf][0] = -1e30f;
                if (c + 1 > rg0) s4[nf][1] = -1e30f;
                if (c     > rg1) s4[nf][2] = -1e30f;
                if (c + 1 > rg1) s4[nf][3] = -1e30f;
            }
        }

        // ---- online softmax in registers ----
        float mx0 = -1e30f, mx1 = -1e30f;
#pragma unroll
        for (int nf = 0; nf < 4; nf++) {
            mx0 = fmaxf(mx0, fmaxf(s4[nf][0], s4[nf][1]));
            mx1 = fmaxf(mx1, fmaxf(s4[nf][2], s4[nf][3]));
        }
        mx0 = fmaxf(mx0, __shfl_xor_sync(0xffffffffu, mx0, 1));
        mx0 = fmaxf(mx0, __shfl_xor_sync(0xffffffffu, mx0, 2));
        mx1 = fmaxf(mx1, __shfl_xor_sync(0xffffffffu, mx1, 1));
        mx1 = fmaxf(mx1, __shfl_xor_sync(0xffffffffu, mx1, 2));
        float mn0 = fmaxf(m0, mx0), mn1 = fmaxf(m1, mx1);
        float c0 = __expf(m0 - mn0), c1 = __expf(m1 - mn1);
        m0 = mn0; m1 = mn1;
        float sum0 = 0.f, sum1 = 0.f;
#pragma unroll
        for (int nf = 0; nf < 4; nf++) {
            s4[nf][0] = __expf(s4[nf][0] - mn0);
            s4[nf][1] = __expf(s4[nf][1] - mn0);
            s4[nf][2] = __expf(s4[nf][2] - mn1);
            s4[nf][3] = __expf(s4[nf][3] - mn1);
            sum0 += s4[nf][0] + s4[nf][1];
            sum1 += s4[nf][2] + s4[nf][3];
        }
        sum0 += __shfl_xor_sync(0xffffffffu, sum0, 1);
        sum0 += __shfl_xor_sync(0xffffffffu, sum0, 2);
        sum1 += __shfl_xor_sync(0xffffffffu, sum1, 1);
        sum1 += __shfl_xor_sync(0xffffffffu, sum1, 2);
        l0 = l0*c0 + sum0;
        l1 = l1*c1 + sum1;
#pragma unroll
        for (int nf = 0; nf < 16; nf++) {
            o[nf][0] *= c0; o[nf][1] *= c0; o[nf][2] *= c1; o[nf][3] *= c1;
        }

        // ---- O += P V (fp16 P, 1 MMA per fragment) ----
#pragma unroll
        for (int kk = 0; kk < 2; kk++) {
            uint32_t ap[4] = {
                pkh2(s4[2*kk][0],   s4[2*kk][1]),
                pkh2(s4[2*kk][2],   s4[2*kk][3]),
                pkh2(s4[2*kk+1][0], s4[2*kk+1][1]),
                pkh2(s4[2*kk+1][2], s4[2*kk+1][3])
            };
            int r = kk*16 + (lane & 15);
#pragma unroll
            for (int np = 0; np < 8; np++) {
                int nf = np*2 + (lane >> 4);
                uint32_t voff = (uint32_t)((((r>>3)*16 + nf)*128) + (r&7)*16);
                uint32_t rh[4];
                LDSM_X4T(rh, st + ATS_V + voff);
                MMAH16816(o[np*2],   ap, rh);
                MMAH16816(o[np*2+1], ap, rh+2);
            }
        }
        __syncthreads();   // all warps done with stage j before it's refilled
    }

    // ---- epilogue: normalize + split-store (feeds wo GEMM, stays bf16 3-term) --
    const float i0 = 1.f / l0, i1 = 1.f / l1;
    const size_t t0 = (size_t)b*SEQ + rg0;
#pragma unroll
    for (int nf = 0; nf < 16; nf++) {
        int col = h*VD + nf*8 + (lane & 3)*2;
        size_t d0 = t0*(size_t)(NH*VD) + col;
        size_t d1 = (t0+8)*(size_t)(NH*VD) + col;
        split_store2(o[nf][0]*i0, o[nf][1]*i0, outh + d0, outl + d0);
        split_store2(o[nf][2]*i1, o[nf][3]*i1, outh + d1, outl + d1);
    }
}

// ---------------------------------- launch -----------------------------------
extern "C" void kernel_launch(void* const* d_in, const int* in_sizes, int n_in,
                              void* d_out, int out_size)
{
    const float* x     = (const float*)d_in[0];
    const float* wq    = (const float*)d_in[1];
    const float* wkv_a = (const float*)d_in[2];
    const float* kvnw  = (const float*)d_in[3];
    const float* wkv_b = (const float*)d_in[4];
    const float* wo    = (const float*)d_in[5];
    const float* fcos  = (const float*)d_in[6];
    const float* fsin  = (const float*)d_in[7];
    float* out = (float*)d_out;

    float *kv;
    cudaGetSymbolAddress((void**)&kv, g_kv);

    __nv_bfloat16 *xh,*xl,*wqh,*wql,*wah,*wal,*wbh,*wbl,*woh,*wol,*kvch,*kvcl,*ath,*atl;
    __half *aq,*ak,*av;
    cudaGetSymbolAddress((void**)&xh,  g_xh);   cudaGetSymbolAddress((void**)&xl,  g_xl);
    cudaGetSymbolAddress((void**)&wqh, g_wqh);  cudaGetSymbolAddress((void**)&wql, g_wql);
    cudaGetSymbolAddress((void**)&wah, g_wah);  cudaGetSymbolAddress((void**)&wal, g_wal);
    cudaGetSymbolAddress((void**)&wbh, g_wbh);  cudaGetSymbolAddress((void**)&wbl, g_wbl);
    cudaGetSymbolAddress((void**)&woh, g_woh);  cudaGetSymbolAddress((void**)&wol, g_wol);
    cudaGetSymbolAddress((void**)&kvch,g_kvch); cudaGetSymbolAddress((void**)&kvcl,g_kvcl);
    cudaGetSymbolAddress((void**)&ath, g_ath);  cudaGetSymbolAddress((void**)&atl, g_atl);
    cudaGetSymbolAddress((void**)&aq,  g_aq);
    cudaGetSymbolAddress((void**)&ak,  g_ak);
    cudaGetSymbolAddress((void**)&av,  g_av);

    double mm = 0.1 * 1.0 * log(40.0) + 1.0;
    float scale = (float)(mm * mm / sqrt((double)QKD));

    cudaFuncSetAttribute(gemm_sm,     cudaFuncAttributeMaxDynamicSharedMemorySize, GSMEM);
    cudaFuncSetAttribute(gemm_big<0>, cudaFuncAttributeMaxDynamicSharedMemorySize, BSMEM);
    cudaFuncSetAttribute(gemm_big<1>, cudaFuncAttributeMaxDynamicSharedMemorySize, BSMEM);
    cudaFuncSetAttribute(gemm_big<2>, cudaFuncAttributeMaxDynamicSharedMemorySize, BSMEM);
    cudaFuncSetAttribute(attn_mma,    cudaFuncAttributeMaxDynamicSharedMemorySize, ATS_TOTAL);

    // one fused split pass over all inputs/weights
    const int n0 = (NTOK*DIM)/1024;
    const int n1 = (NH*QKD*DIM)/1024;
    const int n2 = ((KV_LORA+ROPE_D)*DIM)/1024;
    const int n3 = (NH*(NOPE+VD)*KV_LORA)/1024;
    const int n4 = (DIM*NH*VD)/1024;
    cvt_all<<<n0+n1+n2+n3+n4, 256>>>(
        x,     xh,  xl,  n0,
        wq,    wqh, wql, n0+n1,
        wkv_a, wah, wal, n0+n1+n2,
        wkv_b, wbh, wbl, n0+n1+n2+n3,
        wo,    woh, wol, n0+n1+n2+n3+n4);

    // q = x @ wq^T -> scaled fp16 Q in attention layout
    gemm_big<1><<<dim3(3072/128, 4096/256), 256, BSMEM>>>(
        xh, xl, wqh, wql, nullptr, aq, nullptr, scale, NTOK, NH*QKD, DIM);
    // kv = x @ wkv_a^T (fp32; prep consumes it)
    gemm_sm<<<dim3(5, 32), 256, GSMEM>>>(
        xh, xl, wah, wal, kv, NTOK, KV_LORA+ROPE_D, DIM);
    // rmsnorm -> split kvc; rope -> fp16 K[:,128:192] all heads (q NOT rotated)
    prep_kernel<<<NTOK, 256>>>(kv, kvnw, fcos, fsin, kvch, kvcl, ak);
    // kvb = kvc @ wkv_b^T -> fp16 K-nope / V attention layouts
    gemm_big<2><<<dim3(4096/128, 4096/256), 256, BSMEM>>>(
        kvch, kvcl, wbh, wbl, nullptr, ak, av, 1.f, NTOK, NH*(NOPE+VD), KV_LORA);
    // fp16 tensor-core flash attention -> split bf16 output (feeds wo GEMM)
    attn_mma<<<dim3(SEQ/128, NH, BATCH), 256, ATS_TOTAL>>>(
        aq, ak, av, ath, atl);
    // out = attn @ wo^T (bf16 3-term, safe)
    gemm_big<0><<<dim3(2048/128, 4096/256), 256, BSMEM>>>(
        ath, atl, woh, wol, out, nullptr, nullptr, 1.f, NTOK, DIM, NH*VD);
}